// round 1
// baseline (speedup 1.0000x reference)
#include <cuda_runtime.h>
#include <cuda_bf16.h>

// Problem constants
#define BATCH 2
#define SEQ   2048
#define DM    1024
#define NH    16
#define DK    64
#define M_ROWS (BATCH*SEQ)   // 4096

// Scratch (device globals: allocation-free rule)
__device__ float g_q[BATCH*NH*SEQ*DK];   // [b][h][s][d]
__device__ float g_k[BATCH*NH*SEQ*DK];
__device__ float g_v[BATCH*NH*SEQ*DK];
__device__ float g_x[BATCH*SEQ*DM];      // attention out, [b][s][h*64+d]

// ---------------------------------------------------------------------------
// NT GEMM: C[m,n] = (sum_k A[m,k]*W[n,k] + bias[n]) * scale
// A: [4096,1024] row-major, W: [1024,1024] row-major (N x K), both K-contiguous.
// BM=BN=64, BK=16, 256 threads, 4x4 per thread.
// head_layout: write C to [b][h][s][d] layout instead of [m][n].
// ---------------------------------------------------------------------------
__global__ void __launch_bounds__(256)
gemm_nt(const float* __restrict__ A, const float* __restrict__ W,
        const float* __restrict__ bias, float* __restrict__ C,
        float scale, int head_layout)
{
    const int K = DM, N = DM;
    __shared__ float As[16*64];   // As[k][m]
    __shared__ float Ws[16*64];   // Ws[k][n]

    int tid = threadIdx.x;
    int tx = tid & 15;            // 0..15 -> n
    int ty = tid >> 4;            // 0..15 -> m
    int m0 = blockIdx.y * 64;
    int n0 = blockIdx.x * 64;

    int lr = tid >> 2;            // 0..63  loader row
    int lc = (tid & 3) << 2;      // 0,4,8,12 loader col (k)

    float acc[4][4] = {};

    for (int k0 = 0; k0 < K; k0 += 16) {
        float4 av = *(const float4*)&A[(m0 + lr) * K + k0 + lc];
        float4 wv = *(const float4*)&W[(n0 + lr) * K + k0 + lc];
        __syncthreads();
        As[(lc+0)*64 + lr] = av.x; As[(lc+1)*64 + lr] = av.y;
        As[(lc+2)*64 + lr] = av.z; As[(lc+3)*64 + lr] = av.w;
        Ws[(lc+0)*64 + lr] = wv.x; Ws[(lc+1)*64 + lr] = wv.y;
        Ws[(lc+2)*64 + lr] = wv.z; Ws[(lc+3)*64 + lr] = wv.w;
        __syncthreads();
        #pragma unroll
        for (int kk = 0; kk < 16; kk++) {
            float4 a4 = *(const float4*)&As[kk*64 + ty*4];
            float4 w4 = *(const float4*)&Ws[kk*64 + tx*4];
            float af[4] = {a4.x, a4.y, a4.z, a4.w};
            float wf[4] = {w4.x, w4.y, w4.z, w4.w};
            #pragma unroll
            for (int i = 0; i < 4; i++)
                #pragma unroll
                for (int j = 0; j < 4; j++)
                    acc[i][j] += af[i] * wf[j];
        }
    }

    #pragma unroll
    for (int i = 0; i < 4; i++) {
        int m = m0 + ty*4 + i;
        #pragma unroll
        for (int j = 0; j < 4; j++) {
            int n = n0 + tx*4 + j;
            float v = (acc[i][j] + bias[n]) * scale;
            if (head_layout) {
                int b = m >> 11;        // /2048
                int s = m & 2047;
                int h = n >> 6;
                int d = n & 63;
                C[(((b << 4) + h) * SEQ + s) * DK + d] = v;
            } else {
                C[m * N + n] = v;
            }
        }
    }
}

// ---------------------------------------------------------------------------
// Flash attention: one CTA per (b,h, q-tile of 64). fp32, online softmax.
// Q pre-scaled by 1/8 at projection time.
// ---------------------------------------------------------------------------
__global__ void __launch_bounds__(256)
attn_kernel(const float* __restrict__ gq, const float* __restrict__ gk,
            const float* __restrict__ gv, const int* __restrict__ mask,
            float* __restrict__ gx)
{
    __shared__ float Qt[64*64];   // Qt[d][r]
    __shared__ float KVs[64*64];  // Kt[d][c] then Vs[k][d]
    __shared__ float Pt[64*64];   // Pt[k][r]

    int tid = threadIdx.x;
    int tx = tid & 15;
    int ty = tid >> 4;
    int bh = blockIdx.y;
    int b  = bh >> 4;
    int h  = bh & 15;
    int q0 = blockIdx.x * 64;

    int lr = tid >> 2;            // 0..63
    int lc = (tid & 3) << 4;      // 0,16,32,48

    const float* qbase = gq + (bh * SEQ + q0) * DK;
    const float* kbase = gk + bh * SEQ * DK;
    const float* vbase = gv + bh * SEQ * DK;
    const int*   mbase = mask + b * SEQ;

    // Load Q tile transposed: Qt[d][r]
    #pragma unroll
    for (int u = 0; u < 4; u++) {
        float4 v = *(const float4*)&qbase[lr * DK + lc + u*4];
        Qt[(lc+u*4+0)*64 + lr] = v.x;
        Qt[(lc+u*4+1)*64 + lr] = v.y;
        Qt[(lc+u*4+2)*64 + lr] = v.z;
        Qt[(lc+u*4+3)*64 + lr] = v.w;
    }

    float acc[4][4] = {};
    float mrow[4] = {-1e30f, -1e30f, -1e30f, -1e30f};
    float lrow[4] = {};

    for (int kt = 0; kt < SEQ; kt += 64) {
        __syncthreads();   // previous PV done with KVs & Pt
        // Load K tile transposed: Kt[d][c]
        #pragma unroll
        for (int u = 0; u < 4; u++) {
            float4 v = *(const float4*)&kbase[(kt + lr) * DK + lc + u*4];
            KVs[(lc+u*4+0)*64 + lr] = v.x;
            KVs[(lc+u*4+1)*64 + lr] = v.y;
            KVs[(lc+u*4+2)*64 + lr] = v.z;
            KVs[(lc+u*4+3)*64 + lr] = v.w;
        }
        __syncthreads();

        // Scores s[i][j] = sum_d Q[q0+4ty+i][d] * K[kt+4tx+j][d]
        float s[4][4] = {};
        #pragma unroll
        for (int d = 0; d < 64; d++) {
            float4 q4 = *(const float4*)&Qt[d*64 + ty*4];
            float4 k4 = *(const float4*)&KVs[d*64 + tx*4];
            float qf[4] = {q4.x, q4.y, q4.z, q4.w};
            float kf[4] = {k4.x, k4.y, k4.z, k4.w};
            #pragma unroll
            for (int i = 0; i < 4; i++)
                #pragma unroll
                for (int j = 0; j < 4; j++)
                    s[i][j] += qf[i] * kf[j];
        }

        // Key mask
        #pragma unroll
        for (int j = 0; j < 4; j++) {
            if (mbase[kt + tx*4 + j] == 0) {
                s[0][j] = -1e9f; s[1][j] = -1e9f;
                s[2][j] = -1e9f; s[3][j] = -1e9f;
            }
        }

        // Online softmax (rows owned by this ty group; reduce over 16 tx lanes)
        #pragma unroll
        for (int i = 0; i < 4; i++) {
            float mx = fmaxf(fmaxf(s[i][0], s[i][1]), fmaxf(s[i][2], s[i][3]));
            #pragma unroll
            for (int off = 8; off > 0; off >>= 1)
                mx = fmaxf(mx, __shfl_xor_sync(0xffffffffu, mx, off, 16));
            float mnew = fmaxf(mrow[i], mx);
            float alpha = __expf(mrow[i] - mnew);
            float p[4], sum = 0.f;
            #pragma unroll
            for (int j = 0; j < 4; j++) { p[j] = __expf(s[i][j] - mnew); sum += p[j]; }
            #pragma unroll
            for (int off = 8; off > 0; off >>= 1)
                sum += __shfl_xor_sync(0xffffffffu, sum, off, 16);
            lrow[i] = lrow[i] * alpha + sum;
            mrow[i] = mnew;
            #pragma unroll
            for (int j = 0; j < 4; j++) acc[i][j] *= alpha;
            // Store P transposed: Pt[k][r]
            #pragma unroll
            for (int j = 0; j < 4; j++)
                Pt[(tx*4 + j)*64 + ty*4 + i] = p[j];
        }
        __syncthreads();   // K reads done, Pt visible

        // Load V tile (natural layout): Vs[k][d]
        #pragma unroll
        for (int u = 0; u < 4; u++) {
            float4 v = *(const float4*)&vbase[(kt + lr) * DK + lc + u*4];
            *(float4*)&KVs[lr*64 + lc + u*4] = v;
        }
        __syncthreads();

        // O += P * V
        #pragma unroll
        for (int k = 0; k < 64; k++) {
            float4 p4 = *(const float4*)&Pt[k*64 + ty*4];
            float4 v4 = *(const float4*)&KVs[k*64 + tx*4];
            float pf[4] = {p4.x, p4.y, p4.z, p4.w};
            float vf[4] = {v4.x, v4.y, v4.z, v4.w};
            #pragma unroll
            for (int i = 0; i < 4; i++)
                #pragma unroll
                for (int j = 0; j < 4; j++)
                    acc[i][j] += pf[i] * vf[j];
        }
    }

    // Epilogue: x[b][q][h*64+d] = acc / l
    #pragma unroll
    for (int i = 0; i < 4; i++) {
        float inv = 1.0f / lrow[i];
        int srow = q0 + ty*4 + i;
        #pragma unroll
        for (int j = 0; j < 4; j++) {
            int d = tx*4 + j;
            gx[(b * SEQ + srow) * DM + h * DK + d] = acc[i][j] * inv;
        }
    }
}

// ---------------------------------------------------------------------------
extern "C" void kernel_launch(void* const* d_in, const int* in_sizes, int n_in,
                              void* d_out, int out_size)
{
    const float* query = (const float*)d_in[0];
    const float* key   = (const float*)d_in[1];
    const float* value = (const float*)d_in[2];
    const int*   mask  = (const int*)  d_in[3];
    const float* Wq    = (const float*)d_in[4];
    const float* bq    = (const float*)d_in[5];
    const float* Wk    = (const float*)d_in[6];
    const float* bk    = (const float*)d_in[7];
    const float* Wv    = (const float*)d_in[8];
    const float* bv    = (const float*)d_in[9];
    const float* Wo    = (const float*)d_in[10];
    const float* bo    = (const float*)d_in[11];
    float* out = (float*)d_out;

    float *pq, *pk, *pv, *px;
    cudaGetSymbolAddress((void**)&pq, g_q);
    cudaGetSymbolAddress((void**)&pk, g_k);
    cudaGetSymbolAddress((void**)&pv, g_v);
    cudaGetSymbolAddress((void**)&px, g_x);

    dim3 ggrid(DM/64, M_ROWS/64);   // (16, 64)
    gemm_nt<<<ggrid, 256>>>(query, Wq, bq, pq, 0.125f, 1);  // Q pre-scaled by 1/sqrt(64)
    gemm_nt<<<ggrid, 256>>>(key,   Wk, bk, pk, 1.0f,   1);
    gemm_nt<<<ggrid, 256>>>(value, Wv, bv, pv, 1.0f,   1);

    dim3 agrid(SEQ/64, BATCH*NH);   // (32, 32)
    attn_kernel<<<agrid, 256>>>(pq, pk, pv, mask, px);

    gemm_nt<<<ggrid, 256>>>(px, Wo, bo, out, 1.0f, 0);
}

// round 3
// speedup vs baseline: 3.0937x; 3.0937x over previous
#include <cuda_runtime.h>
#include <cuda_bf16.h>
#include <cstdint>

// Problem constants
#define BATCH 2
#define SEQ   2048
#define DM    1024
#define NH    16
#define DK    64
#define M_ROWS (BATCH*SEQ)   // 4096

// ---------------------------------------------------------------------------
// Helpers (all base-sm_103 features: ldmatrix + mma.sync, no tcgen05)
// ---------------------------------------------------------------------------
__device__ __forceinline__ uint32_t smem_to_u32(const void* p) {
    uint32_t a;
    asm("{ .reg .u64 t; cvta.to.shared.u64 t, %1; cvt.u32.u64 %0, t; }" : "=r"(a) : "l"(p));
    return a;
}
#define SWZ(o) ((uint32_t)(o) ^ ((((uint32_t)(o)) >> 3) & 0x70))

#define STS128(a, r0, r1, r2, r3) \
    asm volatile("st.shared.v4.b32 [%0], {%1, %2, %3, %4};" \
                 :: "r"(a), "r"(r0), "r"(r1), "r"(r2), "r"(r3) : "memory")

__device__ __forceinline__ void ldmx4(uint32_t addr, uint32_t r[4]) {
    asm volatile("ldmatrix.sync.aligned.m8n8.x4.shared.b16 {%0,%1,%2,%3}, [%4];"
                 : "=r"(r[0]), "=r"(r[1]), "=r"(r[2]), "=r"(r[3]) : "r"(addr));
}
__device__ __forceinline__ void ldmx4t(uint32_t addr, uint32_t r[4]) {
    asm volatile("ldmatrix.sync.aligned.m8n8.x4.trans.shared.b16 {%0,%1,%2,%3}, [%4];"
                 : "=r"(r[0]), "=r"(r[1]), "=r"(r[2]), "=r"(r[3]) : "r"(addr));
}
__device__ __forceinline__ void mma16816(float d[4], const uint32_t a[4],
                                         uint32_t b0, uint32_t b1) {
    asm volatile("mma.sync.aligned.m16n8k16.row.col.f32.bf16.bf16.f32 "
                 "{%0,%1,%2,%3}, {%4,%5,%6,%7}, {%8,%9}, {%0,%1,%2,%3};"
                 : "+f"(d[0]), "+f"(d[1]), "+f"(d[2]), "+f"(d[3])
                 : "r"(a[0]), "r"(a[1]), "r"(a[2]), "r"(a[3]), "r"(b0), "r"(b1));
}

// ---------------------------------------------------------------------------
// Scratch (device globals: allocation-free rule)
// ---------------------------------------------------------------------------
__device__ __nv_bfloat16 g_ahi[M_ROWS*DM];
__device__ __nv_bfloat16 g_alo[M_ROWS*DM];
__device__ __nv_bfloat16 g_whi[DM*DM];
__device__ __nv_bfloat16 g_wlo[DM*DM];
__device__ __nv_bfloat16 g_qhi[BATCH*NH*SEQ*DK];
__device__ __nv_bfloat16 g_qlo[BATCH*NH*SEQ*DK];
__device__ __nv_bfloat16 g_khi[BATCH*NH*SEQ*DK];
__device__ __nv_bfloat16 g_klo[BATCH*NH*SEQ*DK];
__device__ __nv_bfloat16 g_vhi[BATCH*NH*SEQ*DK];
__device__ __nv_bfloat16 g_vlo[BATCH*NH*SEQ*DK];
__device__ __nv_bfloat16 g_xhi[M_ROWS*DM];
__device__ __nv_bfloat16 g_xlo[M_ROWS*DM];

// ---------------------------------------------------------------------------
// Split fp32 -> bf16 hi + lo, float4-vectorized
// ---------------------------------------------------------------------------
__global__ void __launch_bounds__(256)
convert_split4(const float4* __restrict__ x, __nv_bfloat162* __restrict__ hi,
               __nv_bfloat162* __restrict__ lo, int n4)
{
    int i = blockIdx.x * blockDim.x + threadIdx.x;
    if (i < n4) {
        float4 v = x[i];
        __nv_bfloat162 h0 = __floats2bfloat162_rn(v.x, v.y);
        __nv_bfloat162 h1 = __floats2bfloat162_rn(v.z, v.w);
        __nv_bfloat162 l0 = __floats2bfloat162_rn(v.x - __bfloat162float(h0.x),
                                                  v.y - __bfloat162float(h0.y));
        __nv_bfloat162 l1 = __floats2bfloat162_rn(v.z - __bfloat162float(h1.x),
                                                  v.w - __bfloat162float(h1.y));
        hi[i*2]   = h0; hi[i*2+1] = h1;
        lo[i*2]   = l0; lo[i*2+1] = l1;
    }
}

// ---------------------------------------------------------------------------
// Split-bf16 NT GEMM on mma.sync: C = (A*W^T + bias) * scale
// BM=64, BN=128, BK=64, 256 threads (8 warps, 2x4), warp tile 32x32.
// Smem exactly 48KB dynamic: Ahi(8K) Alo(8K) Bhi(16K) Blo(16K), SW128.
// mode 0: f32 C[m][n].  mode 1: split bf16, head layout.  mode 2: split flat.
// ---------------------------------------------------------------------------
#define GA_HI 0
#define GA_LO 8192
#define GB_HI 16384
#define GB_LO 32768
#define G_SMEM 49152

__global__ void __launch_bounds__(256)
gemm_tc(const __nv_bfloat16* __restrict__ Ahi, const __nv_bfloat16* __restrict__ Alo,
        const __nv_bfloat16* __restrict__ Whi, const __nv_bfloat16* __restrict__ Wlo,
        const float* __restrict__ bias, float* __restrict__ C,
        __nv_bfloat16* __restrict__ Chi, __nv_bfloat16* __restrict__ Clo,
        float scale, int mode)
{
    extern __shared__ char smem[];
    uint32_t sb = smem_to_u32(smem);
    const int tid = threadIdx.x, lane = tid & 31, wid = tid >> 5;
    const int wm = wid & 1, wn = wid >> 1;
    const int m0 = blockIdx.y * 64, n0 = blockIdx.x * 128;

    float acc[2][4][4] = {};

    // fragment addressing (per-thread, k-chunk varies with kk)
    int a_row[2], b_row[2];
    #pragma unroll
    for (int mt = 0; mt < 2; mt++) a_row[mt] = wm*32 + mt*16 + (lane & 15);
    #pragma unroll
    for (int g = 0; g < 2; g++)
        b_row[g] = wn*32 + g*16 + ((lane >> 4) << 3) + (lane & 7);
    const int a_half = lane >> 4;
    const int b_half = (lane >> 3) & 1;

    for (int st = 0; st < 16; st++) {
        int kc = st * 64;
        __syncthreads();
        {   // A tiles: 64 rows x 8 chunks = 512 uint4 -> 2 iters
            const uint4* pah = (const uint4*)(Ahi + (size_t)m0*DM + kc);
            const uint4* pal = (const uint4*)(Alo + (size_t)m0*DM + kc);
            #pragma unroll
            for (int it = 0; it < 2; it++) {
                int q = tid + it*256; int r = q >> 3, c = q & 7;
                uint32_t so = SWZ(r*128 + c*16);
                uint4 v = pah[r*128 + c];                 // gmem row = 128 uint4
                STS128(sb + GA_HI + so, v.x, v.y, v.z, v.w);
                v = pal[r*128 + c];
                STS128(sb + GA_LO + so, v.x, v.y, v.z, v.w);
            }
            // B tiles: 128 rows x 8 chunks = 1024 uint4 -> 4 iters
            const uint4* pbh = (const uint4*)(Whi + (size_t)n0*DM + kc);
            const uint4* pbl = (const uint4*)(Wlo + (size_t)n0*DM + kc);
            #pragma unroll
            for (int it = 0; it < 4; it++) {
                int q = tid + it*256; int r = q >> 3, c = q & 7;
                uint32_t so = SWZ(r*128 + c*16);
                uint4 v = pbh[r*128 + c];
                STS128(sb + GB_HI + so, v.x, v.y, v.z, v.w);
                v = pbl[r*128 + c];
                STS128(sb + GB_LO + so, v.x, v.y, v.z, v.w);
            }
        }
        __syncthreads();
        #pragma unroll
        for (int kk = 0; kk < 4; kk++) {
            uint32_t ah[2][4], al[2][4], bh2[2][4], bl2[2][4];
            #pragma unroll
            for (int mt = 0; mt < 2; mt++) {
                uint32_t off = SWZ(a_row[mt]*128 + (kk*2 + a_half)*16);
                ldmx4(sb + GA_HI + off, ah[mt]);
                ldmx4(sb + GA_LO + off, al[mt]);
            }
            #pragma unroll
            for (int g = 0; g < 2; g++) {
                uint32_t off = SWZ(b_row[g]*128 + (kk*2 + b_half)*16);
                ldmx4(sb + GB_HI + off, bh2[g]);
                ldmx4(sb + GB_LO + off, bl2[g]);
            }
            #pragma unroll
            for (int mt = 0; mt < 2; mt++)
                #pragma unroll
                for (int j = 0; j < 4; j++) {
                    int g = j >> 1, pr = (j & 1) * 2;
                    mma16816(acc[mt][j], ah[mt], bh2[g][pr], bh2[g][pr+1]);
                    mma16816(acc[mt][j], ah[mt], bl2[g][pr], bl2[g][pr+1]);
                    mma16816(acc[mt][j], al[mt], bh2[g][pr], bh2[g][pr+1]);
                }
        }
    }

    // Epilogue
    #pragma unroll
    for (int mt = 0; mt < 2; mt++) {
        int r0 = m0 + wm*32 + mt*16 + (lane >> 2);
        #pragma unroll
        for (int j = 0; j < 4; j++) {
            int cb = n0 + wn*32 + j*8 + 2*(lane & 3);
            float b0 = __ldg(&bias[cb]), b1 = __ldg(&bias[cb+1]);
            #pragma unroll
            for (int half = 0; half < 2; half++) {
                int m = r0 + half*8;
                float x0 = (acc[mt][j][half*2+0] + b0) * scale;
                float x1 = (acc[mt][j][half*2+1] + b1) * scale;
                if (mode == 0) {
                    C[(size_t)m*DM + cb]   = x0;
                    C[(size_t)m*DM + cb+1] = x1;
                } else {
                    size_t idx;
                    if (mode == 1) {
                        int b = m >> 11, s = m & 2047, h = cb >> 6, d = cb & 63;
                        idx = (((size_t)(b*NH + h))*SEQ + s)*DK + d;
                    } else {
                        idx = (size_t)m*DM + cb;
                    }
                    __nv_bfloat162 h2 = __floats2bfloat162_rn(x0, x1);
                    __nv_bfloat162 l2 = __floats2bfloat162_rn(
                        x0 - __bfloat162float(h2.x), x1 - __bfloat162float(h2.y));
                    *(__nv_bfloat162*)(Chi + idx) = h2;
                    *(__nv_bfloat162*)(Clo + idx) = l2;
                }
            }
        }
    }
}

// ---------------------------------------------------------------------------
// Flash attention on mma.sync, split bf16 (Q,K,V,P all hi/lo; 3 MMA passes).
// CTA: 64 q-rows, 128 threads (4 warps; warp = 16 q-rows).
// Q fragments register-resident; smem = K/V tiles (33KB static).
// ---------------------------------------------------------------------------
__global__ void __launch_bounds__(128)
attn_tc(const __nv_bfloat16* __restrict__ qhi, const __nv_bfloat16* __restrict__ qlo,
        const __nv_bfloat16* __restrict__ khi, const __nv_bfloat16* __restrict__ klo,
        const __nv_bfloat16* __restrict__ vhi, const __nv_bfloat16* __restrict__ vlo,
        const int* __restrict__ mask,
        __nv_bfloat16* __restrict__ xhi, __nv_bfloat16* __restrict__ xlo)
{
    __shared__ __align__(16) char kv[32768];   // KHI 0, KLO 8K, VHI 16K, VLO 24K
    __shared__ float msks[64];
    uint32_t sb = smem_to_u32(kv);
    const uint32_t KHI = 0, KLO = 8192, VHI = 16384, VLO = 24576;

    const int tid = threadIdx.x, lane = tid & 31, w = tid >> 5;
    const int bh = blockIdx.y, b = bh >> 4, h = bh & 15;
    const int q0 = blockIdx.x * 64;

    const int a_row  = w*16 + (lane & 15);
    const int a_half = lane >> 4;
    const int b_rowb = ((lane >> 4) << 3) + (lane & 7);
    const int b_half = (lane >> 3) & 1;
    const int v_krow = ((lane >> 3) & 1)*8 + (lane & 7);
    const int v_dhalf = lane >> 4;

    // ---- Stage Q through KHI/KLO, pull fragments into registers ----
    uint32_t qfh[4][4], qfl[4][4];
    {
        const uint4* ph = (const uint4*)(qhi + ((size_t)bh*SEQ + q0)*DK);
        const uint4* pl = (const uint4*)(qlo + ((size_t)bh*SEQ + q0)*DK);
        #pragma unroll
        for (int it = 0; it < 4; it++) {
            int q = tid + it*128; int r = q >> 3, c = q & 7;
            uint32_t so = SWZ(r*128 + c*16);
            uint4 v = ph[r*8 + c];                     // head layout: row = 8 uint4
            STS128(sb + KHI + so, v.x, v.y, v.z, v.w);
            v = pl[r*8 + c];
            STS128(sb + KLO + so, v.x, v.y, v.z, v.w);
        }
        __syncthreads();
        #pragma unroll
        for (int kk = 0; kk < 4; kk++) {
            uint32_t off = SWZ(a_row*128 + (kk*2 + a_half)*16);
            ldmx4(sb + KHI + off, qfh[kk]);
            ldmx4(sb + KLO + off, qfl[kk]);
        }
    }

    float acc[8][4] = {};
    float mrow[2] = {-1e30f, -1e30f}, lrow[2] = {0.f, 0.f};

    const uint4* pkh = (const uint4*)(khi + (size_t)bh*SEQ*DK);
    const uint4* pkl = (const uint4*)(klo + (size_t)bh*SEQ*DK);
    const uint4* pvh = (const uint4*)(vhi + (size_t)bh*SEQ*DK);
    const uint4* pvl = (const uint4*)(vlo + (size_t)bh*SEQ*DK);
    const int* mb = mask + b*SEQ;

    for (int kt = 0; kt < SEQ; kt += 64) {
        __syncthreads();   // prior QK/PV reads of K/V done (and Q staging read)
        #pragma unroll
        for (int it = 0; it < 4; it++) {
            int q = tid + it*128; int r = q >> 3, c = q & 7;
            uint32_t so = SWZ(r*128 + c*16);
            int gr = (kt + r)*8 + c;
            uint4 v = pkh[gr]; STS128(sb + KHI + so, v.x, v.y, v.z, v.w);
            v = pkl[gr];       STS128(sb + KLO + so, v.x, v.y, v.z, v.w);
            v = pvh[gr];       STS128(sb + VHI + so, v.x, v.y, v.z, v.w);
            v = pvl[gr];       STS128(sb + VLO + so, v.x, v.y, v.z, v.w);
        }
        if (tid < 64) msks[tid] = (mb[kt + tid] == 0) ? -1e9f : 0.f;
        __syncthreads();

        // ---- S = Q K^T ----
        float s[8][4] = {};
        #pragma unroll
        for (int kk = 0; kk < 4; kk++) {
            #pragma unroll
            for (int g = 0; g < 4; g++) {
                uint32_t kh2[4], kl2[4];
                uint32_t boff = SWZ((g*16 + b_rowb)*128 + (kk*2 + b_half)*16);
                ldmx4(sb + KHI + boff, kh2);
                ldmx4(sb + KLO + boff, kl2);
                #pragma unroll
                for (int pr = 0; pr < 2; pr++) {
                    int j = g*2 + pr;
                    mma16816(s[j], qfh[kk], kh2[pr*2], kh2[pr*2+1]);
                    mma16816(s[j], qfh[kk], kl2[pr*2], kl2[pr*2+1]);
                    mma16816(s[j], qfl[kk], kh2[pr*2], kh2[pr*2+1]);
                }
            }
        }

        // ---- mask + online softmax ----
        #pragma unroll
        for (int j = 0; j < 8; j++) {
            float m0v = msks[j*8 + 2*(lane & 3)];
            float m1v = msks[j*8 + 2*(lane & 3) + 1];
            s[j][0] += m0v; s[j][1] += m1v; s[j][2] += m0v; s[j][3] += m1v;
        }
        float tlo = -1e30f, thi = -1e30f;
        #pragma unroll
        for (int j = 0; j < 8; j++) {
            tlo = fmaxf(tlo, fmaxf(s[j][0], s[j][1]));
            thi = fmaxf(thi, fmaxf(s[j][2], s[j][3]));
        }
        tlo = fmaxf(tlo, __shfl_xor_sync(0xffffffffu, tlo, 1));
        tlo = fmaxf(tlo, __shfl_xor_sync(0xffffffffu, tlo, 2));
        thi = fmaxf(thi, __shfl_xor_sync(0xffffffffu, thi, 1));
        thi = fmaxf(thi, __shfl_xor_sync(0xffffffffu, thi, 2));
        float mnlo = fmaxf(mrow[0], tlo), mnhi = fmaxf(mrow[1], thi);
        float alo = __expf(mrow[0] - mnlo), ahi = __expf(mrow[1] - mnhi);
        float slo = 0.f, shi = 0.f;
        uint32_t pfh[8][2], pfl[8][2];
        #pragma unroll
        for (int j = 0; j < 8; j++) {
            float p0 = __expf(s[j][0] - mnlo), p1 = __expf(s[j][1] - mnlo);
            float p2 = __expf(s[j][2] - mnhi), p3 = __expf(s[j][3] - mnhi);
            slo += p0 + p1; shi += p2 + p3;
            __nv_bfloat162 h0 = __floats2bfloat162_rn(p0, p1);
            __nv_bfloat162 h1 = __floats2bfloat162_rn(p2, p3);
            __nv_bfloat162 l0 = __floats2bfloat162_rn(p0 - __bfloat162float(h0.x),
                                                      p1 - __bfloat162float(h0.y));
            __nv_bfloat162 l1 = __floats2bfloat162_rn(p2 - __bfloat162float(h1.x),
                                                      p3 - __bfloat162float(h1.y));
            pfh[j][0] = *(uint32_t*)&h0; pfh[j][1] = *(uint32_t*)&h1;
            pfl[j][0] = *(uint32_t*)&l0; pfl[j][1] = *(uint32_t*)&l1;
        }
        slo += __shfl_xor_sync(0xffffffffu, slo, 1);
        slo += __shfl_xor_sync(0xffffffffu, slo, 2);
        shi += __shfl_xor_sync(0xffffffffu, shi, 1);
        shi += __shfl_xor_sync(0xffffffffu, shi, 2);
        lrow[0] = lrow[0]*alo + slo; lrow[1] = lrow[1]*ahi + shi;
        mrow[0] = mnlo; mrow[1] = mnhi;
        #pragma unroll
        for (int j = 0; j < 8; j++) {
            acc[j][0] *= alo; acc[j][1] *= alo;
            acc[j][2] *= ahi; acc[j][3] *= ahi;
        }

        // ---- O += P V ----
        #pragma unroll
        for (int ks = 0; ks < 4; ks++) {
            uint32_t pah[4] = {pfh[2*ks][0], pfh[2*ks][1], pfh[2*ks+1][0], pfh[2*ks+1][1]};
            uint32_t pal[4] = {pfl[2*ks][0], pfl[2*ks][1], pfl[2*ks+1][0], pfl[2*ks+1][1]};
            #pragma unroll
            for (int g = 0; g < 4; g++) {
                uint32_t vb_h[4], vb_l[4];
                uint32_t voff = SWZ((ks*16 + v_krow)*128 + (g*2 + v_dhalf)*16);
                ldmx4t(sb + VHI + voff, vb_h);
                ldmx4t(sb + VLO + voff, vb_l);
                #pragma unroll
                for (int pr = 0; pr < 2; pr++) {
                    int j = g*2 + pr;
                    mma16816(acc[j], pah, vb_h[pr*2], vb_h[pr*2+1]);
                    mma16816(acc[j], pah, vb_l[pr*2], vb_l[pr*2+1]);
                    mma16816(acc[j], pal, vb_h[pr*2], vb_h[pr*2+1]);
                }
            }
        }
    }

    // ---- epilogue: x = acc / l, split bf16, layout [b][s][h*64+d] ----
    float il0 = 1.0f / lrow[0], il1 = 1.0f / lrow[1];
    int r0g = q0 + w*16 + (lane >> 2);
    #pragma unroll
    for (int j = 0; j < 8; j++) {
        int d = j*8 + 2*(lane & 3);
        #pragma unroll
        for (int half = 0; half < 2; half++) {
            int srow = r0g + half*8;
            float il = half ? il1 : il0;
            float x0 = acc[j][half*2+0] * il, x1 = acc[j][half*2+1] * il;
            size_t idx = ((size_t)b*SEQ + srow)*DM + h*DK + d;
            __nv_bfloat162 h2 = __floats2bfloat162_rn(x0, x1);
            __nv_bfloat162 l2 = __floats2bfloat162_rn(
                x0 - __bfloat162float(h2.x), x1 - __bfloat162float(h2.y));
            *(__nv_bfloat162*)(xhi + idx) = h2;
            *(__nv_bfloat162*)(xlo + idx) = l2;
        }
    }
}

// ---------------------------------------------------------------------------
extern "C" void kernel_launch(void* const* d_in, const int* in_sizes, int n_in,
                              void* d_out, int out_size)
{
    const float* query = (const float*)d_in[0];
    const float* key   = (const float*)d_in[1];
    const float* value = (const float*)d_in[2];
    const int*   mask  = (const int*)  d_in[3];
    const float* Wq    = (const float*)d_in[4];
    const float* bq    = (const float*)d_in[5];
    const float* Wk    = (const float*)d_in[6];
    const float* bk    = (const float*)d_in[7];
    const float* Wv    = (const float*)d_in[8];
    const float* bv    = (const float*)d_in[9];
    const float* Wo    = (const float*)d_in[10];
    const float* bo    = (const float*)d_in[11];
    float* out = (float*)d_out;

    __nv_bfloat16 *ahi, *alo, *whi, *wlo;
    __nv_bfloat16 *qhi, *qlo, *khi, *klo, *vhi, *vlo, *xhi, *xlo;
    cudaGetSymbolAddress((void**)&ahi, g_ahi);
    cudaGetSymbolAddress((void**)&alo, g_alo);
    cudaGetSymbolAddress((void**)&whi, g_whi);
    cudaGetSymbolAddress((void**)&wlo, g_wlo);
    cudaGetSymbolAddress((void**)&qhi, g_qhi);
    cudaGetSymbolAddress((void**)&qlo, g_qlo);
    cudaGetSymbolAddress((void**)&khi, g_khi);
    cudaGetSymbolAddress((void**)&klo, g_klo);
    cudaGetSymbolAddress((void**)&vhi, g_vhi);
    cudaGetSymbolAddress((void**)&vlo, g_vlo);
    cudaGetSymbolAddress((void**)&xhi, g_xhi);
    cudaGetSymbolAddress((void**)&xlo, g_xlo);

    const int nA4 = M_ROWS*DM/4, nW4 = DM*DM/4;
    dim3 cgA((nA4 + 255)/256), cgW((nW4 + 255)/256);
    dim3 ggrid(DM/128, M_ROWS/64);     // (8, 64)
    dim3 agrid(SEQ/64, BATCH*NH);      // (32, 32)

    // Q projection (scale 1/sqrt(64) folded)
    convert_split4<<<cgA, 256>>>((const float4*)query, (__nv_bfloat162*)ahi, (__nv_bfloat162*)alo, nA4);
    convert_split4<<<cgW, 256>>>((const float4*)Wq, (__nv_bfloat162*)whi, (__nv_bfloat162*)wlo, nW4);
    gemm_tc<<<ggrid, 256, G_SMEM>>>(ahi, alo, whi, wlo, bq, nullptr, qhi, qlo, 0.125f, 1);
    // K projection
    convert_split4<<<cgA, 256>>>((const float4*)key, (__nv_bfloat162*)ahi, (__nv_bfloat162*)alo, nA4);
    convert_split4<<<cgW, 256>>>((const float4*)Wk, (__nv_bfloat162*)whi, (__nv_bfloat162*)wlo, nW4);
    gemm_tc<<<ggrid, 256, G_SMEM>>>(ahi, alo, whi, wlo, bk, nullptr, khi, klo, 1.0f, 1);
    // V projection
    convert_split4<<<cgA, 256>>>((const float4*)value, (__nv_bfloat162*)ahi, (__nv_bfloat162*)alo, nA4);
    convert_split4<<<cgW, 256>>>((const float4*)Wv, (__nv_bfloat162*)whi, (__nv_bfloat162*)wlo, nW4);
    gemm_tc<<<ggrid, 256, G_SMEM>>>(ahi, alo, whi, wlo, bv, nullptr, vhi, vlo, 1.0f, 1);

    // Attention (HMMA flash, split precision, writes x split directly)
    attn_tc<<<agrid, 128>>>(qhi, qlo, khi, klo, vhi, vlo, mask, xhi, xlo);

    // Output projection (reads split x directly, writes f32 out)
    convert_split4<<<cgW, 256>>>((const float4*)Wo, (__nv_bfloat162*)whi, (__nv_bfloat162*)wlo, nW4);
    gemm_tc<<<ggrid, 256, G_SMEM>>>(xhi, xlo, whi, wlo, bo, out, nullptr, nullptr, 1.0f, 0);
}

// round 4
// speedup vs baseline: 4.4522x; 1.4391x over previous
#include <cuda_runtime.h>
#include <cuda_bf16.h>
#include <cuda_fp16.h>
#include <cstdint>

// Problem constants
#define BATCH 2
#define SEQ   2048
#define DM    1024
#define NH    16
#define DK    64
#define M_ROWS (BATCH*SEQ)   // 4096

// ---------------------------------------------------------------------------
// Helpers (base-sm_103 features: ldmatrix + mma.sync + cp.async)
// ---------------------------------------------------------------------------
__device__ __forceinline__ uint32_t smem_to_u32(const void* p) {
    uint32_t a;
    asm("{ .reg .u64 t; cvta.to.shared.u64 t, %1; cvt.u32.u64 %0, t; }" : "=r"(a) : "l"(p));
    return a;
}
#define SWZ(o) ((uint32_t)(o) ^ ((((uint32_t)(o)) >> 3) & 0x70))

#define STS128(a, r0, r1, r2, r3) \
    asm volatile("st.shared.v4.b32 [%0], {%1, %2, %3, %4};" \
                 :: "r"(a), "r"(r0), "r"(r1), "r"(r2), "r"(r3) : "memory")
#define CP_ASYNC16(dst, src) \
    asm volatile("cp.async.cg.shared.global [%0], [%1], 16;" :: "r"(dst), "l"(src) : "memory")
#define CP_COMMIT() asm volatile("cp.async.commit_group;" ::: "memory")
#define CP_WAIT1()  asm volatile("cp.async.wait_group 1;" ::: "memory")
#define CP_WAIT0()  asm volatile("cp.async.wait_group 0;" ::: "memory")

__device__ __forceinline__ void ldmx4(uint32_t addr, uint32_t r[4]) {
    asm volatile("ldmatrix.sync.aligned.m8n8.x4.shared.b16 {%0,%1,%2,%3}, [%4];"
                 : "=r"(r[0]), "=r"(r[1]), "=r"(r[2]), "=r"(r[3]) : "r"(addr));
}
__device__ __forceinline__ void ldmx4t(uint32_t addr, uint32_t r[4]) {
    asm volatile("ldmatrix.sync.aligned.m8n8.x4.trans.shared.b16 {%0,%1,%2,%3}, [%4];"
                 : "=r"(r[0]), "=r"(r[1]), "=r"(r[2]), "=r"(r[3]) : "r"(addr));
}
__device__ __forceinline__ void mma_bf(float d[4], const uint32_t a[4],
                                       uint32_t b0, uint32_t b1) {
    asm volatile("mma.sync.aligned.m16n8k16.row.col.f32.bf16.bf16.f32 "
                 "{%0,%1,%2,%3}, {%4,%5,%6,%7}, {%8,%9}, {%0,%1,%2,%3};"
                 : "+f"(d[0]), "+f"(d[1]), "+f"(d[2]), "+f"(d[3])
                 : "r"(a[0]), "r"(a[1]), "r"(a[2]), "r"(a[3]), "r"(b0), "r"(b1));
}
__device__ __forceinline__ void mma_fp(float d[4], const uint32_t a[4],
                                       uint32_t b0, uint32_t b1) {
    asm volatile("mma.sync.aligned.m16n8k16.row.col.f32.f16.f16.f32 "
                 "{%0,%1,%2,%3}, {%4,%5,%6,%7}, {%8,%9}, {%0,%1,%2,%3};"
                 : "+f"(d[0]), "+f"(d[1]), "+f"(d[2]), "+f"(d[3])
                 : "r"(a[0]), "r"(a[1]), "r"(a[2]), "r"(a[3]), "r"(b0), "r"(b1));
}

// ---------------------------------------------------------------------------
// Scratch (device globals: allocation-free rule)
// ---------------------------------------------------------------------------
__device__ __nv_bfloat16 g_qhi[BATCH*NH*SEQ*DK];
__device__ __nv_bfloat16 g_qlo[BATCH*NH*SEQ*DK];
__device__ __nv_bfloat16 g_khi[BATCH*NH*SEQ*DK];
__device__ __nv_bfloat16 g_klo[BATCH*NH*SEQ*DK];
__device__ __half        g_vh [BATCH*NH*SEQ*DK];
__device__ __half        g_vl [BATCH*NH*SEQ*DK];
__device__ float         g_x  [M_ROWS*DM];
__device__ int           g_perm[BATCH*SEQ];
__device__ int           g_ncnt[BATCH];

// ---------------------------------------------------------------------------
// Deterministic mask compaction: 1 CTA per batch, Hillis-Steele scan.
// perm[b][j] = original key index of j-th unmasked key (0-padded), ncnt[b]=n.
// ---------------------------------------------------------------------------
__global__ void __launch_bounds__(1024)
mask_scan(const int* __restrict__ mask, int* __restrict__ perm, int* __restrict__ ncnt)
{
    __shared__ int sm[1024];
    int b = blockIdx.x, t = threadIdx.x;
    const int* m = mask + b*SEQ;
    int* pb = perm + b*SEQ;
    pb[2*t] = 0; pb[2*t+1] = 0;
    int a0 = (m[2*t] != 0), a1 = (m[2*t+1] != 0);
    int sum = a0 + a1;
    sm[t] = sum;
    __syncthreads();
    #pragma unroll
    for (int off = 1; off < 1024; off <<= 1) {
        int v = (t >= off) ? sm[t-off] : 0;
        __syncthreads();
        sm[t] += v;
        __syncthreads();
    }
    int excl = sm[t] - sum;
    if (a0) pb[excl] = 2*t;
    if (a1) pb[excl + a0] = 2*t + 1;
    if (t == 1023) ncnt[b] = sm[1023];
}

// ---------------------------------------------------------------------------
// Fused-convert split-bf16 NT GEMM: C = (A*W^T + bias) * scale
// A,W fp32 in gmem; converted to bf16 hi/lo in-register at load.
// BM=64, BN=128, BK=64, 256 threads (2x4 warps), 3-pass split MMA.
// mode 0: fp32 flat. mode 1: bf16 split head layout. mode 2: fp16 split head.
// ---------------------------------------------------------------------------
#define GA_HI 0
#define GA_LO 8192
#define GB_HI 16384
#define GB_LO 32768
#define G_SMEM 49152

__device__ __forceinline__ void cvt_sts8(uint32_t dhi, uint32_t dlo, const float* g)
{
    float4 v0 = *(const float4*)g;
    float4 v1 = *(const float4*)(g + 4);
    float vs[8] = {v0.x, v0.y, v0.z, v0.w, v1.x, v1.y, v1.z, v1.w};
    uint32_t h[4], l[4];
    #pragma unroll
    for (int i = 0; i < 4; i++) {
        __nv_bfloat162 hh = __floats2bfloat162_rn(vs[2*i], vs[2*i+1]);
        __nv_bfloat162 ll = __floats2bfloat162_rn(vs[2*i]   - __bfloat162float(hh.x),
                                                  vs[2*i+1] - __bfloat162float(hh.y));
        h[i] = *(uint32_t*)&hh; l[i] = *(uint32_t*)&ll;
    }
    STS128(dhi, h[0], h[1], h[2], h[3]);
    STS128(dlo, l[0], l[1], l[2], l[3]);
}

__global__ void __launch_bounds__(256)
gemm_f(const float* __restrict__ A, const float* __restrict__ W,
       const float* __restrict__ bias, float* __restrict__ Cf,
       __nv_bfloat16* __restrict__ Chi, __nv_bfloat16* __restrict__ Clo,
       __half* __restrict__ Chh, __half* __restrict__ Chl,
       float scale, int mode)
{
    extern __shared__ char smem[];
    uint32_t sb = smem_to_u32(smem);
    const int tid = threadIdx.x, lane = tid & 31, wid = tid >> 5;
    const int wm = wid & 1, wn = wid >> 1;
    const int m0 = blockIdx.y * 64, n0 = blockIdx.x * 128;

    float acc[2][4][4] = {};

    int a_row[2], b_row[2];
    #pragma unroll
    for (int mt = 0; mt < 2; mt++) a_row[mt] = wm*32 + mt*16 + (lane & 15);
    #pragma unroll
    for (int g = 0; g < 2; g++)
        b_row[g] = wn*32 + g*16 + ((lane >> 4) << 3) + (lane & 7);
    const int a_half = lane >> 4;
    const int b_half = (lane >> 3) & 1;

    for (int st = 0; st < 16; st++) {
        int kc = st * 64;
        __syncthreads();
        // A tile: 64 rows x 64 f32 -> 512 8-float chunks -> 2 iters
        #pragma unroll
        for (int it = 0; it < 2; it++) {
            int q = tid + it*256; int r = q >> 3, c8 = q & 7;
            uint32_t so = SWZ(r*128 + c8*16);
            cvt_sts8(sb + GA_HI + so, sb + GA_LO + so,
                     A + (size_t)(m0 + r)*DM + kc + c8*8);
        }
        // B tile: 128 rows -> 4 iters
        #pragma unroll
        for (int it = 0; it < 4; it++) {
            int q = tid + it*256; int r = q >> 3, c8 = q & 7;
            uint32_t so = SWZ(r*128 + c8*16);
            cvt_sts8(sb + GB_HI + so, sb + GB_LO + so,
                     W + (size_t)(n0 + r)*DM + kc + c8*8);
        }
        __syncthreads();
        #pragma unroll
        for (int kk = 0; kk < 4; kk++) {
            uint32_t ah[2][4], al[2][4], bh2[2][4], bl2[2][4];
            #pragma unroll
            for (int mt = 0; mt < 2; mt++) {
                uint32_t off = SWZ(a_row[mt]*128 + (kk*2 + a_half)*16);
                ldmx4(sb + GA_HI + off, ah[mt]);
                ldmx4(sb + GA_LO + off, al[mt]);
            }
            #pragma unroll
            for (int g = 0; g < 2; g++) {
                uint32_t off = SWZ(b_row[g]*128 + (kk*2 + b_half)*16);
                ldmx4(sb + GB_HI + off, bh2[g]);
                ldmx4(sb + GB_LO + off, bl2[g]);
            }
            #pragma unroll
            for (int mt = 0; mt < 2; mt++)
                #pragma unroll
                for (int j = 0; j < 4; j++) {
                    int g = j >> 1, pr = (j & 1) * 2;
                    mma_bf(acc[mt][j], ah[mt], bh2[g][pr], bh2[g][pr+1]);
                    mma_bf(acc[mt][j], ah[mt], bl2[g][pr], bl2[g][pr+1]);
                    mma_bf(acc[mt][j], al[mt], bh2[g][pr], bh2[g][pr+1]);
                }
        }
    }

    // Epilogue
    #pragma unroll
    for (int mt = 0; mt < 2; mt++) {
        int r0 = m0 + wm*32 + mt*16 + (lane >> 2);
        #pragma unroll
        for (int j = 0; j < 4; j++) {
            int cb = n0 + wn*32 + j*8 + 2*(lane & 3);
            float b0 = __ldg(&bias[cb]), b1 = __ldg(&bias[cb+1]);
            #pragma unroll
            for (int half = 0; half < 2; half++) {
                int m = r0 + half*8;
                float x0 = (acc[mt][j][half*2+0] + b0) * scale;
                float x1 = (acc[mt][j][half*2+1] + b1) * scale;
                if (mode == 0) {
                    float2 o; o.x = x0; o.y = x1;
                    *(float2*)(Cf + (size_t)m*DM + cb) = o;
                } else {
                    int b = m >> 11, s = m & 2047, h = cb >> 6, d = cb & 63;
                    size_t idx = (((size_t)(b*NH + h))*SEQ + s)*DK + d;
                    if (mode == 1) {
                        __nv_bfloat162 h2 = __floats2bfloat162_rn(x0, x1);
                        __nv_bfloat162 l2 = __floats2bfloat162_rn(
                            x0 - __bfloat162float(h2.x), x1 - __bfloat162float(h2.y));
                        *(__nv_bfloat162*)(Chi + idx) = h2;
                        *(__nv_bfloat162*)(Clo + idx) = l2;
                    } else {
                        __half2 h2 = __floats2half2_rn(x0, x1);
                        __half2 l2 = __floats2half2_rn(
                            x0 - __half2float(h2.x), x1 - __half2float(h2.y));
                        *(__half2*)(Chh + idx) = h2;
                        *(__half2*)(Chl + idx) = l2;
                    }
                }
            }
        }
    }
}

// ---------------------------------------------------------------------------
// Flash attention over COMPACTED keys (perm-indirected), cp.async double buffer.
// QK: 3-pass split bf16. PV: P single fp16, V split fp16 (2 passes).
// CTA: 64 q-rows, 128 threads. Output fp32 x [b][s][h*64+d].
// ---------------------------------------------------------------------------
#define AT_KH 0
#define AT_KL 8192
#define AT_VH 16384
#define AT_VL 24576
#define AT_BUF 32768
#define AT_SMEM 65536

__device__ __forceinline__ void attn_load_tile(
    uint32_t sbuf, const __nv_bfloat16* kh, const __nv_bfloat16* kl,
    const __half* vh, const __half* vl, const int* permb, int kt, int tid)
{
    #pragma unroll
    for (int it = 0; it < 4; it++) {
        int q = tid + it*128; int r = q >> 3, c = q & 7;
        int s = __ldg(&permb[kt + r]);
        size_t ro = (size_t)s * DK + c*8;
        uint32_t so = SWZ(r*128 + c*16);
        CP_ASYNC16(sbuf + AT_KH + so, (const void*)(kh + ro));
        CP_ASYNC16(sbuf + AT_KL + so, (const void*)(kl + ro));
        CP_ASYNC16(sbuf + AT_VH + so, (const void*)(vh + ro));
        CP_ASYNC16(sbuf + AT_VL + so, (const void*)(vl + ro));
    }
}

__global__ void __launch_bounds__(128)
attn_tc(const __nv_bfloat16* __restrict__ qhi, const __nv_bfloat16* __restrict__ qlo,
        const __nv_bfloat16* __restrict__ khi, const __nv_bfloat16* __restrict__ klo,
        const __half* __restrict__ vhh, const __half* __restrict__ vhl,
        const int* __restrict__ perm, const int* __restrict__ ncnt,
        float* __restrict__ xout)
{
    extern __shared__ char dsm[];
    uint32_t sb = smem_to_u32(dsm);

    const int tid = threadIdx.x, lane = tid & 31, w = tid >> 5;
    const int bh = blockIdx.y, b = bh >> 4, h = bh & 15;
    const int q0 = blockIdx.x * 64;

    const int a_row  = w*16 + (lane & 15);
    const int a_half = lane >> 4;
    const int b_rowb = ((lane >> 4) << 3) + (lane & 7);
    const int b_half = (lane >> 3) & 1;
    const int v_krow = ((lane >> 3) & 1)*8 + (lane & 7);
    const int v_dhalf = lane >> 4;

    // ---- Stage Q through buf0, pull fragments into registers ----
    uint32_t qfh[4][4], qfl[4][4];
    {
        const uint4* ph = (const uint4*)(qhi + ((size_t)bh*SEQ + q0)*DK);
        const uint4* pl = (const uint4*)(qlo + ((size_t)bh*SEQ + q0)*DK);
        #pragma unroll
        for (int it = 0; it < 4; it++) {
            int q = tid + it*128; int r = q >> 3, c = q & 7;
            uint32_t so = SWZ(r*128 + c*16);
            uint4 v = ph[r*8 + c];
            STS128(sb + AT_KH + so, v.x, v.y, v.z, v.w);
            v = pl[r*8 + c];
            STS128(sb + AT_KL + so, v.x, v.y, v.z, v.w);
        }
        __syncthreads();
        #pragma unroll
        for (int kk = 0; kk < 4; kk++) {
            uint32_t off = SWZ(a_row*128 + (kk*2 + a_half)*16);
            ldmx4(sb + AT_KH + off, qfh[kk]);
            ldmx4(sb + AT_KL + off, qfl[kk]);
        }
        __syncthreads();   // buf0 free for tile 0
    }

    float acc[8][4] = {};
    float mrow[2] = {-1e30f, -1e30f}, lrow[2] = {0.f, 0.f};

    const __nv_bfloat16* kh = khi + (size_t)bh*SEQ*DK;
    const __nv_bfloat16* kl = klo + (size_t)bh*SEQ*DK;
    const __half* vh = vhh + (size_t)bh*SEQ*DK;
    const __half* vl = vhl + (size_t)bh*SEQ*DK;
    const int* permb = perm + b*SEQ;

    const int n = __ldg(&ncnt[b]);
    const int nt = (n + 63) >> 6;

    attn_load_tile(sb, kh, kl, vh, vl, permb, 0, tid);
    CP_COMMIT();

    for (int t = 0; t < nt; t++) {
        uint32_t cb = sb + (uint32_t)((t & 1) ? AT_BUF : 0);
        uint32_t nb = sb + (uint32_t)((t & 1) ? 0 : AT_BUF);
        __syncthreads();   // all warps done reading buffer nb (tile t-1)
        if (t + 1 < nt) {
            attn_load_tile(nb, kh, kl, vh, vl, permb, (t+1)*64, tid);
            CP_COMMIT();
            CP_WAIT1();
        } else {
            CP_WAIT0();
        }
        __syncthreads();   // tile t visible to all

        // ---- S = Q K^T (3-pass split bf16) ----
        float s[8][4] = {};
        #pragma unroll
        for (int kk = 0; kk < 4; kk++) {
            #pragma unroll
            for (int g = 0; g < 4; g++) {
                uint32_t kh2[4], kl2[4];
                uint32_t boff = SWZ((g*16 + b_rowb)*128 + (kk*2 + b_half)*16);
                ldmx4(cb + AT_KH + boff, kh2);
                ldmx4(cb + AT_KL + boff, kl2);
                #pragma unroll
                for (int pr = 0; pr < 2; pr++) {
                    int j = g*2 + pr;
                    mma_bf(s[j], qfh[kk], kh2[pr*2], kh2[pr*2+1]);
                    mma_bf(s[j], qfh[kk], kl2[pr*2], kl2[pr*2+1]);
                    mma_bf(s[j], qfl[kk], kh2[pr*2], kh2[pr*2+1]);
                }
            }
        }

        // ---- tail mask (only last tile can be partial) ----
        int rem = n - t*64;
        if (rem < 64) {
            int c0 = 2*(lane & 3);
            #pragma unroll
            for (int j = 0; j < 8; j++) {
                if (j*8 + c0     >= rem) { s[j][0] = -1e9f; s[j][2] = -1e9f; }
                if (j*8 + c0 + 1 >= rem) { s[j][1] = -1e9f; s[j][3] = -1e9f; }
            }
        }

        // ---- online softmax ----
        float tlo = -1e30f, thi = -1e30f;
        #pragma unroll
        for (int j = 0; j < 8; j++) {
            tlo = fmaxf(tlo, fmaxf(s[j][0], s[j][1]));
            thi = fmaxf(thi, fmaxf(s[j][2], s[j][3]));
        }
        tlo = fmaxf(tlo, __shfl_xor_sync(0xffffffffu, tlo, 1));
        tlo = fmaxf(tlo, __shfl_xor_sync(0xffffffffu, tlo, 2));
        thi = fmaxf(thi, __shfl_xor_sync(0xffffffffu, thi, 1));
        thi = fmaxf(thi, __shfl_xor_sync(0xffffffffu, thi, 2));
        float mnlo = fmaxf(mrow[0], tlo), mnhi = fmaxf(mrow[1], thi);
        float alo = __expf(mrow[0] - mnlo), ahi = __expf(mrow[1] - mnhi);
        float slo = 0.f, shi = 0.f;
        uint32_t pf[8][2];
        #pragma unroll
        for (int j = 0; j < 8; j++) {
            float p0 = __expf(s[j][0] - mnlo), p1 = __expf(s[j][1] - mnlo);
            float p2 = __expf(s[j][2] - mnhi), p3 = __expf(s[j][3] - mnhi);
            slo += p0 + p1; shi += p2 + p3;
            __half2 h0 = __floats2half2_rn(p0, p1);
            __half2 h1 = __floats2half2_rn(p2, p3);
            pf[j][0] = *(uint32_t*)&h0; pf[j][1] = *(uint32_t*)&h1;
        }
        slo += __shfl_xor_sync(0xffffffffu, slo, 1);
        slo += __shfl_xor_sync(0xffffffffu, slo, 2);
        shi += __shfl_xor_sync(0xffffffffu, shi, 1);
        shi += __shfl_xor_sync(0xffffffffu, shi, 2);
        lrow[0] = lrow[0]*alo + slo; lrow[1] = lrow[1]*ahi + shi;
        mrow[0] = mnlo; mrow[1] = mnhi;
        #pragma unroll
        for (int j = 0; j < 8; j++) {
            acc[j][0] *= alo; acc[j][1] *= alo;
            acc[j][2] *= ahi; acc[j][3] *= ahi;
        }

        // ---- O += P V (P fp16, V split fp16, 2 passes) ----
        #pragma unroll
        for (int ks = 0; ks < 4; ks++) {
            uint32_t pa[4] = {pf[2*ks][0], pf[2*ks][1], pf[2*ks+1][0], pf[2*ks+1][1]};
            #pragma unroll
            for (int g = 0; g < 4; g++) {
                uint32_t vbh[4], vbl[4];
                uint32_t voff = SWZ((ks*16 + v_krow)*128 + (g*2 + v_dhalf)*16);
                ldmx4t(cb + AT_VH + voff, vbh);
                ldmx4t(cb + AT_VL + voff, vbl);
                #pragma unroll
                for (int pr = 0; pr < 2; pr++) {
                    int j = g*2 + pr;
                    mma_fp(acc[j], pa, vbh[pr*2], vbh[pr*2+1]);
                    mma_fp(acc[j], pa, vbl[pr*2], vbl[pr*2+1]);
                }
            }
        }
    }

    // ---- epilogue: x = acc / l, fp32, layout [b][s][h*64+d] ----
    float il0 = 1.0f / lrow[0], il1 = 1.0f / lrow[1];
    int r0g = q0 + w*16 + (lane >> 2);
    #pragma unroll
    for (int j = 0; j < 8; j++) {
        int d = j*8 + 2*(lane & 3);
        #pragma unroll
        for (int half = 0; half < 2; half++) {
            int srow = r0g + half*8;
            float il = half ? il1 : il0;
            float2 o;
            o.x = acc[j][half*2+0] * il;
            o.y = acc[j][half*2+1] * il;
            *(float2*)(xout + ((size_t)b*SEQ + srow)*DM + h*DK + d) = o;
        }
    }
}

// ---------------------------------------------------------------------------
extern "C" void kernel_launch(void* const* d_in, const int* in_sizes, int n_in,
                              void* d_out, int out_size)
{
    const float* query = (const float*)d_in[0];
    const float* key   = (const float*)d_in[1];
    const float* value = (const float*)d_in[2];
    const int*   mask  = (const int*)  d_in[3];
    const float* Wq    = (const float*)d_in[4];
    const float* bq    = (const float*)d_in[5];
    const float* Wk    = (const float*)d_in[6];
    const float* bk    = (const float*)d_in[7];
    const float* Wv    = (const float*)d_in[8];
    const float* bv    = (const float*)d_in[9];
    const float* Wo    = (const float*)d_in[10];
    const float* bo    = (const float*)d_in[11];
    float* out = (float*)d_out;

    __nv_bfloat16 *qhi, *qlo, *khi, *klo;
    __half *vh, *vl;
    float *px;
    int *perm, *ncnt;
    cudaGetSymbolAddress((void**)&qhi, g_qhi);
    cudaGetSymbolAddress((void**)&qlo, g_qlo);
    cudaGetSymbolAddress((void**)&khi, g_khi);
    cudaGetSymbolAddress((void**)&klo, g_klo);
    cudaGetSymbolAddress((void**)&vh, g_vh);
    cudaGetSymbolAddress((void**)&vl, g_vl);
    cudaGetSymbolAddress((void**)&px, g_x);
    cudaGetSymbolAddress((void**)&perm, g_perm);
    cudaGetSymbolAddress((void**)&ncnt, g_ncnt);

    cudaFuncSetAttribute(attn_tc, cudaFuncAttributeMaxDynamicSharedMemorySize, AT_SMEM);

    dim3 ggrid(DM/128, M_ROWS/64);     // (8, 64)
    dim3 agrid(SEQ/64, BATCH*NH);      // (32, 32)

    mask_scan<<<BATCH, 1024>>>(mask, perm, ncnt);

    gemm_f<<<ggrid, 256, G_SMEM>>>(query, Wq, bq, nullptr, qhi, qlo, nullptr, nullptr, 0.125f, 1);
    gemm_f<<<ggrid, 256, G_SMEM>>>(key,   Wk, bk, nullptr, khi, klo, nullptr, nullptr, 1.0f,   1);
    gemm_f<<<ggrid, 256, G_SMEM>>>(value, Wv, bv, nullptr, nullptr, nullptr, vh, vl,   1.0f,   2);

    attn_tc<<<agrid, 128, AT_SMEM>>>(qhi, qlo, khi, klo, vh, vl, perm, ncnt, px);

    gemm_f<<<ggrid, 256, G_SMEM>>>(px, Wo, bo, out, nullptr, nullptr, nullptr, nullptr, 1.0f, 0);
}

// round 5
// speedup vs baseline: 6.6509x; 1.4939x over previous
#include <cuda_runtime.h>
#include <cuda_bf16.h>
#include <cuda_fp16.h>
#include <cstdint>

// Problem constants
#define BATCH 2
#define SEQ   2048
#define DM    1024
#define NH    16
#define DK    64
#define M_ROWS (BATCH*SEQ)   // 4096

// ---------------------------------------------------------------------------
// Helpers (base-sm_103 features: ldmatrix + mma.sync + cp.async)
// ---------------------------------------------------------------------------
__device__ __forceinline__ uint32_t smem_to_u32(const void* p) {
    uint32_t a;
    asm("{ .reg .u64 t; cvta.to.shared.u64 t, %1; cvt.u32.u64 %0, t; }" : "=r"(a) : "l"(p));
    return a;
}
#define SWZ(o) ((uint32_t)(o) ^ ((((uint32_t)(o)) >> 3) & 0x70))

#define STS128(a, r0, r1, r2, r3) \
    asm volatile("st.shared.v4.b32 [%0], {%1, %2, %3, %4};" \
                 :: "r"(a), "r"(r0), "r"(r1), "r"(r2), "r"(r3) : "memory")
#define CP_ASYNC16(dst, src) \
    asm volatile("cp.async.cg.shared.global [%0], [%1], 16;" :: "r"(dst), "l"(src) : "memory")
#define CP_COMMIT() asm volatile("cp.async.commit_group;" ::: "memory")
#define CP_WAIT1()  asm volatile("cp.async.wait_group 1;" ::: "memory")
#define CP_WAIT0()  asm volatile("cp.async.wait_group 0;" ::: "memory")

__device__ __forceinline__ void ldmx4(uint32_t addr, uint32_t r[4]) {
    asm volatile("ldmatrix.sync.aligned.m8n8.x4.shared.b16 {%0,%1,%2,%3}, [%4];"
                 : "=r"(r[0]), "=r"(r[1]), "=r"(r[2]), "=r"(r[3]) : "r"(addr));
}
__device__ __forceinline__ void ldmx4t(uint32_t addr, uint32_t r[4]) {
    asm volatile("ldmatrix.sync.aligned.m8n8.x4.trans.shared.b16 {%0,%1,%2,%3}, [%4];"
                 : "=r"(r[0]), "=r"(r[1]), "=r"(r[2]), "=r"(r[3]) : "r"(addr));
}
__device__ __forceinline__ void mma_fp(float d[4], const uint32_t a[4],
                                       uint32_t b0, uint32_t b1) {
    asm volatile("mma.sync.aligned.m16n8k16.row.col.f32.f16.f16.f32 "
                 "{%0,%1,%2,%3}, {%4,%5,%6,%7}, {%8,%9}, {%0,%1,%2,%3};"
                 : "+f"(d[0]), "+f"(d[1]), "+f"(d[2]), "+f"(d[3])
                 : "r"(a[0]), "r"(a[1]), "r"(a[2]), "r"(a[3]), "r"(b0), "r"(b1));
}

// ---------------------------------------------------------------------------
// Scratch (device globals: allocation-free rule)
// ---------------------------------------------------------------------------
__device__ __half g_ah[M_ROWS*DM];            // A-side fp16 hi (reused per GEMM)
__device__ __half g_wh[DM*DM];                // W fp16 hi (reused)
__device__ __half g_wl[DM*DM];                // W fp16 lo (reused)
__device__ __half g_qh[BATCH*NH*SEQ*DK];
__device__ __half g_ql[BATCH*NH*SEQ*DK];
__device__ __half g_kh[BATCH*NH*SEQ*DK];
__device__ __half g_vh[BATCH*NH*SEQ*DK];
__device__ __half g_vl[BATCH*NH*SEQ*DK];
__device__ __half g_xh[M_ROWS*DM];
__device__ int    g_perm[BATCH*SEQ];
__device__ int    g_ncnt[BATCH];

// ---------------------------------------------------------------------------
// Converts: fp32 -> fp16 hi (and optionally lo), float4-vectorized
// ---------------------------------------------------------------------------
__global__ void __launch_bounds__(256)
cvt_hi(const float4* __restrict__ x, __half2* __restrict__ h, int n4)
{
    int i = blockIdx.x * blockDim.x + threadIdx.x;
    if (i < n4) {
        float4 v = x[i];
        h[2*i]   = __floats2half2_rn(v.x, v.y);
        h[2*i+1] = __floats2half2_rn(v.z, v.w);
    }
}
__global__ void __launch_bounds__(256)
cvt_hilo(const float4* __restrict__ x, __half2* __restrict__ h,
         __half2* __restrict__ l, int n4)
{
    int i = blockIdx.x * blockDim.x + threadIdx.x;
    if (i < n4) {
        float4 v = x[i];
        __half2 h0 = __floats2half2_rn(v.x, v.y);
        __half2 h1 = __floats2half2_rn(v.z, v.w);
        h[2*i] = h0; h[2*i+1] = h1;
        l[2*i]   = __floats2half2_rn(v.x - __half2float(h0.x), v.y - __half2float(h0.y));
        l[2*i+1] = __floats2half2_rn(v.z - __half2float(h1.x), v.w - __half2float(h1.y));
    }
}

// ---------------------------------------------------------------------------
// Deterministic mask compaction: 1 CTA per batch, Hillis-Steele scan.
// ---------------------------------------------------------------------------
__global__ void __launch_bounds__(1024)
mask_scan(const int* __restrict__ mask, int* __restrict__ perm, int* __restrict__ ncnt)
{
    __shared__ int sm[1024];
    int b = blockIdx.x, t = threadIdx.x;
    const int* m = mask + b*SEQ;
    int* pb = perm + b*SEQ;
    pb[2*t] = 0; pb[2*t+1] = 0;
    int a0 = (m[2*t] != 0), a1 = (m[2*t+1] != 0);
    int sum = a0 + a1;
    sm[t] = sum;
    __syncthreads();
    #pragma unroll
    for (int off = 1; off < 1024; off <<= 1) {
        int v = (t >= off) ? sm[t-off] : 0;
        __syncthreads();
        sm[t] += v;
        __syncthreads();
    }
    int excl = sm[t] - sum;
    if (a0) pb[excl] = 2*t;
    if (a1) pb[excl + a0] = 2*t + 1;
    if (t == 1023) ncnt[b] = sm[1023];
}

// ---------------------------------------------------------------------------
// Pure-fp16 2-pass NT GEMM, cp.async double-buffered.
// C = (Ah * (Wh+Wl)^T + bias) * scale
// BM=BN=128, BK=64, 256 threads (2m x 4n warps), warp tile 64x32.
// Buffer: Ah 16K @0, Wh 16K @16384, Wl 16K @32768; x2 buffers = 96KB dynamic.
// mode 0: fp32 flat. mode 1: fp16 hi+lo head layout. mode 2: fp16 hi head layout.
// ---------------------------------------------------------------------------
#define GB_STRIDE 49152
#define G2_SMEM   98304

__device__ __forceinline__ void g_load(uint32_t sbuf, const __half* Ah,
                                       const __half* Wh, const __half* Wl,
                                       int m0, int n0, int kc, int tid)
{
    #pragma unroll
    for (int it = 0; it < 4; it++) {
        int q = tid + it*256; int r = q >> 3, c = q & 7;
        uint32_t so = SWZ(r*128 + c*16);
        CP_ASYNC16(sbuf + so,         (const void*)(Ah + (size_t)(m0+r)*DM + kc + c*8));
        CP_ASYNC16(sbuf + 16384 + so, (const void*)(Wh + (size_t)(n0+r)*DM + kc + c*8));
        CP_ASYNC16(sbuf + 32768 + so, (const void*)(Wl + (size_t)(n0+r)*DM + kc + c*8));
    }
}

__global__ void __launch_bounds__(256, 2)
gemm_h(const __half* __restrict__ Ah, const __half* __restrict__ Wh,
       const __half* __restrict__ Wl, const float* __restrict__ bias,
       float* __restrict__ Cf, __half* __restrict__ Ch, __half* __restrict__ Cl,
       float scale, int mode)
{
    extern __shared__ char smem[];
    uint32_t sb = smem_to_u32(smem);
    const int tid = threadIdx.x, lane = tid & 31, wid = tid >> 5;
    const int wm = wid & 1, wn = wid >> 1;
    const int m0 = blockIdx.y * 128, n0 = blockIdx.x * 128;

    float acc[4][4][4] = {};

    int a_row[4], b_row[2];
    #pragma unroll
    for (int mt = 0; mt < 4; mt++) a_row[mt] = wm*64 + mt*16 + (lane & 15);
    #pragma unroll
    for (int g = 0; g < 2; g++)
        b_row[g] = wn*32 + g*16 + ((lane >> 4) << 3) + (lane & 7);
    const int a_half = lane >> 4;
    const int b_half = (lane >> 3) & 1;

    g_load(sb, Ah, Wh, Wl, m0, n0, 0, tid);
    CP_COMMIT();

    for (int ci = 0; ci < 16; ci++) {
        uint32_t cbuf = sb + (uint32_t)(ci & 1) * GB_STRIDE;
        if (ci + 1 < 16) {
            g_load(sb + (uint32_t)((ci+1) & 1) * GB_STRIDE, Ah, Wh, Wl,
                   m0, n0, (ci+1)*64, tid);
            CP_COMMIT();
            CP_WAIT1();
        } else {
            CP_WAIT0();
        }
        __syncthreads();
        #pragma unroll
        for (int kk = 0; kk < 4; kk++) {
            uint32_t af[4][4], bh2[2][4], bl2[2][4];
            #pragma unroll
            for (int mt = 0; mt < 4; mt++) {
                uint32_t off = SWZ(a_row[mt]*128 + (kk*2 + a_half)*16);
                ldmx4(cbuf + off, af[mt]);
            }
            #pragma unroll
            for (int g = 0; g < 2; g++) {
                uint32_t off = SWZ(b_row[g]*128 + (kk*2 + b_half)*16);
                ldmx4(cbuf + 16384 + off, bh2[g]);
                ldmx4(cbuf + 32768 + off, bl2[g]);
            }
            #pragma unroll
            for (int mt = 0; mt < 4; mt++)
                #pragma unroll
                for (int j = 0; j < 4; j++) {
                    int g = j >> 1, pr = (j & 1) * 2;
                    mma_fp(acc[mt][j], af[mt], bh2[g][pr], bh2[g][pr+1]);
                    mma_fp(acc[mt][j], af[mt], bl2[g][pr], bl2[g][pr+1]);
                }
        }
        __syncthreads();
    }

    // Epilogue
    #pragma unroll
    for (int mt = 0; mt < 4; mt++) {
        int r0 = m0 + wm*64 + mt*16 + (lane >> 2);
        #pragma unroll
        for (int j = 0; j < 4; j++) {
            int cb = n0 + wn*32 + j*8 + 2*(lane & 3);
            float b0 = __ldg(&bias[cb]), b1 = __ldg(&bias[cb+1]);
            #pragma unroll
            for (int half = 0; half < 2; half++) {
                int m = r0 + half*8;
                float x0 = (acc[mt][j][half*2+0] + b0) * scale;
                float x1 = (acc[mt][j][half*2+1] + b1) * scale;
                if (mode == 0) {
                    float2 o; o.x = x0; o.y = x1;
                    *(float2*)(Cf + (size_t)m*DM + cb) = o;
                } else {
                    int b = m >> 11, s = m & 2047, h = cb >> 6, d = cb & 63;
                    size_t idx = (((size_t)(b*NH + h))*SEQ + s)*DK + d;
                    __half2 h2 = __floats2half2_rn(x0, x1);
                    *(__half2*)(Ch + idx) = h2;
                    if (mode == 1) {
                        __half2 l2 = __floats2half2_rn(
                            x0 - __half2float(h2.x), x1 - __half2float(h2.y));
                        *(__half2*)(Cl + idx) = l2;
                    }
                }
            }
        }
    }
}

// ---------------------------------------------------------------------------
// Flash attention over COMPACTED keys, cp.async double buffer.
// QK: Q split fp16 hi/lo (registers), K single fp16 -> 2 passes.
// PV: P single fp16, V split fp16 -> 2 passes.
// CTA: 64 q-rows, 128 threads. Output fp16-hi x [b][s][h*64+d].
// ---------------------------------------------------------------------------
#define AT_KH 0
#define AT_VH 8192
#define AT_VL 16384
#define AT_STRIDE 24576
#define AT_SMEM 49152

__device__ __forceinline__ void attn_load_tile(
    uint32_t sbuf, const __half* kh, const __half* vh, const __half* vl,
    const int* permb, int kt, int tid)
{
    #pragma unroll
    for (int it = 0; it < 4; it++) {
        int q = tid + it*128; int r = q >> 3, c = q & 7;
        int s = __ldg(&permb[kt + r]);
        size_t ro = (size_t)s * DK + c*8;
        uint32_t so = SWZ(r*128 + c*16);
        CP_ASYNC16(sbuf + AT_KH + so, (const void*)(kh + ro));
        CP_ASYNC16(sbuf + AT_VH + so, (const void*)(vh + ro));
        CP_ASYNC16(sbuf + AT_VL + so, (const void*)(vl + ro));
    }
}

__global__ void __launch_bounds__(128)
attn_tc(const __half* __restrict__ qhp, const __half* __restrict__ qlp,
        const __half* __restrict__ khp, const __half* __restrict__ vhp,
        const __half* __restrict__ vlp,
        const int* __restrict__ perm, const int* __restrict__ ncnt,
        __half* __restrict__ xout)
{
    extern __shared__ char dsm[];
    uint32_t sb = smem_to_u32(dsm);

    const int tid = threadIdx.x, lane = tid & 31, w = tid >> 5;
    const int bh = blockIdx.y, b = bh >> 4, h = bh & 15;
    const int q0 = blockIdx.x * 64;

    const int a_row  = w*16 + (lane & 15);
    const int a_half = lane >> 4;
    const int b_rowb = ((lane >> 4) << 3) + (lane & 7);
    const int b_half = (lane >> 3) & 1;
    const int v_krow = ((lane >> 3) & 1)*8 + (lane & 7);
    const int v_dhalf = lane >> 4;

    // ---- Stage Q hi/lo through buf0, pull fragments into registers ----
    uint32_t qfh[4][4], qfl[4][4];
    {
        const uint4* ph = (const uint4*)(qhp + ((size_t)bh*SEQ + q0)*DK);
        const uint4* pl = (const uint4*)(qlp + ((size_t)bh*SEQ + q0)*DK);
        #pragma unroll
        for (int it = 0; it < 4; it++) {
            int q = tid + it*128; int r = q >> 3, c = q & 7;
            uint32_t so = SWZ(r*128 + c*16);
            uint4 v = ph[r*8 + c];
            STS128(sb + AT_KH + so, v.x, v.y, v.z, v.w);
            v = pl[r*8 + c];
            STS128(sb + AT_VH + so, v.x, v.y, v.z, v.w);
        }
        __syncthreads();
        #pragma unroll
        for (int kk = 0; kk < 4; kk++) {
            uint32_t off = SWZ(a_row*128 + (kk*2 + a_half)*16);
            ldmx4(sb + AT_KH + off, qfh[kk]);
            ldmx4(sb + AT_VH + off, qfl[kk]);
        }
        __syncthreads();   // buf0 free for tile 0
    }

    float acc[8][4] = {};
    float mrow[2] = {-1e30f, -1e30f}, lrow[2] = {0.f, 0.f};

    const __half* kh = khp + (size_t)bh*SEQ*DK;
    const __half* vh = vhp + (size_t)bh*SEQ*DK;
    const __half* vl = vlp + (size_t)bh*SEQ*DK;
    const int* permb = perm + b*SEQ;

    const int n = __ldg(&ncnt[b]);
    const int nt = (n + 63) >> 6;

    attn_load_tile(sb, kh, vh, vl, permb, 0, tid);
    CP_COMMIT();

    for (int t = 0; t < nt; t++) {
        uint32_t cb = sb + (uint32_t)(t & 1) * AT_STRIDE;
        if (t + 1 < nt) {
            attn_load_tile(sb + (uint32_t)((t+1) & 1) * AT_STRIDE,
                           kh, vh, vl, permb, (t+1)*64, tid);
            CP_COMMIT();
            CP_WAIT1();
        } else {
            CP_WAIT0();
        }
        __syncthreads();

        // ---- S = Q K^T (Q hi/lo, K single: 2 passes) ----
        float s[8][4] = {};
        #pragma unroll
        for (int kk = 0; kk < 4; kk++) {
            #pragma unroll
            for (int g = 0; g < 4; g++) {
                uint32_t kf[4];
                uint32_t boff = SWZ((g*16 + b_rowb)*128 + (kk*2 + b_half)*16);
                ldmx4(cb + AT_KH + boff, kf);
                #pragma unroll
                for (int pr = 0; pr < 2; pr++) {
                    int j = g*2 + pr;
                    mma_fp(s[j], qfh[kk], kf[pr*2], kf[pr*2+1]);
                    mma_fp(s[j], qfl[kk], kf[pr*2], kf[pr*2+1]);
                }
            }
        }

        // ---- tail mask (only last tile can be partial) ----
        int rem = n - t*64;
        if (rem < 64) {
            int c0 = 2*(lane & 3);
            #pragma unroll
            for (int j = 0; j < 8; j++) {
                if (j*8 + c0     >= rem) { s[j][0] = -1e9f; s[j][2] = -1e9f; }
                if (j*8 + c0 + 1 >= rem) { s[j][1] = -1e9f; s[j][3] = -1e9f; }
            }
        }

        // ---- online softmax ----
        float tlo = -1e30f, thi = -1e30f;
        #pragma unroll
        for (int j = 0; j < 8; j++) {
            tlo = fmaxf(tlo, fmaxf(s[j][0], s[j][1]));
            thi = fmaxf(thi, fmaxf(s[j][2], s[j][3]));
        }
        tlo = fmaxf(tlo, __shfl_xor_sync(0xffffffffu, tlo, 1));
        tlo = fmaxf(tlo, __shfl_xor_sync(0xffffffffu, tlo, 2));
        thi = fmaxf(thi, __shfl_xor_sync(0xffffffffu, thi, 1));
        thi = fmaxf(thi, __shfl_xor_sync(0xffffffffu, thi, 2));
        float mnlo = fmaxf(mrow[0], tlo), mnhi = fmaxf(mrow[1], thi);
        float alo = __expf(mrow[0] - mnlo), ahi = __expf(mrow[1] - mnhi);
        float slo = 0.f, shi = 0.f;
        uint32_t pf[8][2];
        #pragma unroll
        for (int j = 0; j < 8; j++) {
            float p0 = __expf(s[j][0] - mnlo), p1 = __expf(s[j][1] - mnlo);
            float p2 = __expf(s[j][2] - mnhi), p3 = __expf(s[j][3] - mnhi);
            slo += p0 + p1; shi += p2 + p3;
            __half2 h0 = __floats2half2_rn(p0, p1);
            __half2 h1 = __floats2half2_rn(p2, p3);
            pf[j][0] = *(uint32_t*)&h0; pf[j][1] = *(uint32_t*)&h1;
        }
        slo += __shfl_xor_sync(0xffffffffu, slo, 1);
        slo += __shfl_xor_sync(0xffffffffu, slo, 2);
        shi += __shfl_xor_sync(0xffffffffu, shi, 1);
        shi += __shfl_xor_sync(0xffffffffu, shi, 2);
        lrow[0] = lrow[0]*alo + slo; lrow[1] = lrow[1]*ahi + shi;
        mrow[0] = mnlo; mrow[1] = mnhi;
        #pragma unroll
        for (int j = 0; j < 8; j++) {
            acc[j][0] *= alo; acc[j][1] *= alo;
            acc[j][2] *= ahi; acc[j][3] *= ahi;
        }

        // ---- O += P V (P fp16, V split fp16: 2 passes) ----
        #pragma unroll
        for (int ks = 0; ks < 4; ks++) {
            uint32_t pa[4] = {pf[2*ks][0], pf[2*ks][1], pf[2*ks+1][0], pf[2*ks+1][1]};
            #pragma unroll
            for (int g = 0; g < 4; g++) {
                uint32_t vbh[4], vbl[4];
                uint32_t voff = SWZ((ks*16 + v_krow)*128 + (g*2 + v_dhalf)*16);
                ldmx4t(cb + AT_VH + voff, vbh);
                ldmx4t(cb + AT_VL + voff, vbl);
                #pragma unroll
                for (int pr = 0; pr < 2; pr++) {
                    int j = g*2 + pr;
                    mma_fp(acc[j], pa, vbh[pr*2], vbh[pr*2+1]);
                    mma_fp(acc[j], pa, vbl[pr*2], vbl[pr*2+1]);
                }
            }
        }
        __syncthreads();   // all warps done with buffer cb before reload
    }

    // ---- epilogue: x = acc / l, fp16 hi, layout [b][s][h*64+d] ----
    float il0 = 1.0f / lrow[0], il1 = 1.0f / lrow[1];
    int r0g = q0 + w*16 + (lane >> 2);
    #pragma unroll
    for (int j = 0; j < 8; j++) {
        int d = j*8 + 2*(lane & 3);
        #pragma unroll
        for (int half = 0; half < 2; half++) {
            int srow = r0g + half*8;
            float il = half ? il1 : il0;
            __half2 o = __floats2half2_rn(acc[j][half*2+0] * il,
                                          acc[j][half*2+1] * il);
            *(__half2*)(xout + ((size_t)b*SEQ + srow)*DM + h*DK + d) = o;
        }
    }
}

// ---------------------------------------------------------------------------
extern "C" void kernel_launch(void* const* d_in, const int* in_sizes, int n_in,
                              void* d_out, int out_size)
{
    const float* query = (const float*)d_in[0];
    const float* key   = (const float*)d_in[1];
    const float* value = (const float*)d_in[2];
    const int*   mask  = (const int*)  d_in[3];
    const float* Wq    = (const float*)d_in[4];
    const float* bq    = (const float*)d_in[5];
    const float* Wk    = (const float*)d_in[6];
    const float* bk    = (const float*)d_in[7];
    const float* Wv    = (const float*)d_in[8];
    const float* bv    = (const float*)d_in[9];
    const float* Wo    = (const float*)d_in[10];
    const float* bo    = (const float*)d_in[11];
    float* out = (float*)d_out;

    __half *ah, *wh, *wl, *qh, *ql, *kh, *vh, *vl, *xh;
    int *perm, *ncnt;
    cudaGetSymbolAddress((void**)&ah, g_ah);
    cudaGetSymbolAddress((void**)&wh, g_wh);
    cudaGetSymbolAddress((void**)&wl, g_wl);
    cudaGetSymbolAddress((void**)&qh, g_qh);
    cudaGetSymbolAddress((void**)&ql, g_ql);
    cudaGetSymbolAddress((void**)&kh, g_kh);
    cudaGetSymbolAddress((void**)&vh, g_vh);
    cudaGetSymbolAddress((void**)&vl, g_vl);
    cudaGetSymbolAddress((void**)&xh, g_xh);
    cudaGetSymbolAddress((void**)&perm, g_perm);
    cudaGetSymbolAddress((void**)&ncnt, g_ncnt);

    cudaFuncSetAttribute(gemm_h, cudaFuncAttributeMaxDynamicSharedMemorySize, G2_SMEM);
    cudaFuncSetAttribute(attn_tc, cudaFuncAttributeMaxDynamicSharedMemorySize, AT_SMEM);

    const int nA4 = M_ROWS*DM/4, nW4 = DM*DM/4;
    dim3 cgA((nA4 + 255)/256), cgW((nW4 + 255)/256);
    dim3 ggrid(DM/128, M_ROWS/128);    // (8, 32)
    dim3 agrid(SEQ/64, BATCH*NH);      // (32, 32)

    mask_scan<<<BATCH, 1024>>>(mask, perm, ncnt);

    // Q projection (scale 1/8 folded): needs hi+lo (Q is split side of QK)
    cvt_hi<<<cgA, 256>>>((const float4*)query, (__half2*)ah, nA4);
    cvt_hilo<<<cgW, 256>>>((const float4*)Wq, (__half2*)wh, (__half2*)wl, nW4);
    gemm_h<<<ggrid, 256, G2_SMEM>>>(ah, wh, wl, bq, nullptr, qh, ql, 0.125f, 1);
    // K projection: hi only
    cvt_hi<<<cgA, 256>>>((const float4*)key, (__half2*)ah, nA4);
    cvt_hilo<<<cgW, 256>>>((const float4*)Wk, (__half2*)wh, (__half2*)wl, nW4);
    gemm_h<<<ggrid, 256, G2_SMEM>>>(ah, wh, wl, bk, nullptr, kh, nullptr, 1.0f, 2);
    // V projection: hi+lo (V is split side of PV)
    cvt_hi<<<cgA, 256>>>((const float4*)value, (__half2*)ah, nA4);
    cvt_hilo<<<cgW, 256>>>((const float4*)Wv, (__half2*)wh, (__half2*)wl, nW4);
    gemm_h<<<ggrid, 256, G2_SMEM>>>(ah, wh, wl, bv, nullptr, vh, vl, 1.0f, 1);

    // Attention -> xh (fp16 hi, flat layout)
    attn_tc<<<agrid, 128, AT_SMEM>>>(qh, ql, kh, vh, vl, perm, ncnt, xh);

    // Output projection (xh is already fp16 A-side)
    cvt_hilo<<<cgW, 256>>>((const float4*)Wo, (__half2*)wh, (__half2*)wl, nW4);
    gemm_h<<<ggrid, 256, G2_SMEM>>>(xh, wh, wl, bo, out, nullptr, nullptr, 1.0f, 0);
}

// round 6
// speedup vs baseline: 7.8667x; 1.1828x over previous
#include <cuda_runtime.h>
#include <cuda_bf16.h>
#include <cuda_fp16.h>
#include <cstdint>

// Problem constants
#define BATCH 2
#define SEQ   2048
#define DM    1024
#define NH    16
#define DK    64
#define M_ROWS (BATCH*SEQ)   // 4096
#define NA (M_ROWS*DM)
#define NW (DM*DM)

// ---------------------------------------------------------------------------
// Helpers (base-sm_103 features: ldmatrix + mma.sync + cp.async)
// ---------------------------------------------------------------------------
__device__ __forceinline__ uint32_t smem_to_u32(const void* p) {
    uint32_t a;
    asm("{ .reg .u64 t; cvta.to.shared.u64 t, %1; cvt.u32.u64 %0, t; }" : "=r"(a) : "l"(p));
    return a;
}
#define SWZ(o) ((uint32_t)(o) ^ ((((uint32_t)(o)) >> 3) & 0x70))

#define STS128(a, r0, r1, r2, r3) \
    asm volatile("st.shared.v4.b32 [%0], {%1, %2, %3, %4};" \
                 :: "r"(a), "r"(r0), "r"(r1), "r"(r2), "r"(r3) : "memory")
#define CP_ASYNC16(dst, src) \
    asm volatile("cp.async.cg.shared.global [%0], [%1], 16;" :: "r"(dst), "l"(src) : "memory")
#define CP_COMMIT() asm volatile("cp.async.commit_group;" ::: "memory")
#define CP_WAIT1()  asm volatile("cp.async.wait_group 1;" ::: "memory")
#define CP_WAIT0()  asm volatile("cp.async.wait_group 0;" ::: "memory")

__device__ __forceinline__ void ldmx4(uint32_t addr, uint32_t r[4]) {
    asm volatile("ldmatrix.sync.aligned.m8n8.x4.shared.b16 {%0,%1,%2,%3}, [%4];"
                 : "=r"(r[0]), "=r"(r[1]), "=r"(r[2]), "=r"(r[3]) : "r"(addr));
}
__device__ __forceinline__ void ldmx4t(uint32_t addr, uint32_t r[4]) {
    asm volatile("ldmatrix.sync.aligned.m8n8.x4.trans.shared.b16 {%0,%1,%2,%3}, [%4];"
                 : "=r"(r[0]), "=r"(r[1]), "=r"(r[2]), "=r"(r[3]) : "r"(addr));
}
__device__ __forceinline__ void mma_fp(float d[4], const uint32_t a[4],
                                       uint32_t b0, uint32_t b1) {
    asm volatile("mma.sync.aligned.m16n8k16.row.col.f32.f16.f16.f32 "
                 "{%0,%1,%2,%3}, {%4,%5,%6,%7}, {%8,%9}, {%0,%1,%2,%3};"
                 : "+f"(d[0]), "+f"(d[1]), "+f"(d[2]), "+f"(d[3])
                 : "r"(a[0]), "r"(a[1]), "r"(a[2]), "r"(a[3]), "r"(b0), "r"(b1));
}

// ---------------------------------------------------------------------------
// Scratch (device globals: allocation-free rule)
// ---------------------------------------------------------------------------
__device__ __half g_ah3[3*NA];                // converted q/k/v inputs (fp16 hi)
__device__ __half g_wh4[4*NW];                // Wq,Wk,Wv,Wo fp16 hi
__device__ __half g_wl4[4*NW];                // Wq,Wk,Wv,Wo fp16 lo
__device__ __half g_qh[BATCH*NH*SEQ*DK];
__device__ __half g_kh[BATCH*NH*SEQ*DK];
__device__ __half g_vh[BATCH*NH*SEQ*DK];
__device__ __half g_vl[BATCH*NH*SEQ*DK];
__device__ __half g_xh[NA];
__device__ int    g_perm[BATCH*SEQ];
__device__ int    g_ncnt[BATCH];

// ---------------------------------------------------------------------------
// Batched converts
// ---------------------------------------------------------------------------
__global__ void __launch_bounds__(256)
cvt_in3(const float4* __restrict__ q, const float4* __restrict__ k,
        const float4* __restrict__ v, __half2* __restrict__ dst)
{
    int z = blockIdx.y;
    const float4* src = (z == 0) ? q : (z == 1) ? k : v;
    int i = blockIdx.x * blockDim.x + threadIdx.x;
    float4 w = src[i];
    __half2* h = dst + (size_t)z*(NA/2);
    h[2*i]   = __floats2half2_rn(w.x, w.y);
    h[2*i+1] = __floats2half2_rn(w.z, w.w);
}
__global__ void __launch_bounds__(256)
cvt_w4(const float4* __restrict__ wq, const float4* __restrict__ wk,
       const float4* __restrict__ wv, const float4* __restrict__ wo,
       __half2* __restrict__ hd, __half2* __restrict__ ld)
{
    int z = blockIdx.y;
    const float4* src = (z == 0) ? wq : (z == 1) ? wk : (z == 2) ? wv : wo;
    int i = blockIdx.x * blockDim.x + threadIdx.x;
    float4 w = src[i];
    __half2 h0 = __floats2half2_rn(w.x, w.y);
    __half2 h1 = __floats2half2_rn(w.z, w.w);
    __half2* h = hd + (size_t)z*(NW/2);
    __half2* l = ld + (size_t)z*(NW/2);
    h[2*i] = h0; h[2*i+1] = h1;
    l[2*i]   = __floats2half2_rn(w.x - __half2float(h0.x), w.y - __half2float(h0.y));
    l[2*i+1] = __floats2half2_rn(w.z - __half2float(h1.x), w.w - __half2float(h1.y));
}

// ---------------------------------------------------------------------------
// Deterministic mask compaction: 1 CTA per batch, Hillis-Steele scan.
// ---------------------------------------------------------------------------
__global__ void __launch_bounds__(1024)
mask_scan(const int* __restrict__ mask, int* __restrict__ perm, int* __restrict__ ncnt)
{
    __shared__ int sm[1024];
    int b = blockIdx.x, t = threadIdx.x;
    const int* m = mask + b*SEQ;
    int* pb = perm + b*SEQ;
    pb[2*t] = 0; pb[2*t+1] = 0;
    int a0 = (m[2*t] != 0), a1 = (m[2*t+1] != 0);
    int sum = a0 + a1;
    sm[t] = sum;
    __syncthreads();
    #pragma unroll
    for (int off = 1; off < 1024; off <<= 1) {
        int v = (t >= off) ? sm[t-off] : 0;
        __syncthreads();
        sm[t] += v;
        __syncthreads();
    }
    int excl = sm[t] - sum;
    if (a0) pb[excl] = 2*t;
    if (a1) pb[excl + a0] = 2*t + 1;
    if (t == 1023) ncnt[b] = sm[1023];
}

// ---------------------------------------------------------------------------
// Pure-fp16 2-pass NT GEMM core, cp.async double-buffered, chain-free MMAs.
// BM=BN=128, BK=64, 256 threads (2m x 4n warps), warp tile 64x32.
// mode 0: fp32 flat. mode 1: fp16 hi+lo head layout. mode 2: fp16 hi head.
// ---------------------------------------------------------------------------
#define GB_STRIDE 49152
#define G2_SMEM   98304

__device__ __forceinline__ void g_load(uint32_t sbuf, const __half* Ah,
                                       const __half* Wh, const __half* Wl,
                                       int m0, int n0, int kc, int tid)
{
    #pragma unroll
    for (int it = 0; it < 4; it++) {
        int q = tid + it*256; int r = q >> 3, c = q & 7;
        uint32_t so = SWZ(r*128 + c*16);
        CP_ASYNC16(sbuf + so,         (const void*)(Ah + (size_t)(m0+r)*DM + kc + c*8));
        CP_ASYNC16(sbuf + 16384 + so, (const void*)(Wh + (size_t)(n0+r)*DM + kc + c*8));
        CP_ASYNC16(sbuf + 32768 + so, (const void*)(Wl + (size_t)(n0+r)*DM + kc + c*8));
    }
}

__device__ __forceinline__ void gemm_core(
    const __half* __restrict__ Ah, const __half* __restrict__ Wh,
    const __half* __restrict__ Wl, const float* __restrict__ bias,
    float* __restrict__ Cf, __half* __restrict__ Ch, __half* __restrict__ Cl,
    float scale, int mode, char* smem)
{
    uint32_t sb = smem_to_u32(smem);
    const int tid = threadIdx.x, lane = tid & 31, wid = tid >> 5;
    const int wm = wid & 1, wn = wid >> 1;
    const int m0 = blockIdx.y * 128, n0 = blockIdx.x * 128;

    float acc[4][4][4] = {};

    int a_row[4], b_row[2];
    #pragma unroll
    for (int mt = 0; mt < 4; mt++) a_row[mt] = wm*64 + mt*16 + (lane & 15);
    #pragma unroll
    for (int g = 0; g < 2; g++)
        b_row[g] = wn*32 + g*16 + ((lane >> 4) << 3) + (lane & 7);
    const int a_half = lane >> 4;
    const int b_half = (lane >> 3) & 1;

    g_load(sb, Ah, Wh, Wl, m0, n0, 0, tid);
    CP_COMMIT();

    for (int ci = 0; ci < 16; ci++) {
        uint32_t cbuf = sb + (uint32_t)(ci & 1) * GB_STRIDE;
        if (ci + 1 < 16) {
            g_load(sb + (uint32_t)((ci+1) & 1) * GB_STRIDE, Ah, Wh, Wl,
                   m0, n0, (ci+1)*64, tid);
            CP_COMMIT();
            CP_WAIT1();
        } else {
            CP_WAIT0();
        }
        __syncthreads();
        #pragma unroll
        for (int kk = 0; kk < 4; kk++) {
            uint32_t af[4][4], bh2[2][4], bl2[2][4];
            #pragma unroll
            for (int mt = 0; mt < 4; mt++) {
                uint32_t off = SWZ(a_row[mt]*128 + (kk*2 + a_half)*16);
                ldmx4(cbuf + off, af[mt]);
            }
            #pragma unroll
            for (int g = 0; g < 2; g++) {
                uint32_t off = SWZ(b_row[g]*128 + (kk*2 + b_half)*16);
                ldmx4(cbuf + 16384 + off, bh2[g]);
                ldmx4(cbuf + 32768 + off, bl2[g]);
            }
            // hi pass: 16 independent accumulators, no RAW chain
            #pragma unroll
            for (int mt = 0; mt < 4; mt++)
                #pragma unroll
                for (int j = 0; j < 4; j++) {
                    int g = j >> 1, pr = (j & 1) * 2;
                    mma_fp(acc[mt][j], af[mt], bh2[g][pr], bh2[g][pr+1]);
                }
            // lo pass
            #pragma unroll
            for (int mt = 0; mt < 4; mt++)
                #pragma unroll
                for (int j = 0; j < 4; j++) {
                    int g = j >> 1, pr = (j & 1) * 2;
                    mma_fp(acc[mt][j], af[mt], bl2[g][pr], bl2[g][pr+1]);
                }
        }
        __syncthreads();
    }

    // Epilogue
    #pragma unroll
    for (int mt = 0; mt < 4; mt++) {
        int r0 = m0 + wm*64 + mt*16 + (lane >> 2);
        #pragma unroll
        for (int j = 0; j < 4; j++) {
            int cb = n0 + wn*32 + j*8 + 2*(lane & 3);
            float b0 = __ldg(&bias[cb]), b1 = __ldg(&bias[cb+1]);
            #pragma unroll
            for (int half = 0; half < 2; half++) {
                int m = r0 + half*8;
                float x0 = (acc[mt][j][half*2+0] + b0) * scale;
                float x1 = (acc[mt][j][half*2+1] + b1) * scale;
                if (mode == 0) {
                    float2 o; o.x = x0; o.y = x1;
                    *(float2*)(Cf + (size_t)m*DM + cb) = o;
                } else {
                    int b = m >> 11, s = m & 2047, h = cb >> 6, d = cb & 63;
                    size_t idx = (((size_t)(b*NH + h))*SEQ + s)*DK + d;
                    __half2 h2 = __floats2half2_rn(x0, x1);
                    *(__half2*)(Ch + idx) = h2;
                    if (mode == 1) {
                        __half2 l2 = __floats2half2_rn(
                            x0 - __half2float(h2.x), x1 - __half2float(h2.y));
                        *(__half2*)(Cl + idx) = l2;
                    }
                }
            }
        }
    }
}

// Q/K/V projections in one launch (z selects)
__global__ void __launch_bounds__(256, 2)
proj3(const __half* __restrict__ A3,
      const __half* __restrict__ Wh4, const __half* __restrict__ Wl4,
      const float* __restrict__ bq, const float* __restrict__ bk,
      const float* __restrict__ bv,
      __half* __restrict__ qh, __half* __restrict__ kh,
      __half* __restrict__ vh, __half* __restrict__ vl)
{
    extern __shared__ char smem[];
    int z = blockIdx.z;
    const __half* Ah = A3 + (size_t)z*NA;
    const __half* Wh = Wh4 + (size_t)z*NW;
    const __half* Wl = Wl4 + (size_t)z*NW;
    const float* bias = (z == 0) ? bq : (z == 1) ? bk : bv;
    __half* Ch = (z == 0) ? qh : (z == 1) ? kh : vh;
    __half* Cl = (z == 2) ? vl : nullptr;
    int mode = (z == 2) ? 1 : 2;
    float scale = (z == 0) ? 0.125f : 1.0f;
    gemm_core(Ah, Wh, Wl, bias, nullptr, Ch, Cl, scale, mode, smem);
}

// Output projection
__global__ void __launch_bounds__(256, 2)
gemm_o(const __half* __restrict__ Ah,
       const __half* __restrict__ Wh, const __half* __restrict__ Wl,
       const float* __restrict__ bias, float* __restrict__ Cf)
{
    extern __shared__ char smem[];
    gemm_core(Ah, Wh, Wl, bias, Cf, nullptr, nullptr, 1.0f, 0, smem);
}

// ---------------------------------------------------------------------------
// Flash attention over COMPACTED keys, cp.async double buffer.
// QK: single fp16 pass. PV: P fp16, V split fp16 (pass-separated, chain-free).
// CTA: 64 q-rows, 128 threads. Output fp16 x [b][s][h*64+d].
// ---------------------------------------------------------------------------
#define AT_KH 0
#define AT_VH 8192
#define AT_VL 16384
#define AT_STRIDE 24576
#define AT_SMEM 49152

__device__ __forceinline__ void attn_load_tile(
    uint32_t sbuf, const __half* kh, const __half* vh, const __half* vl,
    const int* permb, int kt, int tid)
{
    #pragma unroll
    for (int it = 0; it < 4; it++) {
        int q = tid + it*128; int r = q >> 3, c = q & 7;
        int s = __ldg(&permb[kt + r]);
        size_t ro = (size_t)s * DK + c*8;
        uint32_t so = SWZ(r*128 + c*16);
        CP_ASYNC16(sbuf + AT_KH + so, (const void*)(kh + ro));
        CP_ASYNC16(sbuf + AT_VH + so, (const void*)(vh + ro));
        CP_ASYNC16(sbuf + AT_VL + so, (const void*)(vl + ro));
    }
}

__global__ void __launch_bounds__(128)
attn_tc(const __half* __restrict__ qhp, const __half* __restrict__ khp,
        const __half* __restrict__ vhp, const __half* __restrict__ vlp,
        const int* __restrict__ perm, const int* __restrict__ ncnt,
        __half* __restrict__ xout)
{
    extern __shared__ char dsm[];
    uint32_t sb = smem_to_u32(dsm);

    const int tid = threadIdx.x, lane = tid & 31, w = tid >> 5;
    const int bh = blockIdx.y, b = bh >> 4, h = bh & 15;
    const int q0 = blockIdx.x * 64;

    const int a_row  = w*16 + (lane & 15);
    const int a_half = lane >> 4;
    const int b_rowb = ((lane >> 4) << 3) + (lane & 7);
    const int b_half = (lane >> 3) & 1;
    const int v_krow = ((lane >> 3) & 1)*8 + (lane & 7);
    const int v_dhalf = lane >> 4;

    // ---- Stage Q (hi only) through buf0, pull fragments into registers ----
    uint32_t qfh[4][4];
    {
        const uint4* ph = (const uint4*)(qhp + ((size_t)bh*SEQ + q0)*DK);
        #pragma unroll
        for (int it = 0; it < 4; it++) {
            int q = tid + it*128; int r = q >> 3, c = q & 7;
            uint32_t so = SWZ(r*128 + c*16);
            uint4 v = ph[r*8 + c];
            STS128(sb + AT_KH + so, v.x, v.y, v.z, v.w);
        }
        __syncthreads();
        #pragma unroll
        for (int kk = 0; kk < 4; kk++) {
            uint32_t off = SWZ(a_row*128 + (kk*2 + a_half)*16);
            ldmx4(sb + AT_KH + off, qfh[kk]);
        }
        __syncthreads();   // buf0 free for tile 0
    }

    float acc[8][4] = {};
    float mrow[2] = {-1e30f, -1e30f}, lrow[2] = {0.f, 0.f};

    const __half* kh = khp + (size_t)bh*SEQ*DK;
    const __half* vh = vhp + (size_t)bh*SEQ*DK;
    const __half* vl = vlp + (size_t)bh*SEQ*DK;
    const int* permb = perm + b*SEQ;

    const int n = __ldg(&ncnt[b]);
    const int nt = (n + 63) >> 6;

    attn_load_tile(sb, kh, vh, vl, permb, 0, tid);
    CP_COMMIT();

    for (int t = 0; t < nt; t++) {
        uint32_t cb = sb + (uint32_t)(t & 1) * AT_STRIDE;
        if (t + 1 < nt) {
            attn_load_tile(sb + (uint32_t)((t+1) & 1) * AT_STRIDE,
                           kh, vh, vl, permb, (t+1)*64, tid);
            CP_COMMIT();
            CP_WAIT1();
        } else {
            CP_WAIT0();
        }
        __syncthreads();

        // ---- S = Q K^T (single fp16 pass; s[j] reuse distance 8) ----
        float s[8][4] = {};
        #pragma unroll
        for (int kk = 0; kk < 4; kk++) {
            #pragma unroll
            for (int g = 0; g < 4; g++) {
                uint32_t kf[4];
                uint32_t boff = SWZ((g*16 + b_rowb)*128 + (kk*2 + b_half)*16);
                ldmx4(cb + AT_KH + boff, kf);
                #pragma unroll
                for (int pr = 0; pr < 2; pr++)
                    mma_fp(s[g*2 + pr], qfh[kk], kf[pr*2], kf[pr*2+1]);
            }
        }

        // ---- tail mask (only last tile can be partial) ----
        int rem = n - t*64;
        if (rem < 64) {
            int c0 = 2*(lane & 3);
            #pragma unroll
            for (int j = 0; j < 8; j++) {
                if (j*8 + c0     >= rem) { s[j][0] = -1e9f; s[j][2] = -1e9f; }
                if (j*8 + c0 + 1 >= rem) { s[j][1] = -1e9f; s[j][3] = -1e9f; }
            }
        }

        // ---- online softmax ----
        float tlo = -1e30f, thi = -1e30f;
        #pragma unroll
        for (int j = 0; j < 8; j++) {
            tlo = fmaxf(tlo, fmaxf(s[j][0], s[j][1]));
            thi = fmaxf(thi, fmaxf(s[j][2], s[j][3]));
        }
        tlo = fmaxf(tlo, __shfl_xor_sync(0xffffffffu, tlo, 1));
        tlo = fmaxf(tlo, __shfl_xor_sync(0xffffffffu, tlo, 2));
        thi = fmaxf(thi, __shfl_xor_sync(0xffffffffu, thi, 1));
        thi = fmaxf(thi, __shfl_xor_sync(0xffffffffu, thi, 2));
        float mnlo = fmaxf(mrow[0], tlo), mnhi = fmaxf(mrow[1], thi);
        float alo = __expf(mrow[0] - mnlo), ahi = __expf(mrow[1] - mnhi);
        float slo = 0.f, shi = 0.f;
        uint32_t pf[8][2];
        #pragma unroll
        for (int j = 0; j < 8; j++) {
            float p0 = __expf(s[j][0] - mnlo), p1 = __expf(s[j][1] - mnlo);
            float p2 = __expf(s[j][2] - mnhi), p3 = __expf(s[j][3] - mnhi);
            slo += p0 + p1; shi += p2 + p3;
            __half2 h0 = __floats2half2_rn(p0, p1);
            __half2 h1 = __floats2half2_rn(p2, p3);
            pf[j][0] = *(uint32_t*)&h0; pf[j][1] = *(uint32_t*)&h1;
        }
        slo += __shfl_xor_sync(0xffffffffu, slo, 1);
        slo += __shfl_xor_sync(0xffffffffu, slo, 2);
        shi += __shfl_xor_sync(0xffffffffu, shi, 1);
        shi += __shfl_xor_sync(0xffffffffu, shi, 2);
        lrow[0] = lrow[0]*alo + slo; lrow[1] = lrow[1]*ahi + shi;
        mrow[0] = mnlo; mrow[1] = mnhi;
        #pragma unroll
        for (int j = 0; j < 8; j++) {
            acc[j][0] *= alo; acc[j][1] *= alo;
            acc[j][2] *= ahi; acc[j][3] *= ahi;
        }

        // ---- O += P V: pass-separated (hi sweep then lo sweep) ----
        #pragma unroll
        for (int ks = 0; ks < 4; ks++) {
            uint32_t pa[4] = {pf[2*ks][0], pf[2*ks][1], pf[2*ks+1][0], pf[2*ks+1][1]};
            uint32_t vbh[4][4], vbl[4][4];
            #pragma unroll
            for (int g = 0; g < 4; g++) {
                uint32_t voff = SWZ((ks*16 + v_krow)*128 + (g*2 + v_dhalf)*16);
                ldmx4t(cb + AT_VH + voff, vbh[g]);
                ldmx4t(cb + AT_VL + voff, vbl[g]);
            }
            #pragma unroll
            for (int g = 0; g < 4; g++)
                #pragma unroll
                for (int pr = 0; pr < 2; pr++)
                    mma_fp(acc[g*2+pr], pa, vbh[g][pr*2], vbh[g][pr*2+1]);
            #pragma unroll
            for (int g = 0; g < 4; g++)
                #pragma unroll
                for (int pr = 0; pr < 2; pr++)
                    mma_fp(acc[g*2+pr], pa, vbl[g][pr*2], vbl[g][pr*2+1]);
        }
        __syncthreads();   // all warps done with buffer cb before reload
    }

    // ---- epilogue: x = acc / l, fp16 hi, layout [b][s][h*64+d] ----
    float il0 = 1.0f / lrow[0], il1 = 1.0f / lrow[1];
    int r0g = q0 + w*16 + (lane >> 2);
    #pragma unroll
    for (int j = 0; j < 8; j++) {
        int d = j*8 + 2*(lane & 3);
        #pragma unroll
        for (int half = 0; half < 2; half++) {
            int srow = r0g + half*8;
            float il = half ? il1 : il0;
            __half2 o = __floats2half2_rn(acc[j][half*2+0] * il,
                                          acc[j][half*2+1] * il);
            *(__half2*)(xout + ((size_t)b*SEQ + srow)*DM + h*DK + d) = o;
        }
    }
}

// ---------------------------------------------------------------------------
extern "C" void kernel_launch(void* const* d_in, const int* in_sizes, int n_in,
                              void* d_out, int out_size)
{
    const float* query = (const float*)d_in[0];
    const float* key   = (const float*)d_in[1];
    const float* value = (const float*)d_in[2];
    const int*   mask  = (const int*)  d_in[3];
    const float* Wq    = (const float*)d_in[4];
    const float* bq    = (const float*)d_in[5];
    const float* Wk    = (const float*)d_in[6];
    const float* bk    = (const float*)d_in[7];
    const float* Wv    = (const float*)d_in[8];
    const float* bv    = (const float*)d_in[9];
    const float* Wo    = (const float*)d_in[10];
    const float* bo    = (const float*)d_in[11];
    float* out = (float*)d_out;

    __half *ah3, *wh4, *wl4, *qh, *kh, *vh, *vl, *xh;
    int *perm, *ncnt;
    cudaGetSymbolAddress((void**)&ah3, g_ah3);
    cudaGetSymbolAddress((void**)&wh4, g_wh4);
    cudaGetSymbolAddress((void**)&wl4, g_wl4);
    cudaGetSymbolAddress((void**)&qh, g_qh);
    cudaGetSymbolAddress((void**)&kh, g_kh);
    cudaGetSymbolAddress((void**)&vh, g_vh);
    cudaGetSymbolAddress((void**)&vl, g_vl);
    cudaGetSymbolAddress((void**)&xh, g_xh);
    cudaGetSymbolAddress((void**)&perm, g_perm);
    cudaGetSymbolAddress((void**)&ncnt, g_ncnt);

    cudaFuncSetAttribute(proj3,  cudaFuncAttributeMaxDynamicSharedMemorySize, G2_SMEM);
    cudaFuncSetAttribute(gemm_o, cudaFuncAttributeMaxDynamicSharedMemorySize, G2_SMEM);
    cudaFuncSetAttribute(attn_tc, cudaFuncAttributeMaxDynamicSharedMemorySize, AT_SMEM);

    const int nA4 = NA/4, nW4 = NW/4;
    dim3 cgA(nA4/256, 3), cgW(nW4/256, 4);
    dim3 pgrid(DM/128, M_ROWS/128, 3);   // (8, 32, 3)
    dim3 ogrid(DM/128, M_ROWS/128);      // (8, 32)
    dim3 agrid(SEQ/64, BATCH*NH);        // (32, 32)

    mask_scan<<<BATCH, 1024>>>(mask, perm, ncnt);
    cvt_in3<<<cgA, 256>>>((const float4*)query, (const float4*)key,
                          (const float4*)value, (__half2*)ah3);
    cvt_w4<<<cgW, 256>>>((const float4*)Wq, (const float4*)Wk,
                         (const float4*)Wv, (const float4*)Wo,
                         (__half2*)wh4, (__half2*)wl4);

    proj3<<<pgrid, 256, G2_SMEM>>>(ah3, wh4, wl4, bq, bk, bv, qh, kh, vh, vl);

    attn_tc<<<agrid, 128, AT_SMEM>>>(qh, kh, vh, vl, perm, ncnt, xh);

    gemm_o<<<ogrid, 256, G2_SMEM>>>(xh, wh4 + 3*(size_t)NW, wl4 + 3*(size_t)NW, bo, out);
}

// round 7
// speedup vs baseline: 7.9808x; 1.0145x over previous
#include <cuda_runtime.h>
#include <cuda_bf16.h>
#include <cuda_fp16.h>
#include <cstdint>

// Problem constants
#define BATCH 2
#define SEQ   2048
#define DM    1024
#define NH    16
#define DK    64
#define M_ROWS (BATCH*SEQ)   // 4096
#define NA (M_ROWS*DM)
#define NW (DM*DM)

// ---------------------------------------------------------------------------
// Helpers (base-sm_103 features: ldmatrix + mma.sync + cp.async)
// ---------------------------------------------------------------------------
__device__ __forceinline__ uint32_t smem_to_u32(const void* p) {
    uint32_t a;
    asm("{ .reg .u64 t; cvta.to.shared.u64 t, %1; cvt.u32.u64 %0, t; }" : "=r"(a) : "l"(p));
    return a;
}
#define SWZ(o) ((uint32_t)(o) ^ ((((uint32_t)(o)) >> 3) & 0x70))

#define STS128(a, r0, r1, r2, r3) \
    asm volatile("st.shared.v4.b32 [%0], {%1, %2, %3, %4};" \
                 :: "r"(a), "r"(r0), "r"(r1), "r"(r2), "r"(r3) : "memory")
#define CP_ASYNC16(dst, src) \
    asm volatile("cp.async.cg.shared.global [%0], [%1], 16;" :: "r"(dst), "l"(src) : "memory")
#define CP_COMMIT() asm volatile("cp.async.commit_group;" ::: "memory")
#define CP_WAIT1()  asm volatile("cp.async.wait_group 1;" ::: "memory")
#define CP_WAIT0()  asm volatile("cp.async.wait_group 0;" ::: "memory")

__device__ __forceinline__ void ldmx4(uint32_t addr, uint32_t r[4]) {
    asm volatile("ldmatrix.sync.aligned.m8n8.x4.shared.b16 {%0,%1,%2,%3}, [%4];"
                 : "=r"(r[0]), "=r"(r[1]), "=r"(r[2]), "=r"(r[3]) : "r"(addr));
}
__device__ __forceinline__ void ldmx4t(uint32_t addr, uint32_t r[4]) {
    asm volatile("ldmatrix.sync.aligned.m8n8.x4.trans.shared.b16 {%0,%1,%2,%3}, [%4];"
                 : "=r"(r[0]), "=r"(r[1]), "=r"(r[2]), "=r"(r[3]) : "r"(addr));
}
__device__ __forceinline__ void mma_fp(float d[4], const uint32_t a[4],
                                       uint32_t b0, uint32_t b1) {
    asm volatile("mma.sync.aligned.m16n8k16.row.col.f32.f16.f16.f32 "
                 "{%0,%1,%2,%3}, {%4,%5,%6,%7}, {%8,%9}, {%0,%1,%2,%3};"
                 : "+f"(d[0]), "+f"(d[1]), "+f"(d[2]), "+f"(d[3])
                 : "r"(a[0]), "r"(a[1]), "r"(a[2]), "r"(a[3]), "r"(b0), "r"(b1));
}

// ---------------------------------------------------------------------------
// Scratch (device globals: allocation-free rule)
// ---------------------------------------------------------------------------
__device__ __half g_ah3[3*NA];                // converted q/k/v inputs (fp16 hi)
__device__ __half g_wh4[4*NW];                // Wq,Wk,Wv,Wo fp16 hi
__device__ __half g_wl4[4*NW];                // Wq,Wk,Wv,Wo fp16 lo
__device__ __half g_qh[BATCH*NH*SEQ*DK];
__device__ __half g_kh[BATCH*NH*SEQ*DK];
__device__ __half g_vh[BATCH*NH*SEQ*DK];
__device__ __half g_xh[NA];
__device__ int    g_perm[BATCH*SEQ];
__device__ int    g_ncnt[BATCH];

// ---------------------------------------------------------------------------
// Batched converts
// ---------------------------------------------------------------------------
__global__ void __launch_bounds__(256)
cvt_in3(const float4* __restrict__ q, const float4* __restrict__ k,
        const float4* __restrict__ v, __half2* __restrict__ dst)
{
    int z = blockIdx.y;
    const float4* src = (z == 0) ? q : (z == 1) ? k : v;
    int i = blockIdx.x * blockDim.x + threadIdx.x;
    float4 w = src[i];
    __half2* h = dst + (size_t)z*(NA/2);
    h[2*i]   = __floats2half2_rn(w.x, w.y);
    h[2*i+1] = __floats2half2_rn(w.z, w.w);
}
__global__ void __launch_bounds__(256)
cvt_w4(const float4* __restrict__ wq, const float4* __restrict__ wk,
       const float4* __restrict__ wv, const float4* __restrict__ wo,
       __half2* __restrict__ hd, __half2* __restrict__ ld)
{
    int z = blockIdx.y;
    const float4* src = (z == 0) ? wq : (z == 1) ? wk : (z == 2) ? wv : wo;
    int i = blockIdx.x * blockDim.x + threadIdx.x;
    float4 w = src[i];
    __half2 h0 = __floats2half2_rn(w.x, w.y);
    __half2 h1 = __floats2half2_rn(w.z, w.w);
    __half2* h = hd + (size_t)z*(NW/2);
    __half2* l = ld + (size_t)z*(NW/2);
    h[2*i] = h0; h[2*i+1] = h1;
    l[2*i]   = __floats2half2_rn(w.x - __half2float(h0.x), w.y - __half2float(h0.y));
    l[2*i+1] = __floats2half2_rn(w.z - __half2float(h1.x), w.w - __half2float(h1.y));
}

// ---------------------------------------------------------------------------
// Deterministic mask compaction: 1 CTA per batch, Hillis-Steele scan.
// ---------------------------------------------------------------------------
__global__ void __launch_bounds__(1024)
mask_scan(const int* __restrict__ mask, int* __restrict__ perm, int* __restrict__ ncnt)
{
    __shared__ int sm[1024];
    int b = blockIdx.x, t = threadIdx.x;
    const int* m = mask + b*SEQ;
    int* pb = perm + b*SEQ;
    pb[2*t] = 0; pb[2*t+1] = 0;
    int a0 = (m[2*t] != 0), a1 = (m[2*t+1] != 0);
    int sum = a0 + a1;
    sm[t] = sum;
    __syncthreads();
    #pragma unroll
    for (int off = 1; off < 1024; off <<= 1) {
        int v = (t >= off) ? sm[t-off] : 0;
        __syncthreads();
        sm[t] += v;
        __syncthreads();
    }
    int excl = sm[t] - sum;
    if (a0) pb[excl] = 2*t;
    if (a1) pb[excl + a0] = 2*t + 1;
    if (t == 1023) ncnt[b] = sm[1023];
}

// ---------------------------------------------------------------------------
// Pure-fp16 2-pass NT GEMM core, cp.async double-buffered, chain-free MMAs.
// BM=BN=128, BK=64, 256 threads (2m x 4n warps), warp tile 64x32.
// mode 0: fp32 flat. mode 2: fp16 hi head layout.
// ---------------------------------------------------------------------------
#define GB_STRIDE 49152
#define G2_SMEM   98304

__device__ __forceinline__ void g_load(uint32_t sbuf, const __half* Ah,
                                       const __half* Wh, const __half* Wl,
                                       int m0, int n0, int kc, int tid)
{
    #pragma unroll
    for (int it = 0; it < 4; it++) {
        int q = tid + it*256; int r = q >> 3, c = q & 7;
        uint32_t so = SWZ(r*128 + c*16);
        CP_ASYNC16(sbuf + so,         (const void*)(Ah + (size_t)(m0+r)*DM + kc + c*8));
        CP_ASYNC16(sbuf + 16384 + so, (const void*)(Wh + (size_t)(n0+r)*DM + kc + c*8));
        CP_ASYNC16(sbuf + 32768 + so, (const void*)(Wl + (size_t)(n0+r)*DM + kc + c*8));
    }
}

__device__ __forceinline__ void gemm_core(
    const __half* __restrict__ Ah, const __half* __restrict__ Wh,
    const __half* __restrict__ Wl, const float* __restrict__ bias,
    float* __restrict__ Cf, __half* __restrict__ Ch,
    float scale, int mode, char* smem)
{
    uint32_t sb = smem_to_u32(smem);
    const int tid = threadIdx.x, lane = tid & 31, wid = tid >> 5;
    const int wm = wid & 1, wn = wid >> 1;
    const int m0 = blockIdx.y * 128, n0 = blockIdx.x * 128;

    float acc[4][4][4] = {};

    int a_row[4], b_row[2];
    #pragma unroll
    for (int mt = 0; mt < 4; mt++) a_row[mt] = wm*64 + mt*16 + (lane & 15);
    #pragma unroll
    for (int g = 0; g < 2; g++)
        b_row[g] = wn*32 + g*16 + ((lane >> 4) << 3) + (lane & 7);
    const int a_half = lane >> 4;
    const int b_half = (lane >> 3) & 1;

    g_load(sb, Ah, Wh, Wl, m0, n0, 0, tid);
    CP_COMMIT();

    for (int ci = 0; ci < 16; ci++) {
        uint32_t cbuf = sb + (uint32_t)(ci & 1) * GB_STRIDE;
        if (ci + 1 < 16) {
            g_load(sb + (uint32_t)((ci+1) & 1) * GB_STRIDE, Ah, Wh, Wl,
                   m0, n0, (ci+1)*64, tid);
            CP_COMMIT();
            CP_WAIT1();
        } else {
            CP_WAIT0();
        }
        __syncthreads();
        #pragma unroll
        for (int kk = 0; kk < 4; kk++) {
            uint32_t af[4][4], bh2[2][4], bl2[2][4];
            #pragma unroll
            for (int mt = 0; mt < 4; mt++) {
                uint32_t off = SWZ(a_row[mt]*128 + (kk*2 + a_half)*16);
                ldmx4(cbuf + off, af[mt]);
            }
            #pragma unroll
            for (int g = 0; g < 2; g++) {
                uint32_t off = SWZ(b_row[g]*128 + (kk*2 + b_half)*16);
                ldmx4(cbuf + 16384 + off, bh2[g]);
                ldmx4(cbuf + 32768 + off, bl2[g]);
            }
            // hi pass: 16 independent accumulators, no RAW chain
            #pragma unroll
            for (int mt = 0; mt < 4; mt++)
                #pragma unroll
                for (int j = 0; j < 4; j++) {
                    int g = j >> 1, pr = (j & 1) * 2;
                    mma_fp(acc[mt][j], af[mt], bh2[g][pr], bh2[g][pr+1]);
                }
            // lo pass
            #pragma unroll
            for (int mt = 0; mt < 4; mt++)
                #pragma unroll
                for (int j = 0; j < 4; j++) {
                    int g = j >> 1, pr = (j & 1) * 2;
                    mma_fp(acc[mt][j], af[mt], bl2[g][pr], bl2[g][pr+1]);
                }
        }
        __syncthreads();
    }

    // Epilogue
    #pragma unroll
    for (int mt = 0; mt < 4; mt++) {
        int r0 = m0 + wm*64 + mt*16 + (lane >> 2);
        #pragma unroll
        for (int j = 0; j < 4; j++) {
            int cb = n0 + wn*32 + j*8 + 2*(lane & 3);
            float b0 = __ldg(&bias[cb]), b1 = __ldg(&bias[cb+1]);
            #pragma unroll
            for (int half = 0; half < 2; half++) {
                int m = r0 + half*8;
                float x0 = (acc[mt][j][half*2+0] + b0) * scale;
                float x1 = (acc[mt][j][half*2+1] + b1) * scale;
                if (mode == 0) {
                    float2 o; o.x = x0; o.y = x1;
                    *(float2*)(Cf + (size_t)m*DM + cb) = o;
                } else {
                    int b = m >> 11, s = m & 2047, h = cb >> 6, d = cb & 63;
                    size_t idx = (((size_t)(b*NH + h))*SEQ + s)*DK + d;
                    *(__half2*)(Ch + idx) = __floats2half2_rn(x0, x1);
                }
            }
        }
    }
}

// Q/K/V projections in one launch (z selects)
__global__ void __launch_bounds__(256, 2)
proj3(const __half* __restrict__ A3,
      const __half* __restrict__ Wh4, const __half* __restrict__ Wl4,
      const float* __restrict__ bq, const float* __restrict__ bk,
      const float* __restrict__ bv,
      __half* __restrict__ qh, __half* __restrict__ kh, __half* __restrict__ vh)
{
    extern __shared__ char smem[];
    int z = blockIdx.z;
    const __half* Ah = A3 + (size_t)z*NA;
    const __half* Wh = Wh4 + (size_t)z*NW;
    const __half* Wl = Wl4 + (size_t)z*NW;
    const float* bias = (z == 0) ? bq : (z == 1) ? bk : bv;
    __half* Ch = (z == 0) ? qh : (z == 1) ? kh : vh;
    float scale = (z == 0) ? 0.125f : 1.0f;
    gemm_core(Ah, Wh, Wl, bias, nullptr, Ch, scale, 2, smem);
}

// Output projection
__global__ void __launch_bounds__(256, 2)
gemm_o(const __half* __restrict__ Ah,
       const __half* __restrict__ Wh, const __half* __restrict__ Wl,
       const float* __restrict__ bias, float* __restrict__ Cf)
{
    extern __shared__ char smem[];
    gemm_core(Ah, Wh, Wl, bias, Cf, nullptr, 1.0f, 0, smem);
}

// ---------------------------------------------------------------------------
// Flash attention over COMPACTED keys, 128-key tiles, cp.async double buffer.
// QK: single fp16. PV: P fp16, V fp16 (single pass), exp fused into PV loop.
// CTA: 64 q-rows, 128 threads. Output fp16 x [b][s][h*64+d].
// ---------------------------------------------------------------------------
#define AT_K 0
#define AT_V 16384
#define AT_STRIDE 32768
#define AT_SMEM 65536

__device__ __forceinline__ void attn_load_tile(
    uint32_t sbuf, const __half* kh, const __half* vh,
    const int* permb, int kt, int tid)
{
    #pragma unroll
    for (int it = 0; it < 8; it++) {
        int q = tid + it*128; int r = q >> 3, c = q & 7;
        int s = __ldg(&permb[kt + r]);
        size_t ro = (size_t)s * DK + c*8;
        uint32_t so = SWZ(r*128 + c*16);
        CP_ASYNC16(sbuf + AT_K + so, (const void*)(kh + ro));
        CP_ASYNC16(sbuf + AT_V + so, (const void*)(vh + ro));
    }
}

__global__ void __launch_bounds__(128, 2)
attn_tc(const __half* __restrict__ qhp, const __half* __restrict__ khp,
        const __half* __restrict__ vhp,
        const int* __restrict__ perm, const int* __restrict__ ncnt,
        __half* __restrict__ xout)
{
    extern __shared__ char dsm[];
    uint32_t sb = smem_to_u32(dsm);

    const int tid = threadIdx.x, lane = tid & 31, w = tid >> 5;
    const int bh = blockIdx.y, b = bh >> 4, h = bh & 15;
    const int q0 = blockIdx.x * 64;

    const int a_row  = w*16 + (lane & 15);
    const int a_half = lane >> 4;
    const int b_rowb = ((lane >> 4) << 3) + (lane & 7);
    const int b_half = (lane >> 3) & 1;
    const int v_krow = ((lane >> 3) & 1)*8 + (lane & 7);
    const int v_dhalf = lane >> 4;

    // ---- Stage Q through buf0 K region, pull fragments into registers ----
    uint32_t qfh[4][4];
    {
        const uint4* ph = (const uint4*)(qhp + ((size_t)bh*SEQ + q0)*DK);
        #pragma unroll
        for (int it = 0; it < 4; it++) {
            int q = tid + it*128; int r = q >> 3, c = q & 7;
            uint32_t so = SWZ(r*128 + c*16);
            uint4 v = ph[r*8 + c];
            STS128(sb + AT_K + so, v.x, v.y, v.z, v.w);
        }
        __syncthreads();
        #pragma unroll
        for (int kk = 0; kk < 4; kk++) {
            uint32_t off = SWZ(a_row*128 + (kk*2 + a_half)*16);
            ldmx4(sb + AT_K + off, qfh[kk]);
        }
        __syncthreads();   // buf0 free for tile 0
    }

    float acc[8][4] = {};
    float mrow[2] = {-1e30f, -1e30f}, lrow[2] = {0.f, 0.f};

    const __half* kh = khp + (size_t)bh*SEQ*DK;
    const __half* vh = vhp + (size_t)bh*SEQ*DK;
    const int* permb = perm + b*SEQ;

    const int n = __ldg(&ncnt[b]);
    const int nt = (n + 127) >> 7;

    attn_load_tile(sb, kh, vh, permb, 0, tid);
    CP_COMMIT();

    for (int t = 0; t < nt; t++) {
        uint32_t cb = sb + (uint32_t)(t & 1) * AT_STRIDE;
        if (t + 1 < nt) {
            attn_load_tile(sb + (uint32_t)((t+1) & 1) * AT_STRIDE,
                           kh, vh, permb, (t+1)*128, tid);
            CP_COMMIT();
            CP_WAIT1();
        } else {
            CP_WAIT0();
        }
        __syncthreads();

        // ---- S = Q K^T over 128 keys (single fp16 pass) ----
        float s[16][4] = {};
        #pragma unroll
        for (int kk = 0; kk < 4; kk++) {
            #pragma unroll
            for (int g = 0; g < 8; g++) {
                uint32_t kf[4];
                uint32_t boff = SWZ((g*16 + b_rowb)*128 + (kk*2 + b_half)*16);
                ldmx4(cb + AT_K + boff, kf);
                #pragma unroll
                for (int pr = 0; pr < 2; pr++)
                    mma_fp(s[g*2 + pr], qfh[kk], kf[pr*2], kf[pr*2+1]);
            }
        }

        // ---- tail mask (only last tile can be partial) ----
        int rem = n - t*128;
        if (rem < 128) {
            int c0 = 2*(lane & 3);
            #pragma unroll
            for (int j = 0; j < 16; j++) {
                if (j*8 + c0     >= rem) { s[j][0] = -1e9f; s[j][2] = -1e9f; }
                if (j*8 + c0 + 1 >= rem) { s[j][1] = -1e9f; s[j][3] = -1e9f; }
            }
        }

        // ---- online softmax: max reduce, rescale acc ----
        float tlo = -1e30f, thi = -1e30f;
        #pragma unroll
        for (int j = 0; j < 16; j++) {
            tlo = fmaxf(tlo, fmaxf(s[j][0], s[j][1]));
            thi = fmaxf(thi, fmaxf(s[j][2], s[j][3]));
        }
        tlo = fmaxf(tlo, __shfl_xor_sync(0xffffffffu, tlo, 1));
        tlo = fmaxf(tlo, __shfl_xor_sync(0xffffffffu, tlo, 2));
        thi = fmaxf(thi, __shfl_xor_sync(0xffffffffu, thi, 1));
        thi = fmaxf(thi, __shfl_xor_sync(0xffffffffu, thi, 2));
        float mnlo = fmaxf(mrow[0], tlo), mnhi = fmaxf(mrow[1], thi);
        float alo = __expf(mrow[0] - mnlo), ahi = __expf(mrow[1] - mnhi);
        mrow[0] = mnlo; mrow[1] = mnhi;
        #pragma unroll
        for (int j = 0; j < 8; j++) {
            acc[j][0] *= alo; acc[j][1] *= alo;
            acc[j][2] *= ahi; acc[j][3] *= ahi;
        }

        // ---- fused exp + PV over 8 x 16-key chunks ----
        float slo = 0.f, shi = 0.f;
        #pragma unroll
        for (int ks = 0; ks < 8; ks++) {
            uint32_t pa[4];
            #pragma unroll
            for (int jj = 0; jj < 2; jj++) {
                int j = 2*ks + jj;
                float p0 = __expf(s[j][0] - mnlo), p1 = __expf(s[j][1] - mnlo);
                float p2 = __expf(s[j][2] - mnhi), p3 = __expf(s[j][3] - mnhi);
                slo += p0 + p1; shi += p2 + p3;
                __half2 h0 = __floats2half2_rn(p0, p1);
                __half2 h1 = __floats2half2_rn(p2, p3);
                pa[jj*2]   = *(uint32_t*)&h0;
                pa[jj*2+1] = *(uint32_t*)&h1;
            }
            #pragma unroll
            for (int g = 0; g < 4; g++) {
                uint32_t vb[4];
                uint32_t voff = SWZ((ks*16 + v_krow)*128 + (g*2 + v_dhalf)*16);
                ldmx4t(cb + AT_V + voff, vb);
                #pragma unroll
                for (int pr = 0; pr < 2; pr++)
                    mma_fp(acc[g*2+pr], pa, vb[pr*2], vb[pr*2+1]);
            }
        }
        slo += __shfl_xor_sync(0xffffffffu, slo, 1);
        slo += __shfl_xor_sync(0xffffffffu, slo, 2);
        shi += __shfl_xor_sync(0xffffffffu, shi, 1);
        shi += __shfl_xor_sync(0xffffffffu, shi, 2);
        lrow[0] = lrow[0]*alo + slo; lrow[1] = lrow[1]*ahi + shi;

        __syncthreads();   // all warps done with buffer cb before reload
    }

    // ---- epilogue: x = acc / l, fp16, layout [b][s][h*64+d] ----
    float il0 = 1.0f / lrow[0], il1 = 1.0f / lrow[1];
    int r0g = q0 + w*16 + (lane >> 2);
    #pragma unroll
    for (int j = 0; j < 8; j++) {
        int d = j*8 + 2*(lane & 3);
        #pragma unroll
        for (int half = 0; half < 2; half++) {
            int srow = r0g + half*8;
            float il = half ? il1 : il0;
            __half2 o = __floats2half2_rn(acc[j][half*2+0] * il,
                                          acc[j][half*2+1] * il);
            *(__half2*)(xout + ((size_t)b*SEQ + srow)*DM + h*DK + d) = o;
        }
    }
}

// ---------------------------------------------------------------------------
extern "C" void kernel_launch(void* const* d_in, const int* in_sizes, int n_in,
                              void* d_out, int out_size)
{
    const float* query = (const float*)d_in[0];
    const float* key   = (const float*)d_in[1];
    const float* value = (const float*)d_in[2];
    const int*   mask  = (const int*)  d_in[3];
    const float* Wq    = (const float*)d_in[4];
    const float* bq    = (const float*)d_in[5];
    const float* Wk    = (const float*)d_in[6];
    const float* bk    = (const float*)d_in[7];
    const float* Wv    = (const float*)d_in[8];
    const float* bv    = (const float*)d_in[9];
    const float* Wo    = (const float*)d_in[10];
    const float* bo    = (const float*)d_in[11];
    float* out = (float*)d_out;

    __half *ah3, *wh4, *wl4, *qh, *kh, *vh, *xh;
    int *perm, *ncnt;
    cudaGetSymbolAddress((void**)&ah3, g_ah3);
    cudaGetSymbolAddress((void**)&wh4, g_wh4);
    cudaGetSymbolAddress((void**)&wl4, g_wl4);
    cudaGetSymbolAddress((void**)&qh, g_qh);
    cudaGetSymbolAddress((void**)&kh, g_kh);
    cudaGetSymbolAddress((void**)&vh, g_vh);
    cudaGetSymbolAddress((void**)&xh, g_xh);
    cudaGetSymbolAddress((void**)&perm, g_perm);
    cudaGetSymbolAddress((void**)&ncnt, g_ncnt);

    cudaFuncSetAttribute(proj3,  cudaFuncAttributeMaxDynamicSharedMemorySize, G2_SMEM);
    cudaFuncSetAttribute(gemm_o, cudaFuncAttributeMaxDynamicSharedMemorySize, G2_SMEM);
    cudaFuncSetAttribute(attn_tc, cudaFuncAttributeMaxDynamicSharedMemorySize, AT_SMEM);

    const int nA4 = NA/4, nW4 = NW/4;
    dim3 cgA(nA4/256, 3), cgW(nW4/256, 4);
    dim3 pgrid(DM/128, M_ROWS/128, 3);   // (8, 32, 3)
    dim3 ogrid(DM/128, M_ROWS/128);      // (8, 32)
    dim3 agrid(SEQ/64, BATCH*NH);        // (32, 32)

    mask_scan<<<BATCH, 1024>>>(mask, perm, ncnt);
    cvt_in3<<<cgA, 256>>>((const float4*)query, (const float4*)key,
                          (const float4*)value, (__half2*)ah3);
    cvt_w4<<<cgW, 256>>>((const float4*)Wq, (const float4*)Wk,
                         (const float4*)Wv, (const float4*)Wo,
                         (__half2*)wh4, (__half2*)wl4);

    proj3<<<pgrid, 256, G2_SMEM>>>(ah3, wh4, wl4, bq, bk, bv, qh, kh, vh);

    attn_tc<<<agrid, 128, AT_SMEM>>>(qh, kh, vh, perm, ncnt, xh);

    gemm_o<<<ogrid, 256, G2_SMEM>>>(xh, wh4 + 3*(size_t)NW, wl4 + 3*(size_t)NW, bo, out);
}

// round 8
// speedup vs baseline: 9.0115x; 1.1291x over previous
#include <cuda_runtime.h>
#include <cuda_bf16.h>
#include <cuda_fp16.h>
#include <cstdint>

// Problem constants
#define BATCH 2
#define SEQ   2048
#define DM    1024
#define NH    16
#define DK    64
#define M_ROWS (BATCH*SEQ)   // 4096
#define NA (M_ROWS*DM)
#define NW (DM*DM)

// ---------------------------------------------------------------------------
// Helpers (base-sm_103 features: ldmatrix + mma.sync + cp.async)
// ---------------------------------------------------------------------------
__device__ __forceinline__ uint32_t smem_to_u32(const void* p) {
    uint32_t a;
    asm("{ .reg .u64 t; cvta.to.shared.u64 t, %1; cvt.u32.u64 %0, t; }" : "=r"(a) : "l"(p));
    return a;
}
#define SWZ(o) ((uint32_t)(o) ^ ((((uint32_t)(o)) >> 3) & 0x70))

#define STS128(a, r0, r1, r2, r3) \
    asm volatile("st.shared.v4.b32 [%0], {%1, %2, %3, %4};" \
                 :: "r"(a), "r"(r0), "r"(r1), "r"(r2), "r"(r3) : "memory")
#define CP_ASYNC16(dst, src) \
    asm volatile("cp.async.cg.shared.global [%0], [%1], 16;" :: "r"(dst), "l"(src) : "memory")
#define CP_COMMIT() asm volatile("cp.async.commit_group;" ::: "memory")
#define CP_WAIT1()  asm volatile("cp.async.wait_group 1;" ::: "memory")
#define CP_WAIT0()  asm volatile("cp.async.wait_group 0;" ::: "memory")

__device__ __forceinline__ void ldmx4(uint32_t addr, uint32_t r[4]) {
    asm volatile("ldmatrix.sync.aligned.m8n8.x4.shared.b16 {%0,%1,%2,%3}, [%4];"
                 : "=r"(r[0]), "=r"(r[1]), "=r"(r[2]), "=r"(r[3]) : "r"(addr));
}
__device__ __forceinline__ void ldmx4t(uint32_t addr, uint32_t r[4]) {
    asm volatile("ldmatrix.sync.aligned.m8n8.x4.trans.shared.b16 {%0,%1,%2,%3}, [%4];"
                 : "=r"(r[0]), "=r"(r[1]), "=r"(r[2]), "=r"(r[3]) : "r"(addr));
}
__device__ __forceinline__ void mma_fp(float d[4], const uint32_t a[4],
                                       uint32_t b0, uint32_t b1) {
    asm volatile("mma.sync.aligned.m16n8k16.row.col.f32.f16.f16.f32 "
                 "{%0,%1,%2,%3}, {%4,%5,%6,%7}, {%8,%9}, {%0,%1,%2,%3};"
                 : "+f"(d[0]), "+f"(d[1]), "+f"(d[2]), "+f"(d[3])
                 : "r"(a[0]), "r"(a[1]), "r"(a[2]), "r"(a[3]), "r"(b0), "r"(b1));
}

// ---------------------------------------------------------------------------
// Scratch (device globals: allocation-free rule)
// ---------------------------------------------------------------------------
__device__ __half g_ah3[3*NA];                // converted q/k/v inputs (fp16 hi)
__device__ __half g_wh4[4*NW];                // Wq,Wk,Wv,Wo fp16 hi
__device__ __half g_wl4[4*NW];                // Wq,Wk,Wv,Wo fp16 lo (Wv,Wo used)
__device__ __half g_qh[BATCH*NH*SEQ*DK];
__device__ __half g_kh[BATCH*NH*SEQ*DK];
__device__ __half g_vh[BATCH*NH*SEQ*DK];
__device__ __half g_xh[NA];
__device__ int    g_perm[BATCH*SEQ];
__device__ int    g_ncnt[BATCH];

// ---------------------------------------------------------------------------
// Unified convert: z 0..2 -> inputs (hi only), z 3..6 -> weights (hi+lo)
// Input grids sized for NW/4 per z-slice; inputs take 4 z-slices each? No:
// inputs are NA=4*NW, so z=0..2 each handled with gx covering NA/4 chunks.
// Simpler: two grid ranges in one launch using blockIdx.y in [0, 3*4 + 4).
// y in [0,12): input slice y/4 quarter y%4. y in [12,16): weight y-12.
// ---------------------------------------------------------------------------
__global__ void __launch_bounds__(256)
cvt_all(const float4* __restrict__ q, const float4* __restrict__ k,
        const float4* __restrict__ v,
        const float4* __restrict__ wq, const float4* __restrict__ wk,
        const float4* __restrict__ wv, const float4* __restrict__ wo,
        __half2* __restrict__ in_h, __half2* __restrict__ w_h,
        __half2* __restrict__ w_l)
{
    const int y = blockIdx.y;
    const int i = blockIdx.x * blockDim.x + threadIdx.x;   // < NW/4
    if (y < 12) {
        int z = y >> 2, quad = y & 3;
        const float4* src = ((z == 0) ? q : (z == 1) ? k : v) + (size_t)quad*(NW/4);
        __half2* h = in_h + (size_t)z*(NA/2) + (size_t)quad*(NW/2);
        float4 w = src[i];
        h[2*i]   = __floats2half2_rn(w.x, w.y);
        h[2*i+1] = __floats2half2_rn(w.z, w.w);
    } else {
        int z = y - 12;
        const float4* src = (z == 0) ? wq : (z == 1) ? wk : (z == 2) ? wv : wo;
        float4 w = src[i];
        __half2 h0 = __floats2half2_rn(w.x, w.y);
        __half2 h1 = __floats2half2_rn(w.z, w.w);
        __half2* h = w_h + (size_t)z*(NW/2);
        h[2*i] = h0; h[2*i+1] = h1;
        if (z >= 2) {  // only Wv, Wo need lo
            __half2* l = w_l + (size_t)z*(NW/2);
            l[2*i]   = __floats2half2_rn(w.x - __half2float(h0.x), w.y - __half2float(h0.y));
            l[2*i+1] = __floats2half2_rn(w.z - __half2float(h1.x), w.w - __half2float(h1.y));
        }
    }
}

// ---------------------------------------------------------------------------
// Deterministic mask compaction: 1 CTA per batch, Hillis-Steele scan.
// ---------------------------------------------------------------------------
__global__ void __launch_bounds__(1024)
mask_scan(const int* __restrict__ mask, int* __restrict__ perm, int* __restrict__ ncnt)
{
    __shared__ int sm[1024];
    int b = blockIdx.x, t = threadIdx.x;
    const int* m = mask + b*SEQ;
    int* pb = perm + b*SEQ;
    pb[2*t] = 0; pb[2*t+1] = 0;
    int a0 = (m[2*t] != 0), a1 = (m[2*t+1] != 0);
    int sum = a0 + a1;
    sm[t] = sum;
    __syncthreads();
    #pragma unroll
    for (int off = 1; off < 1024; off <<= 1) {
        int v = (t >= off) ? sm[t-off] : 0;
        __syncthreads();
        sm[t] += v;
        __syncthreads();
    }
    int excl = sm[t] - sum;
    if (a0) pb[excl] = 2*t;
    if (a1) pb[excl + a0] = 2*t + 1;
    if (t == 1023) ncnt[b] = sm[1023];
}

// ---------------------------------------------------------------------------
// fp16 NT GEMM core, cp.async double-buffered, chain-free MMAs.
// twopass=1: C = A*(Wh+Wl)^T; twopass=0: C = A*Wh^T (Wl never touched).
// BM=BN=128, BK=64, 256 threads (2m x 4n warps), warp tile 64x32.
// mode 0: fp32 flat. mode 2: fp16 head layout.
// ---------------------------------------------------------------------------
#define GB_STRIDE 49152
#define G2_SMEM   98304

__device__ __forceinline__ void g_load(uint32_t sbuf, const __half* Ah,
                                       const __half* Wh, const __half* Wl,
                                       int m0, int n0, int kc, int tid, int twopass)
{
    #pragma unroll
    for (int it = 0; it < 4; it++) {
        int q = tid + it*256; int r = q >> 3, c = q & 7;
        uint32_t so = SWZ(r*128 + c*16);
        CP_ASYNC16(sbuf + so,         (const void*)(Ah + (size_t)(m0+r)*DM + kc + c*8));
        CP_ASYNC16(sbuf + 16384 + so, (const void*)(Wh + (size_t)(n0+r)*DM + kc + c*8));
        if (twopass)
            CP_ASYNC16(sbuf + 32768 + so, (const void*)(Wl + (size_t)(n0+r)*DM + kc + c*8));
    }
}

__device__ __forceinline__ void gemm_core(
    const __half* __restrict__ Ah, const __half* __restrict__ Wh,
    const __half* __restrict__ Wl, const float* __restrict__ bias,
    float* __restrict__ Cf, __half* __restrict__ Ch,
    float scale, int mode, int twopass, char* smem)
{
    uint32_t sb = smem_to_u32(smem);
    const int tid = threadIdx.x, lane = tid & 31, wid = tid >> 5;
    const int wm = wid & 1, wn = wid >> 1;
    const int m0 = blockIdx.y * 128, n0 = blockIdx.x * 128;

    float acc[4][4][4] = {};

    int a_row[4], b_row[2];
    #pragma unroll
    for (int mt = 0; mt < 4; mt++) a_row[mt] = wm*64 + mt*16 + (lane & 15);
    #pragma unroll
    for (int g = 0; g < 2; g++)
        b_row[g] = wn*32 + g*16 + ((lane >> 4) << 3) + (lane & 7);
    const int a_half = lane >> 4;
    const int b_half = (lane >> 3) & 1;

    g_load(sb, Ah, Wh, Wl, m0, n0, 0, tid, twopass);
    CP_COMMIT();

    for (int ci = 0; ci < 16; ci++) {
        uint32_t cbuf = sb + (uint32_t)(ci & 1) * GB_STRIDE;
        if (ci + 1 < 16) {
            g_load(sb + (uint32_t)((ci+1) & 1) * GB_STRIDE, Ah, Wh, Wl,
                   m0, n0, (ci+1)*64, tid, twopass);
            CP_COMMIT();
            CP_WAIT1();
        } else {
            CP_WAIT0();
        }
        __syncthreads();
        #pragma unroll
        for (int kk = 0; kk < 4; kk++) {
            uint32_t af[4][4], bh2[2][4];
            #pragma unroll
            for (int mt = 0; mt < 4; mt++) {
                uint32_t off = SWZ(a_row[mt]*128 + (kk*2 + a_half)*16);
                ldmx4(cbuf + off, af[mt]);
            }
            #pragma unroll
            for (int g = 0; g < 2; g++) {
                uint32_t off = SWZ(b_row[g]*128 + (kk*2 + b_half)*16);
                ldmx4(cbuf + 16384 + off, bh2[g]);
            }
            // hi pass: 16 independent accumulators, no RAW chain
            #pragma unroll
            for (int mt = 0; mt < 4; mt++)
                #pragma unroll
                for (int j = 0; j < 4; j++) {
                    int g = j >> 1, pr = (j & 1) * 2;
                    mma_fp(acc[mt][j], af[mt], bh2[g][pr], bh2[g][pr+1]);
                }
            if (twopass) {
                uint32_t bl2[2][4];
                #pragma unroll
                for (int g = 0; g < 2; g++) {
                    uint32_t off = SWZ(b_row[g]*128 + (kk*2 + b_half)*16);
                    ldmx4(cbuf + 32768 + off, bl2[g]);
                }
                #pragma unroll
                for (int mt = 0; mt < 4; mt++)
                    #pragma unroll
                    for (int j = 0; j < 4; j++) {
                        int g = j >> 1, pr = (j & 1) * 2;
                        mma_fp(acc[mt][j], af[mt], bl2[g][pr], bl2[g][pr+1]);
                    }
            }
        }
        __syncthreads();
    }

    // Epilogue
    #pragma unroll
    for (int mt = 0; mt < 4; mt++) {
        int r0 = m0 + wm*64 + mt*16 + (lane >> 2);
        #pragma unroll
        for (int j = 0; j < 4; j++) {
            int cb = n0 + wn*32 + j*8 + 2*(lane & 3);
            float b0 = __ldg(&bias[cb]), b1 = __ldg(&bias[cb+1]);
            #pragma unroll
            for (int half = 0; half < 2; half++) {
                int m = r0 + half*8;
                float x0 = (acc[mt][j][half*2+0] + b0) * scale;
                float x1 = (acc[mt][j][half*2+1] + b1) * scale;
                if (mode == 0) {
                    float2 o; o.x = x0; o.y = x1;
                    *(float2*)(Cf + (size_t)m*DM + cb) = o;
                } else {
                    int b = m >> 11, s = m & 2047, h = cb >> 6, d = cb & 63;
                    size_t idx = (((size_t)(b*NH + h))*SEQ + s)*DK + d;
                    *(__half2*)(Ch + idx) = __floats2half2_rn(x0, x1);
                }
            }
        }
    }
}

// Q/K/V projections in one launch (z selects). Q,K single-pass; V two-pass.
__global__ void __launch_bounds__(256, 2)
proj3(const __half* __restrict__ A3,
      const __half* __restrict__ Wh4, const __half* __restrict__ Wl4,
      const float* __restrict__ bq, const float* __restrict__ bk,
      const float* __restrict__ bv,
      __half* __restrict__ qh, __half* __restrict__ kh, __half* __restrict__ vh)
{
    extern __shared__ char smem[];
    int z = blockIdx.z;
    const __half* Ah = A3 + (size_t)z*NA;
    const __half* Wh = Wh4 + (size_t)z*NW;
    const __half* Wl = Wl4 + (size_t)z*NW;
    const float* bias = (z == 0) ? bq : (z == 1) ? bk : bv;
    __half* Ch = (z == 0) ? qh : (z == 1) ? kh : vh;
    float scale = (z == 0) ? 0.125f : 1.0f;
    int twopass = (z == 2);
    gemm_core(Ah, Wh, Wl, bias, nullptr, Ch, scale, 2, twopass, smem);
}

// Output projection (two-pass: error hits output directly)
__global__ void __launch_bounds__(256, 2)
gemm_o(const __half* __restrict__ Ah,
       const __half* __restrict__ Wh, const __half* __restrict__ Wl,
       const float* __restrict__ bias, float* __restrict__ Cf)
{
    extern __shared__ char smem[];
    gemm_core(Ah, Wh, Wl, bias, Cf, nullptr, 1.0f, 0, 1, smem);
}

// ---------------------------------------------------------------------------
// Flash attention over COMPACTED keys, 128-key tiles, cp.async double buffer.
// QK: single fp16. PV: P fp16, V fp16 (single pass), exp fused into PV loop.
// CTA: 64 q-rows, 128 threads. Output fp16 x [b][s][h*64+d].
// ---------------------------------------------------------------------------
#define AT_K 0
#define AT_V 16384
#define AT_STRIDE 32768
#define AT_SMEM 65536

__device__ __forceinline__ void attn_load_tile(
    uint32_t sbuf, const __half* kh, const __half* vh,
    const int* permb, int kt, int tid)
{
    #pragma unroll
    for (int it = 0; it < 8; it++) {
        int q = tid + it*128; int r = q >> 3, c = q & 7;
        int s = __ldg(&permb[kt + r]);
        size_t ro = (size_t)s * DK + c*8;
        uint32_t so = SWZ(r*128 + c*16);
        CP_ASYNC16(sbuf + AT_K + so, (const void*)(kh + ro));
        CP_ASYNC16(sbuf + AT_V + so, (const void*)(vh + ro));
    }
}

__global__ void __launch_bounds__(128, 2)
attn_tc(const __half* __restrict__ qhp, const __half* __restrict__ khp,
        const __half* __restrict__ vhp,
        const int* __restrict__ perm, const int* __restrict__ ncnt,
        __half* __restrict__ xout)
{
    extern __shared__ char dsm[];
    uint32_t sb = smem_to_u32(dsm);

    const int tid = threadIdx.x, lane = tid & 31, w = tid >> 5;
    const int bh = blockIdx.y, b = bh >> 4, h = bh & 15;
    const int q0 = blockIdx.x * 64;

    const int a_row  = w*16 + (lane & 15);
    const int a_half = lane >> 4;
    const int b_rowb = ((lane >> 4) << 3) + (lane & 7);
    const int b_half = (lane >> 3) & 1;
    const int v_krow = ((lane >> 3) & 1)*8 + (lane & 7);
    const int v_dhalf = lane >> 4;

    // ---- Stage Q through buf0 K region, pull fragments into registers ----
    uint32_t qfh[4][4];
    {
        const uint4* ph = (const uint4*)(qhp + ((size_t)bh*SEQ + q0)*DK);
        #pragma unroll
        for (int it = 0; it < 4; it++) {
            int q = tid + it*128; int r = q >> 3, c = q & 7;
            uint32_t so = SWZ(r*128 + c*16);
            uint4 v = ph[r*8 + c];
            STS128(sb + AT_K + so, v.x, v.y, v.z, v.w);
        }
        __syncthreads();
        #pragma unroll
        for (int kk = 0; kk < 4; kk++) {
            uint32_t off = SWZ(a_row*128 + (kk*2 + a_half)*16);
            ldmx4(sb + AT_K + off, qfh[kk]);
        }
        __syncthreads();   // buf0 free for tile 0
    }

    float acc[8][4] = {};
    float mrow[2] = {-1e30f, -1e30f}, lrow[2] = {0.f, 0.f};

    const __half* kh = khp + (size_t)bh*SEQ*DK;
    const __half* vh = vhp + (size_t)bh*SEQ*DK;
    const int* permb = perm + b*SEQ;

    const int n = __ldg(&ncnt[b]);
    const int nt = (n + 127) >> 7;

    attn_load_tile(sb, kh, vh, permb, 0, tid);
    CP_COMMIT();

    for (int t = 0; t < nt; t++) {
        uint32_t cb = sb + (uint32_t)(t & 1) * AT_STRIDE;
        if (t + 1 < nt) {
            attn_load_tile(sb + (uint32_t)((t+1) & 1) * AT_STRIDE,
                           kh, vh, permb, (t+1)*128, tid);
            CP_COMMIT();
            CP_WAIT1();
        } else {
            CP_WAIT0();
        }
        __syncthreads();

        // ---- S = Q K^T over 128 keys (single fp16 pass) ----
        float s[16][4] = {};
        #pragma unroll
        for (int kk = 0; kk < 4; kk++) {
            #pragma unroll
            for (int g = 0; g < 8; g++) {
                uint32_t kf[4];
                uint32_t boff = SWZ((g*16 + b_rowb)*128 + (kk*2 + b_half)*16);
                ldmx4(cb + AT_K + boff, kf);
                #pragma unroll
                for (int pr = 0; pr < 2; pr++)
                    mma_fp(s[g*2 + pr], qfh[kk], kf[pr*2], kf[pr*2+1]);
            }
        }

        // ---- tail mask (only last tile can be partial) ----
        int rem = n - t*128;
        if (rem < 128) {
            int c0 = 2*(lane & 3);
            #pragma unroll
            for (int j = 0; j < 16; j++) {
                if (j*8 + c0     >= rem) { s[j][0] = -1e9f; s[j][2] = -1e9f; }
                if (j*8 + c0 + 1 >= rem) { s[j][1] = -1e9f; s[j][3] = -1e9f; }
            }
        }

        // ---- online softmax: max reduce, rescale acc ----
        float tlo = -1e30f, thi = -1e30f;
        #pragma unroll
        for (int j = 0; j < 16; j++) {
            tlo = fmaxf(tlo, fmaxf(s[j][0], s[j][1]));
            thi = fmaxf(thi, fmaxf(s[j][2], s[j][3]));
        }
        tlo = fmaxf(tlo, __shfl_xor_sync(0xffffffffu, tlo, 1));
        tlo = fmaxf(tlo, __shfl_xor_sync(0xffffffffu, tlo, 2));
        thi = fmaxf(thi, __shfl_xor_sync(0xffffffffu, thi, 1));
        thi = fmaxf(thi, __shfl_xor_sync(0xffffffffu, thi, 2));
        float mnlo = fmaxf(mrow[0], tlo), mnhi = fmaxf(mrow[1], thi);
        float alo = __expf(mrow[0] - mnlo), ahi = __expf(mrow[1] - mnhi);
        mrow[0] = mnlo; mrow[1] = mnhi;
        #pragma unroll
        for (int j = 0; j < 8; j++) {
            acc[j][0] *= alo; acc[j][1] *= alo;
            acc[j][2] *= ahi; acc[j][3] *= ahi;
        }

        // ---- fused exp + PV over 8 x 16-key chunks ----
        float slo = 0.f, shi = 0.f;
        #pragma unroll
        for (int ks = 0; ks < 8; ks++) {
            uint32_t pa[4];
            #pragma unroll
            for (int jj = 0; jj < 2; jj++) {
                int j = 2*ks + jj;
                float p0 = __expf(s[j][0] - mnlo), p1 = __expf(s[j][1] - mnlo);
                float p2 = __expf(s[j][2] - mnhi), p3 = __expf(s[j][3] - mnhi);
                slo += p0 + p1; shi += p2 + p3;
                __half2 h0 = __floats2half2_rn(p0, p1);
                __half2 h1 = __floats2half2_rn(p2, p3);
                pa[jj*2]   = *(uint32_t*)&h0;
                pa[jj*2+1] = *(uint32_t*)&h1;
            }
            #pragma unroll
            for (int g = 0; g < 4; g++) {
                uint32_t vb[4];
                uint32_t voff = SWZ((ks*16 + v_krow)*128 + (g*2 + v_dhalf)*16);
                ldmx4t(cb + AT_V + voff, vb);
                #pragma unroll
                for (int pr = 0; pr < 2; pr++)
                    mma_fp(acc[g*2+pr], pa, vb[pr*2], vb[pr*2+1]);
            }
        }
        slo += __shfl_xor_sync(0xffffffffu, slo, 1);
        slo += __shfl_xor_sync(0xffffffffu, slo, 2);
        shi += __shfl_xor_sync(0xffffffffu, shi, 1);
        shi += __shfl_xor_sync(0xffffffffu, shi, 2);
        lrow[0] = lrow[0]*alo + slo; lrow[1] = lrow[1]*ahi + shi;

        __syncthreads();   // all warps done with buffer cb before reload
    }

    // ---- epilogue: x = acc / l, fp16, layout [b][s][h*64+d] ----
    float il0 = 1.0f / lrow[0], il1 = 1.0f / lrow[1];
    int r0g = q0 + w*16 + (lane >> 2);
    #pragma unroll
    for (int j = 0; j < 8; j++) {
        int d = j*8 + 2*(lane & 3);
        #pragma unroll
        for (int half = 0; half < 2; half++) {
            int srow = r0g + half*8;
            float il = half ? il1 : il0;
            __half2 o = __floats2half2_rn(acc[j][half*2+0] * il,
                                          acc[j][half*2+1] * il);
            *(__half2*)(xout + ((size_t)b*SEQ + srow)*DM + h*DK + d) = o;
        }
    }
}

// ---------------------------------------------------------------------------
extern "C" void kernel_launch(void* const* d_in, const int* in_sizes, int n_in,
                              void* d_out, int out_size)
{
    const float* query = (const float*)d_in[0];
    const float* key   = (const float*)d_in[1];
    const float* value = (const float*)d_in[2];
    const int*   mask  = (const int*)  d_in[3];
    const float* Wq    = (const float*)d_in[4];
    const float* bq    = (const float*)d_in[5];
    const float* Wk    = (const float*)d_in[6];
    const float* bk    = (const float*)d_in[7];
    const float* Wv    = (const float*)d_in[8];
    const float* bv    = (const float*)d_in[9];
    const float* Wo    = (const float*)d_in[10];
    const float* bo    = (const float*)d_in[11];
    float* out = (float*)d_out;

    __half *ah3, *wh4, *wl4, *qh, *kh, *vh, *xh;
    int *perm, *ncnt;
    cudaGetSymbolAddress((void**)&ah3, g_ah3);
    cudaGetSymbolAddress((void**)&wh4, g_wh4);
    cudaGetSymbolAddress((void**)&wl4, g_wl4);
    cudaGetSymbolAddress((void**)&qh, g_qh);
    cudaGetSymbolAddress((void**)&kh, g_kh);
    cudaGetSymbolAddress((void**)&vh, g_vh);
    cudaGetSymbolAddress((void**)&xh, g_xh);
    cudaGetSymbolAddress((void**)&perm, g_perm);
    cudaGetSymbolAddress((void**)&ncnt, g_ncnt);

    cudaFuncSetAttribute(proj3,  cudaFuncAttributeMaxDynamicSharedMemorySize, G2_SMEM);
    cudaFuncSetAttribute(gemm_o, cudaFuncAttributeMaxDynamicSharedMemorySize, G2_SMEM);
    cudaFuncSetAttribute(attn_tc, cudaFuncAttributeMaxDynamicSharedMemorySize, AT_SMEM);

    const int nW4 = NW/4;
    dim3 cgrid(nW4/256, 16);             // 12 input slices + 4 weights
    dim3 pgrid(DM/128, M_ROWS/128, 3);   // (8, 32, 3)
    dim3 ogrid(DM/128, M_ROWS/128);      // (8, 32)
    dim3 agrid(SEQ/64, BATCH*NH);        // (32, 32)

    mask_scan<<<BATCH, 1024>>>(mask, perm, ncnt);
    cvt_all<<<cgrid, 256>>>((const float4*)query, (const float4*)key,
                            (const float4*)value,
                            (const float4*)Wq, (const float4*)Wk,
                            (const float4*)Wv, (const float4*)Wo,
                            (__half2*)ah3, (__half2*)wh4, (__half2*)wl4);

    proj3<<<pgrid, 256, G2_SMEM>>>(ah3, wh4, wl4, bq, bk, bv, qh, kh, vh);

    attn_tc<<<agrid, 128, AT_SMEM>>>(qh, kh, vh, perm, ncnt, xh);

    gemm_o<<<ogrid, 256, G2_SMEM>>>(xh, wh4 + 3*(size_t)NW, wl4 + 3*(size_t)NW, bo, out);
}

// round 9
// speedup vs baseline: 10.5213x; 1.1675x over previous
#include <cuda_runtime.h>
#include <cuda_bf16.h>
#include <cuda_fp16.h>
#include <cstdint>

// Problem constants
#define BATCH 2
#define SEQ   2048
#define DM    1024
#define NH    16
#define DK    64
#define M_ROWS (BATCH*SEQ)   // 4096
#define NA (M_ROWS*DM)
#define NW (DM*DM)
#define LOG2E 1.4426950408889634f

// ---------------------------------------------------------------------------
// Helpers (base-sm_103 features: ldmatrix + mma.sync + cp.async)
// ---------------------------------------------------------------------------
__device__ __forceinline__ uint32_t smem_to_u32(const void* p) {
    uint32_t a;
    asm("{ .reg .u64 t; cvta.to.shared.u64 t, %1; cvt.u32.u64 %0, t; }" : "=r"(a) : "l"(p));
    return a;
}
#define SWZ(o) ((uint32_t)(o) ^ ((((uint32_t)(o)) >> 3) & 0x70))

#define STS128(a, r0, r1, r2, r3) \
    asm volatile("st.shared.v4.b32 [%0], {%1, %2, %3, %4};" \
                 :: "r"(a), "r"(r0), "r"(r1), "r"(r2), "r"(r3) : "memory")
#define CP_ASYNC16(dst, src) \
    asm volatile("cp.async.cg.shared.global [%0], [%1], 16;" :: "r"(dst), "l"(src) : "memory")
#define CP_COMMIT() asm volatile("cp.async.commit_group;" ::: "memory")
#define CP_WAIT1()  asm volatile("cp.async.wait_group 1;" ::: "memory")
#define CP_WAIT0()  asm volatile("cp.async.wait_group 0;" ::: "memory")

__device__ __forceinline__ void ldmx4(uint32_t addr, uint32_t r[4]) {
    asm volatile("ldmatrix.sync.aligned.m8n8.x4.shared.b16 {%0,%1,%2,%3}, [%4];"
                 : "=r"(r[0]), "=r"(r[1]), "=r"(r[2]), "=r"(r[3]) : "r"(addr));
}
__device__ __forceinline__ void ldmx4t(uint32_t addr, uint32_t r[4]) {
    asm volatile("ldmatrix.sync.aligned.m8n8.x4.trans.shared.b16 {%0,%1,%2,%3}, [%4];"
                 : "=r"(r[0]), "=r"(r[1]), "=r"(r[2]), "=r"(r[3]) : "r"(addr));
}
__device__ __forceinline__ void mma_fp(float d[4], const uint32_t a[4],
                                       uint32_t b0, uint32_t b1) {
    asm volatile("mma.sync.aligned.m16n8k16.row.col.f32.f16.f16.f32 "
                 "{%0,%1,%2,%3}, {%4,%5,%6,%7}, {%8,%9}, {%0,%1,%2,%3};"
                 : "+f"(d[0]), "+f"(d[1]), "+f"(d[2]), "+f"(d[3])
                 : "r"(a[0]), "r"(a[1]), "r"(a[2]), "r"(a[3]), "r"(b0), "r"(b1));
}

// ---------------------------------------------------------------------------
// Scratch (device globals: allocation-free rule)
// ---------------------------------------------------------------------------
__device__ __half g_ah3[3*NA];                // converted q/k/v inputs (fp16 hi)
__device__ __half g_wh4[4*NW];                // Wq,Wk,Wv,Wo fp16 hi
__device__ __half g_wl4[4*NW];                // fp16 lo (only Wv slot used)
__device__ __half g_qh[BATCH*NH*SEQ*DK];
__device__ __half g_kh[BATCH*NH*SEQ*DK];
__device__ __half g_vh[BATCH*NH*SEQ*DK];
__device__ __half g_xh[NA];
__device__ int    g_perm[BATCH*SEQ];
__device__ int    g_ncnt[BATCH];

// ---------------------------------------------------------------------------
// Unified convert: y in [0,12): input slice y/4 quarter y%4 (hi only).
// y in [12,16): weight y-12 (hi; lo only for Wv).
// ---------------------------------------------------------------------------
__global__ void __launch_bounds__(256)
cvt_all(const float4* __restrict__ q, const float4* __restrict__ k,
        const float4* __restrict__ v,
        const float4* __restrict__ wq, const float4* __restrict__ wk,
        const float4* __restrict__ wv, const float4* __restrict__ wo,
        __half2* __restrict__ in_h, __half2* __restrict__ w_h,
        __half2* __restrict__ w_l)
{
    const int y = blockIdx.y;
    const int i = blockIdx.x * blockDim.x + threadIdx.x;   // < NW/4
    if (y < 12) {
        int z = y >> 2, quad = y & 3;
        const float4* src = ((z == 0) ? q : (z == 1) ? k : v) + (size_t)quad*(NW/4);
        __half2* h = in_h + (size_t)z*(NA/2) + (size_t)quad*(NW/2);
        float4 w = src[i];
        h[2*i]   = __floats2half2_rn(w.x, w.y);
        h[2*i+1] = __floats2half2_rn(w.z, w.w);
    } else {
        int z = y - 12;
        const float4* src = (z == 0) ? wq : (z == 1) ? wk : (z == 2) ? wv : wo;
        float4 w = src[i];
        __half2 h0 = __floats2half2_rn(w.x, w.y);
        __half2 h1 = __floats2half2_rn(w.z, w.w);
        __half2* h = w_h + (size_t)z*(NW/2);
        h[2*i] = h0; h[2*i+1] = h1;
        if (z == 2) {  // only Wv needs lo
            __half2* l = w_l + (size_t)z*(NW/2);
            l[2*i]   = __floats2half2_rn(w.x - __half2float(h0.x), w.y - __half2float(h0.y));
            l[2*i+1] = __floats2half2_rn(w.z - __half2float(h1.x), w.w - __half2float(h1.y));
        }
    }
}

// ---------------------------------------------------------------------------
// Deterministic mask compaction: 1 CTA per batch, Hillis-Steele scan.
// ---------------------------------------------------------------------------
__global__ void __launch_bounds__(1024)
mask_scan(const int* __restrict__ mask, int* __restrict__ perm, int* __restrict__ ncnt)
{
    __shared__ int sm[1024];
    int b = blockIdx.x, t = threadIdx.x;
    const int* m = mask + b*SEQ;
    int* pb = perm + b*SEQ;
    pb[2*t] = 0; pb[2*t+1] = 0;
    int a0 = (m[2*t] != 0), a1 = (m[2*t+1] != 0);
    int sum = a0 + a1;
    sm[t] = sum;
    __syncthreads();
    #pragma unroll
    for (int off = 1; off < 1024; off <<= 1) {
        int v = (t >= off) ? sm[t-off] : 0;
        __syncthreads();
        sm[t] += v;
        __syncthreads();
    }
    int excl = sm[t] - sum;
    if (a0) pb[excl] = 2*t;
    if (a1) pb[excl + a0] = 2*t + 1;
    if (t == 1023) ncnt[b] = sm[1023];
}

// ---------------------------------------------------------------------------
// fp16 NT GEMM core, cp.async double-buffered, chain-free MMAs.
// twopass: add A*Wl^T second sweep. BM=BN=128, BK=64, 256 threads.
// mode 0: fp32 flat. mode 2: fp16 head layout.
// ---------------------------------------------------------------------------
#define GB_STRIDE 49152
#define G2_SMEM   98304

__device__ __forceinline__ void g_load(uint32_t sbuf, const __half* Ah,
                                       const __half* Wh, const __half* Wl,
                                       int m0, int n0, int kc, int tid, int twopass)
{
    #pragma unroll
    for (int it = 0; it < 4; it++) {
        int q = tid + it*256; int r = q >> 3, c = q & 7;
        uint32_t so = SWZ(r*128 + c*16);
        CP_ASYNC16(sbuf + so,         (const void*)(Ah + (size_t)(m0+r)*DM + kc + c*8));
        CP_ASYNC16(sbuf + 16384 + so, (const void*)(Wh + (size_t)(n0+r)*DM + kc + c*8));
        if (twopass)
            CP_ASYNC16(sbuf + 32768 + so, (const void*)(Wl + (size_t)(n0+r)*DM + kc + c*8));
    }
}

__device__ __forceinline__ void gemm_core(
    const __half* __restrict__ Ah, const __half* __restrict__ Wh,
    const __half* __restrict__ Wl, const float* __restrict__ bias,
    float* __restrict__ Cf, __half* __restrict__ Ch,
    float scale, int mode, int twopass, char* smem)
{
    uint32_t sb = smem_to_u32(smem);
    const int tid = threadIdx.x, lane = tid & 31, wid = tid >> 5;
    const int wm = wid & 1, wn = wid >> 1;
    const int m0 = blockIdx.y * 128, n0 = blockIdx.x * 128;

    float acc[4][4][4] = {};

    int a_row[4], b_row[2];
    #pragma unroll
    for (int mt = 0; mt < 4; mt++) a_row[mt] = wm*64 + mt*16 + (lane & 15);
    #pragma unroll
    for (int g = 0; g < 2; g++)
        b_row[g] = wn*32 + g*16 + ((lane >> 4) << 3) + (lane & 7);
    const int a_half = lane >> 4;
    const int b_half = (lane >> 3) & 1;

    g_load(sb, Ah, Wh, Wl, m0, n0, 0, tid, twopass);
    CP_COMMIT();

    for (int ci = 0; ci < 16; ci++) {
        uint32_t cbuf = sb + (uint32_t)(ci & 1) * GB_STRIDE;
        if (ci + 1 < 16) {
            g_load(sb + (uint32_t)((ci+1) & 1) * GB_STRIDE, Ah, Wh, Wl,
                   m0, n0, (ci+1)*64, tid, twopass);
            CP_COMMIT();
            CP_WAIT1();
        } else {
            CP_WAIT0();
        }
        __syncthreads();
        #pragma unroll
        for (int kk = 0; kk < 4; kk++) {
            uint32_t af[4][4], bh2[2][4];
            #pragma unroll
            for (int mt = 0; mt < 4; mt++) {
                uint32_t off = SWZ(a_row[mt]*128 + (kk*2 + a_half)*16);
                ldmx4(cbuf + off, af[mt]);
            }
            #pragma unroll
            for (int g = 0; g < 2; g++) {
                uint32_t off = SWZ(b_row[g]*128 + (kk*2 + b_half)*16);
                ldmx4(cbuf + 16384 + off, bh2[g]);
            }
            #pragma unroll
            for (int mt = 0; mt < 4; mt++)
                #pragma unroll
                for (int j = 0; j < 4; j++) {
                    int g = j >> 1, pr = (j & 1) * 2;
                    mma_fp(acc[mt][j], af[mt], bh2[g][pr], bh2[g][pr+1]);
                }
            if (twopass) {
                uint32_t bl2[2][4];
                #pragma unroll
                for (int g = 0; g < 2; g++) {
                    uint32_t off = SWZ(b_row[g]*128 + (kk*2 + b_half)*16);
                    ldmx4(cbuf + 32768 + off, bl2[g]);
                }
                #pragma unroll
                for (int mt = 0; mt < 4; mt++)
                    #pragma unroll
                    for (int j = 0; j < 4; j++) {
                        int g = j >> 1, pr = (j & 1) * 2;
                        mma_fp(acc[mt][j], af[mt], bl2[g][pr], bl2[g][pr+1]);
                    }
            }
        }
        __syncthreads();
    }

    // Epilogue
    #pragma unroll
    for (int mt = 0; mt < 4; mt++) {
        int r0 = m0 + wm*64 + mt*16 + (lane >> 2);
        #pragma unroll
        for (int j = 0; j < 4; j++) {
            int cb = n0 + wn*32 + j*8 + 2*(lane & 3);
            float b0 = __ldg(&bias[cb]), b1 = __ldg(&bias[cb+1]);
            #pragma unroll
            for (int half = 0; half < 2; half++) {
                int m = r0 + half*8;
                float x0 = (acc[mt][j][half*2+0] + b0) * scale;
                float x1 = (acc[mt][j][half*2+1] + b1) * scale;
                if (mode == 0) {
                    float2 o; o.x = x0; o.y = x1;
                    *(float2*)(Cf + (size_t)m*DM + cb) = o;
                } else {
                    int b = m >> 11, s = m & 2047, h = cb >> 6, d = cb & 63;
                    size_t idx = (((size_t)(b*NH + h))*SEQ + s)*DK + d;
                    *(__half2*)(Ch + idx) = __floats2half2_rn(x0, x1);
                }
            }
        }
    }
}

// Q/K/V projections in one launch. Q,K single-pass; V two-pass.
// Q scale folds 1/sqrt(dk) AND log2(e) (softmax runs in exp2 domain).
__global__ void __launch_bounds__(256, 2)
proj3(const __half* __restrict__ A3,
      const __half* __restrict__ Wh4, const __half* __restrict__ Wl4,
      const float* __restrict__ bq, const float* __restrict__ bk,
      const float* __restrict__ bv,
      __half* __restrict__ qh, __half* __restrict__ kh, __half* __restrict__ vh)
{
    extern __shared__ char smem[];
    int z = blockIdx.z;
    const __half* Ah = A3 + (size_t)z*NA;
    const __half* Wh = Wh4 + (size_t)z*NW;
    const __half* Wl = Wl4 + (size_t)z*NW;
    const float* bias = (z == 0) ? bq : (z == 1) ? bk : bv;
    __half* Ch = (z == 0) ? qh : (z == 1) ? kh : vh;
    float scale = (z == 0) ? 0.125f * LOG2E : 1.0f;
    int twopass = (z == 2);
    gemm_core(Ah, Wh, Wl, bias, nullptr, Ch, scale, 2, twopass, smem);
}

// Output projection (single-pass)
__global__ void __launch_bounds__(256, 2)
gemm_o(const __half* __restrict__ Ah, const __half* __restrict__ Wh,
       const float* __restrict__ bias, float* __restrict__ Cf)
{
    extern __shared__ char smem[];
    gemm_core(Ah, Wh, nullptr, bias, Cf, nullptr, 1.0f, 0, 0, smem);
}

// ---------------------------------------------------------------------------
// Flash attention over COMPACTED keys. 128-key smem tiles (cp.async double
// buffer), processed as 2 x 64-key subtiles to keep s[] small (regs < 170).
// QK single fp16, PV single fp16, softmax in exp2 domain.
// CTA: 64 q-rows, 128 threads, 3 CTAs/SM target.
// ---------------------------------------------------------------------------
#define AT_K 0
#define AT_V 16384
#define AT_STRIDE 32768
#define AT_SMEM 65536

__device__ __forceinline__ void attn_load_tile(
    uint32_t sbuf, const __half* kh, const __half* vh,
    const int* permb, int kt, int tid)
{
    #pragma unroll
    for (int it = 0; it < 8; it++) {
        int q = tid + it*128; int r = q >> 3, c = q & 7;
        int s = __ldg(&permb[kt + r]);
        size_t ro = (size_t)s * DK + c*8;
        uint32_t so = SWZ(r*128 + c*16);
        CP_ASYNC16(sbuf + AT_K + so, (const void*)(kh + ro));
        CP_ASYNC16(sbuf + AT_V + so, (const void*)(vh + ro));
    }
}

__global__ void __launch_bounds__(128, 3)
attn_tc(const __half* __restrict__ qhp, const __half* __restrict__ khp,
        const __half* __restrict__ vhp,
        const int* __restrict__ perm, const int* __restrict__ ncnt,
        __half* __restrict__ xout)
{
    extern __shared__ char dsm[];
    uint32_t sb = smem_to_u32(dsm);

    const int tid = threadIdx.x, lane = tid & 31, w = tid >> 5;
    const int bh = blockIdx.y, b = bh >> 4, h = bh & 15;
    const int q0 = blockIdx.x * 64;

    const int a_row  = w*16 + (lane & 15);
    const int a_half = lane >> 4;
    const int b_rowb = ((lane >> 4) << 3) + (lane & 7);
    const int b_half = (lane >> 3) & 1;
    const int v_krow = ((lane >> 3) & 1)*8 + (lane & 7);
    const int v_dhalf = lane >> 4;

    // ---- Stage Q through buf0 K region, pull fragments into registers ----
    uint32_t qfh[4][4];
    {
        const uint4* ph = (const uint4*)(qhp + ((size_t)bh*SEQ + q0)*DK);
        #pragma unroll
        for (int it = 0; it < 4; it++) {
            int q = tid + it*128; int r = q >> 3, c = q & 7;
            uint32_t so = SWZ(r*128 + c*16);
            uint4 v = ph[r*8 + c];
            STS128(sb + AT_K + so, v.x, v.y, v.z, v.w);
        }
        __syncthreads();
        #pragma unroll
        for (int kk = 0; kk < 4; kk++) {
            uint32_t off = SWZ(a_row*128 + (kk*2 + a_half)*16);
            ldmx4(sb + AT_K + off, qfh[kk]);
        }
        __syncthreads();   // buf0 free for tile 0
    }

    float acc[8][4] = {};
    float mrow[2] = {-1e30f, -1e30f}, lrow[2] = {0.f, 0.f};

    const __half* kh = khp + (size_t)bh*SEQ*DK;
    const __half* vh = vhp + (size_t)bh*SEQ*DK;
    const int* permb = perm + b*SEQ;

    const int n = __ldg(&ncnt[b]);
    const int nt = (n + 127) >> 7;

    attn_load_tile(sb, kh, vh, permb, 0, tid);
    CP_COMMIT();

    for (int t = 0; t < nt; t++) {
        uint32_t cb = sb + (uint32_t)(t & 1) * AT_STRIDE;
        if (t + 1 < nt) {
            attn_load_tile(sb + (uint32_t)((t+1) & 1) * AT_STRIDE,
                           kh, vh, permb, (t+1)*128, tid);
            CP_COMMIT();
            CP_WAIT1();
        } else {
            CP_WAIT0();
        }
        __syncthreads();

        // ---- two 64-key subtiles ----
        #pragma unroll
        for (int half64 = 0; half64 < 2; half64++) {
            int kbase = half64 * 64;
            int rem = n - t*128 - kbase;
            if (rem <= 0) break;   // uniform across CTA (n is uniform)

            // S = Q K^T over 64 keys (single fp16 pass)
            float s[8][4] = {};
            #pragma unroll
            for (int kk = 0; kk < 4; kk++) {
                #pragma unroll
                for (int g = 0; g < 4; g++) {
                    uint32_t kf[4];
                    uint32_t boff = SWZ((kbase + g*16 + b_rowb)*128 + (kk*2 + b_half)*16);
                    ldmx4(cb + AT_K + boff, kf);
                    #pragma unroll
                    for (int pr = 0; pr < 2; pr++)
                        mma_fp(s[g*2 + pr], qfh[kk], kf[pr*2], kf[pr*2+1]);
                }
            }

            // tail mask
            if (rem < 64) {
                int c0 = 2*(lane & 3);
                #pragma unroll
                for (int j = 0; j < 8; j++) {
                    if (j*8 + c0     >= rem) { s[j][0] = -1e9f; s[j][2] = -1e9f; }
                    if (j*8 + c0 + 1 >= rem) { s[j][1] = -1e9f; s[j][3] = -1e9f; }
                }
            }

            // online softmax (exp2 domain; scores already scaled by log2e)
            float tlo = -1e30f, thi = -1e30f;
            #pragma unroll
            for (int j = 0; j < 8; j++) {
                tlo = fmaxf(tlo, fmaxf(s[j][0], s[j][1]));
                thi = fmaxf(thi, fmaxf(s[j][2], s[j][3]));
            }
            tlo = fmaxf(tlo, __shfl_xor_sync(0xffffffffu, tlo, 1));
            tlo = fmaxf(tlo, __shfl_xor_sync(0xffffffffu, tlo, 2));
            thi = fmaxf(thi, __shfl_xor_sync(0xffffffffu, thi, 1));
            thi = fmaxf(thi, __shfl_xor_sync(0xffffffffu, thi, 2));
            float mnlo = fmaxf(mrow[0], tlo), mnhi = fmaxf(mrow[1], thi);
            float alo = exp2f(mrow[0] - mnlo), ahi = exp2f(mrow[1] - mnhi);
            mrow[0] = mnlo; mrow[1] = mnhi;
            #pragma unroll
            for (int j = 0; j < 8; j++) {
                acc[j][0] *= alo; acc[j][1] *= alo;
                acc[j][2] *= ahi; acc[j][3] *= ahi;
            }

            // fused exp2 + PV over 4 x 16-key chunks
            float slo = 0.f, shi = 0.f;
            #pragma unroll
            for (int ks = 0; ks < 4; ks++) {
                uint32_t pa[4];
                #pragma unroll
                for (int jj = 0; jj < 2; jj++) {
                    int j = 2*ks + jj;
                    float p0 = exp2f(s[j][0] - mnlo), p1 = exp2f(s[j][1] - mnlo);
                    float p2 = exp2f(s[j][2] - mnhi), p3 = exp2f(s[j][3] - mnhi);
                    slo += p0 + p1; shi += p2 + p3;
                    __half2 h0 = __floats2half2_rn(p0, p1);
                    __half2 h1 = __floats2half2_rn(p2, p3);
                    pa[jj*2]   = *(uint32_t*)&h0;
                    pa[jj*2+1] = *(uint32_t*)&h1;
                }
                #pragma unroll
                for (int g = 0; g < 4; g++) {
                    uint32_t vb[4];
                    uint32_t voff = SWZ((kbase + ks*16 + v_krow)*128 + (g*2 + v_dhalf)*16);
                    ldmx4t(cb + AT_V + voff, vb);
                    #pragma unroll
                    for (int pr = 0; pr < 2; pr++)
                        mma_fp(acc[g*2+pr], pa, vb[pr*2], vb[pr*2+1]);
                }
            }
            slo += __shfl_xor_sync(0xffffffffu, slo, 1);
            slo += __shfl_xor_sync(0xffffffffu, slo, 2);
            shi += __shfl_xor_sync(0xffffffffu, shi, 1);
            shi += __shfl_xor_sync(0xffffffffu, shi, 2);
            lrow[0] = lrow[0]*alo + slo; lrow[1] = lrow[1]*ahi + shi;
        }

        __syncthreads();   // all warps done with buffer cb before reload
    }

    // ---- epilogue: x = acc / l, fp16, layout [b][s][h*64+d] ----
    float il0 = 1.0f / lrow[0], il1 = 1.0f / lrow[1];
    int r0g = q0 + w*16 + (lane >> 2);
    #pragma unroll
    for (int j = 0; j < 8; j++) {
        int d = j*8 + 2*(lane & 3);
        #pragma unroll
        for (int half = 0; half < 2; half++) {
            int srow = r0g + half*8;
            float il = half ? il1 : il0;
            __half2 o = __floats2half2_rn(acc[j][half*2+0] * il,
                                          acc[j][half*2+1] * il);
            *(__half2*)(xout + ((size_t)b*SEQ + srow)*DM + h*DK + d) = o;
        }
    }
}

// ---------------------------------------------------------------------------
extern "C" void kernel_launch(void* const* d_in, const int* in_sizes, int n_in,
                              void* d_out, int out_size)
{
    const float* query = (const float*)d_in[0];
    const float* key   = (const float*)d_in[1];
    const float* value = (const float*)d_in[2];
    const int*   mask  = (const int*)  d_in[3];
    const float* Wq    = (const float*)d_in[4];
    const float* bq    = (const float*)d_in[5];
    const float* Wk    = (const float*)d_in[6];
    const float* bk    = (const float*)d_in[7];
    const float* Wv    = (const float*)d_in[8];
    const float* bv    = (const float*)d_in[9];
    const float* Wo    = (const float*)d_in[10];
    const float* bo    = (const float*)d_in[11];
    float* out = (float*)d_out;

    __half *ah3, *wh4, *wl4, *qh, *kh, *vh, *xh;
    int *perm, *ncnt;
    cudaGetSymbolAddress((void**)&ah3, g_ah3);
    cudaGetSymbolAddress((void**)&wh4, g_wh4);
    cudaGetSymbolAddress((void**)&wl4, g_wl4);
    cudaGetSymbolAddress((void**)&qh, g_qh);
    cudaGetSymbolAddress((void**)&kh, g_kh);
    cudaGetSymbolAddress((void**)&vh, g_vh);
    cudaGetSymbolAddress((void**)&xh, g_xh);
    cudaGetSymbolAddress((void**)&perm, g_perm);
    cudaGetSymbolAddress((void**)&ncnt, g_ncnt);

    cudaFuncSetAttribute(proj3,  cudaFuncAttributeMaxDynamicSharedMemorySize, G2_SMEM);
    cudaFuncSetAttribute(gemm_o, cudaFuncAttributeMaxDynamicSharedMemorySize, G2_SMEM);
    cudaFuncSetAttribute(attn_tc, cudaFuncAttributeMaxDynamicSharedMemorySize, AT_SMEM);

    const int nW4 = NW/4;
    dim3 cgrid(nW4/256, 16);             // 12 input slices + 4 weights
    dim3 pgrid(DM/128, M_ROWS/128, 3);   // (8, 32, 3)
    dim3 ogrid(DM/128, M_ROWS/128);      // (8, 32)
    dim3 agrid(SEQ/64, BATCH*NH);        // (32, 32)

    mask_scan<<<BATCH, 1024>>>(mask, perm, ncnt);
    cvt_all<<<cgrid, 256>>>((const float4*)query, (const float4*)key,
                            (const float4*)value,
                            (const float4*)Wq, (const float4*)Wk,
                            (const float4*)Wv, (const float4*)Wo,
                            (__half2*)ah3, (__half2*)wh4, (__half2*)wl4);

    proj3<<<pgrid, 256, G2_SMEM>>>(ah3, wh4, wl4, bq, bk, bv, qh, kh, vh);

    attn_tc<<<agrid, 128, AT_SMEM>>>(qh, kh, vh, perm, ncnt, xh);

    gemm_o<<<ogrid, 256, G2_SMEM>>>(xh, wh4 + 3*(size_t)NW, bo, out);
}

// round 10
// speedup vs baseline: 11.4659x; 1.0898x over previous
#include <cuda_runtime.h>
#include <cuda_bf16.h>
#include <cuda_fp16.h>
#include <cstdint>

// Problem constants
#define BATCH 2
#define SEQ   2048
#define DM    1024
#define NH    16
#define DK    64
#define M_ROWS (BATCH*SEQ)   // 4096
#define NA (M_ROWS*DM)
#define NW (DM*DM)
#define LOG2E 1.4426950408889634f

// ---------------------------------------------------------------------------
// Helpers (base-sm_103 features: ldmatrix + mma.sync + cp.async)
// ---------------------------------------------------------------------------
__device__ __forceinline__ uint32_t smem_to_u32(const void* p) {
    uint32_t a;
    asm("{ .reg .u64 t; cvta.to.shared.u64 t, %1; cvt.u32.u64 %0, t; }" : "=r"(a) : "l"(p));
    return a;
}
#define SWZ(o) ((uint32_t)(o) ^ ((((uint32_t)(o)) >> 3) & 0x70))

#define STS128(a, r0, r1, r2, r3) \
    asm volatile("st.shared.v4.b32 [%0], {%1, %2, %3, %4};" \
                 :: "r"(a), "r"(r0), "r"(r1), "r"(r2), "r"(r3) : "memory")
#define CP_ASYNC16(dst, src) \
    asm volatile("cp.async.cg.shared.global [%0], [%1], 16;" :: "r"(dst), "l"(src) : "memory")
#define CP_COMMIT() asm volatile("cp.async.commit_group;" ::: "memory")
#define CP_WAIT0()  asm volatile("cp.async.wait_group 0;" ::: "memory")

__device__ __forceinline__ void ldmx4(uint32_t addr, uint32_t r[4]) {
    asm volatile("ldmatrix.sync.aligned.m8n8.x4.shared.b16 {%0,%1,%2,%3}, [%4];"
                 : "=r"(r[0]), "=r"(r[1]), "=r"(r[2]), "=r"(r[3]) : "r"(addr));
}
__device__ __forceinline__ void ldmx4t(uint32_t addr, uint32_t r[4]) {
    asm volatile("ldmatrix.sync.aligned.m8n8.x4.trans.shared.b16 {%0,%1,%2,%3}, [%4];"
                 : "=r"(r[0]), "=r"(r[1]), "=r"(r[2]), "=r"(r[3]) : "r"(addr));
}
__device__ __forceinline__ void mma_fp(float d[4], const uint32_t a[4],
                                       uint32_t b0, uint32_t b1) {
    asm volatile("mma.sync.aligned.m16n8k16.row.col.f32.f16.f16.f32 "
                 "{%0,%1,%2,%3}, {%4,%5,%6,%7}, {%8,%9}, {%0,%1,%2,%3};"
                 : "+f"(d[0]), "+f"(d[1]), "+f"(d[2]), "+f"(d[3])
                 : "r"(a[0]), "r"(a[1]), "r"(a[2]), "r"(a[3]), "r"(b0), "r"(b1));
}

// ---------------------------------------------------------------------------
// Scratch (device globals: allocation-free rule)
// ---------------------------------------------------------------------------
__device__ __half g_ah3[3*NA];                // converted q/k/v inputs (fp16)
__device__ __half g_wh4[4*NW];                // Wq,Wk,Wv,Wo fp16
__device__ __half g_qh[BATCH*NH*SEQ*DK];
__device__ __half g_kh[BATCH*NH*SEQ*DK];
__device__ __half g_vh[BATCH*NH*SEQ*DK];
__device__ __half g_xh[NA];
__device__ int    g_perm[BATCH*SEQ];
__device__ int    g_ncnt[BATCH];

// ---------------------------------------------------------------------------
// Unified convert: y in [0,12): input slice y/4 quarter y%4. y in [12,16): weight.
// ---------------------------------------------------------------------------
__global__ void __launch_bounds__(256)
cvt_all(const float4* __restrict__ q, const float4* __restrict__ k,
        const float4* __restrict__ v,
        const float4* __restrict__ wq, const float4* __restrict__ wk,
        const float4* __restrict__ wv, const float4* __restrict__ wo,
        __half2* __restrict__ in_h, __half2* __restrict__ w_h)
{
    const int y = blockIdx.y;
    const int i = blockIdx.x * blockDim.x + threadIdx.x;   // < NW/4
    const float4* src;
    __half2* h;
    if (y < 12) {
        int z = y >> 2, quad = y & 3;
        src = ((z == 0) ? q : (z == 1) ? k : v) + (size_t)quad*(NW/4);
        h = in_h + (size_t)z*(NA/2) + (size_t)quad*(NW/2);
    } else {
        int z = y - 12;
        src = (z == 0) ? wq : (z == 1) ? wk : (z == 2) ? wv : wo;
        h = w_h + (size_t)z*(NW/2);
    }
    float4 w = src[i];
    h[2*i]   = __floats2half2_rn(w.x, w.y);
    h[2*i+1] = __floats2half2_rn(w.z, w.w);
}

// ---------------------------------------------------------------------------
// Deterministic mask compaction: 1 CTA per batch, Hillis-Steele scan.
// ---------------------------------------------------------------------------
__global__ void __launch_bounds__(1024)
mask_scan(const int* __restrict__ mask, int* __restrict__ perm, int* __restrict__ ncnt)
{
    __shared__ int sm[1024];
    int b = blockIdx.x, t = threadIdx.x;
    const int* m = mask + b*SEQ;
    int* pb = perm + b*SEQ;
    pb[2*t] = 0; pb[2*t+1] = 0;
    int a0 = (m[2*t] != 0), a1 = (m[2*t+1] != 0);
    int sum = a0 + a1;
    sm[t] = sum;
    __syncthreads();
    #pragma unroll
    for (int off = 1; off < 1024; off <<= 1) {
        int v = (t >= off) ? sm[t-off] : 0;
        __syncthreads();
        sm[t] += v;
        __syncthreads();
    }
    int excl = sm[t] - sum;
    if (a0) pb[excl] = 2*t;
    if (a1) pb[excl + a0] = 2*t + 1;
    if (t == 1023) ncnt[b] = sm[1023];
}

// ---------------------------------------------------------------------------
// fp16 single-pass NT GEMM core, cp.async double-buffered, ONE barrier/chunk.
// BM=BN=128, BK=64, 256 threads (2m x 4n warps), warp tile 64x32.
// mode 0: fp32 flat. mode 2: fp16 head layout.
// ---------------------------------------------------------------------------
#define GB_STRIDE 32768
#define G2_SMEM   65536

__device__ __forceinline__ void g_load(uint32_t sbuf, const __half* Ah,
                                       const __half* Wh,
                                       int m0, int n0, int kc, int tid)
{
    #pragma unroll
    for (int it = 0; it < 4; it++) {
        int q = tid + it*256; int r = q >> 3, c = q & 7;
        uint32_t so = SWZ(r*128 + c*16);
        CP_ASYNC16(sbuf + so,         (const void*)(Ah + (size_t)(m0+r)*DM + kc + c*8));
        CP_ASYNC16(sbuf + 16384 + so, (const void*)(Wh + (size_t)(n0+r)*DM + kc + c*8));
    }
}

__device__ __forceinline__ void gemm_core(
    const __half* __restrict__ Ah, const __half* __restrict__ Wh,
    const float* __restrict__ bias,
    float* __restrict__ Cf, __half* __restrict__ Ch,
    float scale, int mode, char* smem)
{
    uint32_t sb = smem_to_u32(smem);
    const int tid = threadIdx.x, lane = tid & 31, wid = tid >> 5;
    const int wm = wid & 1, wn = wid >> 1;
    const int m0 = blockIdx.y * 128, n0 = blockIdx.x * 128;

    float acc[4][4][4] = {};

    int a_row[4], b_row[2];
    #pragma unroll
    for (int mt = 0; mt < 4; mt++) a_row[mt] = wm*64 + mt*16 + (lane & 15);
    #pragma unroll
    for (int g = 0; g < 2; g++)
        b_row[g] = wn*32 + g*16 + ((lane >> 4) << 3) + (lane & 7);
    const int a_half = lane >> 4;
    const int b_half = (lane >> 3) & 1;

    g_load(sb, Ah, Wh, m0, n0, 0, tid);
    CP_COMMIT();

    for (int ci = 0; ci < 16; ci++) {
        uint32_t cbuf = sb + (uint32_t)(ci & 1) * GB_STRIDE;
        CP_WAIT0();          // this thread's loads for chunk ci complete
        __syncthreads();     // (a) chunk ci visible from all threads
                             // (b) all warps done with MMA(ci-1) -> other buffer free
        if (ci + 1 < 16) {
            g_load(sb + (uint32_t)((ci+1) & 1) * GB_STRIDE, Ah, Wh,
                   m0, n0, (ci+1)*64, tid);
            CP_COMMIT();
        }
        #pragma unroll
        for (int kk = 0; kk < 4; kk++) {
            uint32_t af[4][4], bh2[2][4];
            #pragma unroll
            for (int mt = 0; mt < 4; mt++) {
                uint32_t off = SWZ(a_row[mt]*128 + (kk*2 + a_half)*16);
                ldmx4(cbuf + off, af[mt]);
            }
            #pragma unroll
            for (int g = 0; g < 2; g++) {
                uint32_t off = SWZ(b_row[g]*128 + (kk*2 + b_half)*16);
                ldmx4(cbuf + 16384 + off, bh2[g]);
            }
            #pragma unroll
            for (int mt = 0; mt < 4; mt++)
                #pragma unroll
                for (int j = 0; j < 4; j++) {
                    int g = j >> 1, pr = (j & 1) * 2;
                    mma_fp(acc[mt][j], af[mt], bh2[g][pr], bh2[g][pr+1]);
                }
        }
    }

    // Epilogue
    #pragma unroll
    for (int mt = 0; mt < 4; mt++) {
        int r0 = m0 + wm*64 + mt*16 + (lane >> 2);
        #pragma unroll
        for (int j = 0; j < 4; j++) {
            int cb = n0 + wn*32 + j*8 + 2*(lane & 3);
            float b0 = __ldg(&bias[cb]), b1 = __ldg(&bias[cb+1]);
            #pragma unroll
            for (int half = 0; half < 2; half++) {
                int m = r0 + half*8;
                float x0 = (acc[mt][j][half*2+0] + b0) * scale;
                float x1 = (acc[mt][j][half*2+1] + b1) * scale;
                if (mode == 0) {
                    float2 o; o.x = x0; o.y = x1;
                    *(float2*)(Cf + (size_t)m*DM + cb) = o;
                } else {
                    int b = m >> 11, s = m & 2047, h = cb >> 6, d = cb & 63;
                    size_t idx = (((size_t)(b*NH + h))*SEQ + s)*DK + d;
                    *(__half2*)(Ch + idx) = __floats2half2_rn(x0, x1);
                }
            }
        }
    }
}

// Q/K/V projections in one launch (z selects). All single-pass.
// Q scale folds 1/sqrt(dk) AND log2(e) (softmax runs in exp2 domain).
__global__ void __launch_bounds__(256, 2)
proj3(const __half* __restrict__ A3, const __half* __restrict__ Wh4,
      const float* __restrict__ bq, const float* __restrict__ bk,
      const float* __restrict__ bv,
      __half* __restrict__ qh, __half* __restrict__ kh, __half* __restrict__ vh)
{
    extern __shared__ char smem[];
    int z = blockIdx.z;
    const __half* Ah = A3 + (size_t)z*NA;
    const __half* Wh = Wh4 + (size_t)z*NW;
    const float* bias = (z == 0) ? bq : (z == 1) ? bk : bv;
    __half* Ch = (z == 0) ? qh : (z == 1) ? kh : vh;
    float scale = (z == 0) ? 0.125f * LOG2E : 1.0f;
    gemm_core(Ah, Wh, bias, nullptr, Ch, scale, 2, smem);
}

// Output projection (single-pass)
__global__ void __launch_bounds__(256, 2)
gemm_o(const __half* __restrict__ Ah, const __half* __restrict__ Wh,
       const float* __restrict__ bias, float* __restrict__ Cf)
{
    extern __shared__ char smem[];
    gemm_core(Ah, Wh, bias, Cf, nullptr, 1.0f, 0, smem);
}

// ---------------------------------------------------------------------------
// Flash attention over COMPACTED keys. 128-key smem tiles (cp.async double
// buffer, ONE barrier/tile), two 64-key compute subtiles (regs < 170).
// QK single fp16, PV single fp16, softmax in exp2 domain.
// CTA: 64 q-rows, 128 threads, 3 CTAs/SM.
// ---------------------------------------------------------------------------
#define AT_K 0
#define AT_V 16384
#define AT_STRIDE 32768
#define AT_SMEM 65536

__device__ __forceinline__ void attn_load_tile(
    uint32_t sbuf, const __half* kh, const __half* vh,
    const int* permb, int kt, int tid)
{
    #pragma unroll
    for (int it = 0; it < 8; it++) {
        int q = tid + it*128; int r = q >> 3, c = q & 7;
        int s = __ldg(&permb[kt + r]);
        size_t ro = (size_t)s * DK + c*8;
        uint32_t so = SWZ(r*128 + c*16);
        CP_ASYNC16(sbuf + AT_K + so, (const void*)(kh + ro));
        CP_ASYNC16(sbuf + AT_V + so, (const void*)(vh + ro));
    }
}

__global__ void __launch_bounds__(128, 3)
attn_tc(const __half* __restrict__ qhp, const __half* __restrict__ khp,
        const __half* __restrict__ vhp,
        const int* __restrict__ perm, const int* __restrict__ ncnt,
        __half* __restrict__ xout)
{
    extern __shared__ char dsm[];
    uint32_t sb = smem_to_u32(dsm);

    const int tid = threadIdx.x, lane = tid & 31, w = tid >> 5;
    const int bh = blockIdx.y, b = bh >> 4, h = bh & 15;
    const int q0 = blockIdx.x * 64;

    const int a_row  = w*16 + (lane & 15);
    const int a_half = lane >> 4;
    const int b_rowb = ((lane >> 4) << 3) + (lane & 7);
    const int b_half = (lane >> 3) & 1;
    const int v_krow = ((lane >> 3) & 1)*8 + (lane & 7);
    const int v_dhalf = lane >> 4;

    // ---- Stage Q through buf0 K region, pull fragments into registers ----
    uint32_t qfh[4][4];
    {
        const uint4* ph = (const uint4*)(qhp + ((size_t)bh*SEQ + q0)*DK);
        #pragma unroll
        for (int it = 0; it < 4; it++) {
            int q = tid + it*128; int r = q >> 3, c = q & 7;
            uint32_t so = SWZ(r*128 + c*16);
            uint4 v = ph[r*8 + c];
            STS128(sb + AT_K + so, v.x, v.y, v.z, v.w);
        }
        __syncthreads();
        #pragma unroll
        for (int kk = 0; kk < 4; kk++) {
            uint32_t off = SWZ(a_row*128 + (kk*2 + a_half)*16);
            ldmx4(sb + AT_K + off, qfh[kk]);
        }
        __syncthreads();   // buf0 free for tile 0
    }

    float acc[8][4] = {};
    float mrow[2] = {-1e30f, -1e30f}, lrow[2] = {0.f, 0.f};

    const __half* kh = khp + (size_t)bh*SEQ*DK;
    const __half* vh = vhp + (size_t)bh*SEQ*DK;
    const int* permb = perm + b*SEQ;

    const int n = __ldg(&ncnt[b]);
    const int nt = (n + 127) >> 7;

    attn_load_tile(sb, kh, vh, permb, 0, tid);
    CP_COMMIT();

    for (int t = 0; t < nt; t++) {
        uint32_t cb = sb + (uint32_t)(t & 1) * AT_STRIDE;
        CP_WAIT0();          // this thread's tile-t loads complete
        __syncthreads();     // visible to all; other buffer free (tile t-1 done)
        if (t + 1 < nt) {
            attn_load_tile(sb + (uint32_t)((t+1) & 1) * AT_STRIDE,
                           kh, vh, permb, (t+1)*128, tid);
            CP_COMMIT();
        }

        // ---- two 64-key subtiles ----
        #pragma unroll
        for (int half64 = 0; half64 < 2; half64++) {
            int kbase = half64 * 64;
            int rem = n - t*128 - kbase;
            if (rem <= 0) break;   // uniform across CTA (n is uniform)

            // S = Q K^T over 64 keys (single fp16 pass)
            float s[8][4] = {};
            #pragma unroll
            for (int kk = 0; kk < 4; kk++) {
                #pragma unroll
                for (int g = 0; g < 4; g++) {
                    uint32_t kf[4];
                    uint32_t boff = SWZ((kbase + g*16 + b_rowb)*128 + (kk*2 + b_half)*16);
                    ldmx4(cb + AT_K + boff, kf);
                    #pragma unroll
                    for (int pr = 0; pr < 2; pr++)
                        mma_fp(s[g*2 + pr], qfh[kk], kf[pr*2], kf[pr*2+1]);
                }
            }

            // tail mask
            if (rem < 64) {
                int c0 = 2*(lane & 3);
                #pragma unroll
                for (int j = 0; j < 8; j++) {
                    if (j*8 + c0     >= rem) { s[j][0] = -1e9f; s[j][2] = -1e9f; }
                    if (j*8 + c0 + 1 >= rem) { s[j][1] = -1e9f; s[j][3] = -1e9f; }
                }
            }

            // online softmax (exp2 domain; scores already scaled by log2e)
            float tlo = -1e30f, thi = -1e30f;
            #pragma unroll
            for (int j = 0; j < 8; j++) {
                tlo = fmaxf(tlo, fmaxf(s[j][0], s[j][1]));
                thi = fmaxf(thi, fmaxf(s[j][2], s[j][3]));
            }
            tlo = fmaxf(tlo, __shfl_xor_sync(0xffffffffu, tlo, 1));
            tlo = fmaxf(tlo, __shfl_xor_sync(0xffffffffu, tlo, 2));
            thi = fmaxf(thi, __shfl_xor_sync(0xffffffffu, thi, 1));
            thi = fmaxf(thi, __shfl_xor_sync(0xffffffffu, thi, 2));
            float mnlo = fmaxf(mrow[0], tlo), mnhi = fmaxf(mrow[1], thi);
            float alo = exp2f(mrow[0] - mnlo), ahi = exp2f(mrow[1] - mnhi);
            mrow[0] = mnlo; mrow[1] = mnhi;
            #pragma unroll
            for (int j = 0; j < 8; j++) {
                acc[j][0] *= alo; acc[j][1] *= alo;
                acc[j][2] *= ahi; acc[j][3] *= ahi;
            }

            // fused exp2 + PV over 4 x 16-key chunks
            float slo = 0.f, shi = 0.f;
            #pragma unroll
            for (int ks = 0; ks < 4; ks++) {
                uint32_t pa[4];
                #pragma unroll
                for (int jj = 0; jj < 2; jj++) {
                    int j = 2*ks + jj;
                    float p0 = exp2f(s[j][0] - mnlo), p1 = exp2f(s[j][1] - mnlo);
                    float p2 = exp2f(s[j][2] - mnhi), p3 = exp2f(s[j][3] - mnhi);
                    slo += p0 + p1; shi += p2 + p3;
                    __half2 h0 = __floats2half2_rn(p0, p1);
                    __half2 h1 = __floats2half2_rn(p2, p3);
                    pa[jj*2]   = *(uint32_t*)&h0;
                    pa[jj*2+1] = *(uint32_t*)&h1;
                }
                #pragma unroll
                for (int g = 0; g < 4; g++) {
                    uint32_t vb[4];
                    uint32_t voff = SWZ((kbase + ks*16 + v_krow)*128 + (g*2 + v_dhalf)*16);
                    ldmx4t(cb + AT_V + voff, vb);
                    #pragma unroll
                    for (int pr = 0; pr < 2; pr++)
                        mma_fp(acc[g*2+pr], pa, vb[pr*2], vb[pr*2+1]);
                }
            }
            slo += __shfl_xor_sync(0xffffffffu, slo, 1);
            slo += __shfl_xor_sync(0xffffffffu, slo, 2);
            shi += __shfl_xor_sync(0xffffffffu, shi, 1);
            shi += __shfl_xor_sync(0xffffffffu, shi, 2);
            lrow[0] = lrow[0]*alo + slo; lrow[1] = lrow[1]*ahi + shi;
        }
    }

    // ---- epilogue: x = acc / l, fp16, layout [b][s][h*64+d] ----
    float il0 = 1.0f / lrow[0], il1 = 1.0f / lrow[1];
    int r0g = q0 + w*16 + (lane >> 2);
    #pragma unroll
    for (int j = 0; j < 8; j++) {
        int d = j*8 + 2*(lane & 3);
        #pragma unroll
        for (int half = 0; half < 2; half++) {
            int srow = r0g + half*8;
            float il = half ? il1 : il0;
            __half2 o = __floats2half2_rn(acc[j][half*2+0] * il,
                                          acc[j][half*2+1] * il);
            *(__half2*)(xout + ((size_t)b*SEQ + srow)*DM + h*DK + d) = o;
        }
    }
}

// ---------------------------------------------------------------------------
extern "C" void kernel_launch(void* const* d_in, const int* in_sizes, int n_in,
                              void* d_out, int out_size)
{
    const float* query = (const float*)d_in[0];
    const float* key   = (const float*)d_in[1];
    const float* value = (const float*)d_in[2];
    const int*   mask  = (const int*)  d_in[3];
    const float* Wq    = (const float*)d_in[4];
    const float* bq    = (const float*)d_in[5];
    const float* Wk    = (const float*)d_in[6];
    const float* bk    = (const float*)d_in[7];
    const float* Wv    = (const float*)d_in[8];
    const float* bv    = (const float*)d_in[9];
    const float* Wo    = (const float*)d_in[10];
    const float* bo    = (const float*)d_in[11];
    float* out = (float*)d_out;

    __half *ah3, *wh4, *qh, *kh, *vh, *xh;
    int *perm, *ncnt;
    cudaGetSymbolAddress((void**)&ah3, g_ah3);
    cudaGetSymbolAddress((void**)&wh4, g_wh4);
    cudaGetSymbolAddress((void**)&qh, g_qh);
    cudaGetSymbolAddress((void**)&kh, g_kh);
    cudaGetSymbolAddress((void**)&vh, g_vh);
    cudaGetSymbolAddress((void**)&xh, g_xh);
    cudaGetSymbolAddress((void**)&perm, g_perm);
    cudaGetSymbolAddress((void**)&ncnt, g_ncnt);

    cudaFuncSetAttribute(proj3,  cudaFuncAttributeMaxDynamicSharedMemorySize, G2_SMEM);
    cudaFuncSetAttribute(gemm_o, cudaFuncAttributeMaxDynamicSharedMemorySize, G2_SMEM);
    cudaFuncSetAttribute(attn_tc, cudaFuncAttributeMaxDynamicSharedMemorySize, AT_SMEM);

    const int nW4 = NW/4;
    dim3 cgrid(nW4/256, 16);             // 12 input slices + 4 weights
    dim3 pgrid(DM/128, M_ROWS/128, 3);   // (8, 32, 3)
    dim3 ogrid(DM/128, M_ROWS/128);      // (8, 32)
    dim3 agrid(SEQ/64, BATCH*NH);        // (32, 32)

    mask_scan<<<BATCH, 1024>>>(mask, perm, ncnt);
    cvt_all<<<cgrid, 256>>>((const float4*)query, (const float4*)key,
                            (const float4*)value,
                            (const float4*)Wq, (const float4*)Wk,
                            (const float4*)Wv, (const float4*)Wo,
                            (__half2*)ah3, (__half2*)wh4);

    proj3<<<pgrid, 256, G2_SMEM>>>(ah3, wh4, bq, bk, bv, qh, kh, vh);

    attn_tc<<<agrid, 128, AT_SMEM>>>(qh, kh, vh, perm, ncnt, xh);

    gemm_o<<<ogrid, 256, G2_SMEM>>>(xh, wh4 + 3*(size_t)NW, bo, out);
}

// round 11
// speedup vs baseline: 13.6262x; 1.1884x over previous
#include <cuda_runtime.h>
#include <cuda_bf16.h>
#include <cuda_fp16.h>
#include <cstdint>

// Problem constants
#define BATCH 2
#define SEQ   2048
#define DM    1024
#define NH    16
#define DK    64
#define M_ROWS (BATCH*SEQ)   // 4096
#define NA (M_ROWS*DM)
#define NW (DM*DM)
#define LOG2E 1.4426950408889634f

// ---------------------------------------------------------------------------
// Helpers (base-sm_103 features: ldmatrix + mma.sync + cp.async)
// ---------------------------------------------------------------------------
__device__ __forceinline__ uint32_t smem_to_u32(const void* p) {
    uint32_t a;
    asm("{ .reg .u64 t; cvta.to.shared.u64 t, %1; cvt.u32.u64 %0, t; }" : "=r"(a) : "l"(p));
    return a;
}
#define SWZ(o) ((uint32_t)(o) ^ ((((uint32_t)(o)) >> 3) & 0x70))

#define STS128(a, r0, r1, r2, r3) \
    asm volatile("st.shared.v4.b32 [%0], {%1, %2, %3, %4};" \
                 :: "r"(a), "r"(r0), "r"(r1), "r"(r2), "r"(r3) : "memory")
#define CP_ASYNC16(dst, src) \
    asm volatile("cp.async.cg.shared.global [%0], [%1], 16;" :: "r"(dst), "l"(src) : "memory")
#define CP_COMMIT() asm volatile("cp.async.commit_group;" ::: "memory")
#define CP_WAIT0()  asm volatile("cp.async.wait_group 0;" ::: "memory")

__device__ __forceinline__ void ldmx4(uint32_t addr, uint32_t r[4]) {
    asm volatile("ldmatrix.sync.aligned.m8n8.x4.shared.b16 {%0,%1,%2,%3}, [%4];"
                 : "=r"(r[0]), "=r"(r[1]), "=r"(r[2]), "=r"(r[3]) : "r"(addr));
}
__device__ __forceinline__ void ldmx4t(uint32_t addr, uint32_t r[4]) {
    asm volatile("ldmatrix.sync.aligned.m8n8.x4.trans.shared.b16 {%0,%1,%2,%3}, [%4];"
                 : "=r"(r[0]), "=r"(r[1]), "=r"(r[2]), "=r"(r[3]) : "r"(addr));
}
__device__ __forceinline__ void mma_fp(float d[4], const uint32_t a[4],
                                       uint32_t b0, uint32_t b1) {
    asm volatile("mma.sync.aligned.m16n8k16.row.col.f32.f16.f16.f32 "
                 "{%0,%1,%2,%3}, {%4,%5,%6,%7}, {%8,%9}, {%0,%1,%2,%3};"
                 : "+f"(d[0]), "+f"(d[1]), "+f"(d[2]), "+f"(d[3])
                 : "r"(a[0]), "r"(a[1]), "r"(a[2]), "r"(a[3]), "r"(b0), "r"(b1));
}

// ---------------------------------------------------------------------------
// Scratch (device globals: allocation-free rule)
// ---------------------------------------------------------------------------
__device__ __half g_ah3[3*NA];                // converted q/k/v inputs (fp16)
__device__ __half g_wh4[4*NW];                // Wq,Wk,Wv,Wo fp16
__device__ __half g_qh[BATCH*NH*SEQ*DK];
__device__ __half g_kh[BATCH*NH*SEQ*DK];      // COMPACTED key index
__device__ __half g_vh[BATCH*NH*SEQ*DK];      // COMPACTED key index
__device__ __half g_xh[NA];
__device__ int    g_perm[BATCH*SEQ];
__device__ int    g_ncnt[BATCH];

// ---------------------------------------------------------------------------
// Unified convert: y in [0,12): input slice y/4 quarter y%4. y in [12,16): weight.
// ---------------------------------------------------------------------------
__global__ void __launch_bounds__(256)
cvt_all(const float4* __restrict__ q, const float4* __restrict__ k,
        const float4* __restrict__ v,
        const float4* __restrict__ wq, const float4* __restrict__ wk,
        const float4* __restrict__ wv, const float4* __restrict__ wo,
        __half2* __restrict__ in_h, __half2* __restrict__ w_h)
{
    const int y = blockIdx.y;
    const int i = blockIdx.x * blockDim.x + threadIdx.x;   // < NW/4
    const float4* src;
    __half2* h;
    if (y < 12) {
        int z = y >> 2, quad = y & 3;
        src = ((z == 0) ? q : (z == 1) ? k : v) + (size_t)quad*(NW/4);
        h = in_h + (size_t)z*(NA/2) + (size_t)quad*(NW/2);
    } else {
        int z = y - 12;
        src = (z == 0) ? wq : (z == 1) ? wk : (z == 2) ? wv : wo;
        h = w_h + (size_t)z*(NW/2);
    }
    float4 w = src[i];
    h[2*i]   = __floats2half2_rn(w.x, w.y);
    h[2*i+1] = __floats2half2_rn(w.z, w.w);
}

// ---------------------------------------------------------------------------
// Deterministic mask compaction: 1 CTA per batch, Hillis-Steele scan.
// perm zero-padded beyond n (gathered padding rows stay in-bounds).
// ---------------------------------------------------------------------------
__global__ void __launch_bounds__(1024)
mask_scan(const int* __restrict__ mask, int* __restrict__ perm, int* __restrict__ ncnt)
{
    __shared__ int sm[1024];
    int b = blockIdx.x, t = threadIdx.x;
    const int* m = mask + b*SEQ;
    int* pb = perm + b*SEQ;
    pb[2*t] = 0; pb[2*t+1] = 0;
    int a0 = (m[2*t] != 0), a1 = (m[2*t+1] != 0);
    int sum = a0 + a1;
    sm[t] = sum;
    __syncthreads();
    #pragma unroll
    for (int off = 1; off < 1024; off <<= 1) {
        int v = (t >= off) ? sm[t-off] : 0;
        __syncthreads();
        sm[t] += v;
        __syncthreads();
    }
    int excl = sm[t] - sum;
    if (a0) pb[excl] = 2*t;
    if (a1) pb[excl + a0] = 2*t + 1;
    if (t == 1023) ncnt[b] = sm[1023];
}

// ---------------------------------------------------------------------------
// fp16 single-pass NT GEMM core, cp.async double-buffered, ONE barrier/chunk.
// gather: A-rows indirected through perm (row = (m & ~2047) + perm[m]).
// BM=BN=128, BK=64, 256 threads (2m x 4n warps), warp tile 64x32.
// mode 0: fp32 flat. mode 2: fp16 head layout (m -> compacted idx when gather).
// ---------------------------------------------------------------------------
#define GB_STRIDE 32768
#define G2_SMEM   65536

__device__ __forceinline__ void g_load(uint32_t sbuf, const __half* Ah,
                                       const __half* Wh, const int* perm,
                                       int m0, int n0, int kc, int tid, int gather)
{
    #pragma unroll
    for (int it = 0; it < 4; it++) {
        int q = tid + it*256; int r = q >> 3, c = q & 7;
        uint32_t so = SWZ(r*128 + c*16);
        int rr = m0 + r;
        int row = gather ? ((rr & ~2047) + __ldg(&perm[rr])) : rr;
        CP_ASYNC16(sbuf + so,         (const void*)(Ah + (size_t)row*DM + kc + c*8));
        CP_ASYNC16(sbuf + 16384 + so, (const void*)(Wh + (size_t)(n0+r)*DM + kc + c*8));
    }
}

__device__ __forceinline__ void gemm_core(
    const __half* __restrict__ Ah, const __half* __restrict__ Wh,
    const int* __restrict__ perm, const float* __restrict__ bias,
    float* __restrict__ Cf, __half* __restrict__ Ch,
    float scale, int mode, int gather, char* smem)
{
    uint32_t sb = smem_to_u32(smem);
    const int tid = threadIdx.x, lane = tid & 31, wid = tid >> 5;
    const int wm = wid & 1, wn = wid >> 1;
    const int m0 = blockIdx.y * 128, n0 = blockIdx.x * 128;

    float acc[4][4][4] = {};

    int a_row[4], b_row[2];
    #pragma unroll
    for (int mt = 0; mt < 4; mt++) a_row[mt] = wm*64 + mt*16 + (lane & 15);
    #pragma unroll
    for (int g = 0; g < 2; g++)
        b_row[g] = wn*32 + g*16 + ((lane >> 4) << 3) + (lane & 7);
    const int a_half = lane >> 4;
    const int b_half = (lane >> 3) & 1;

    g_load(sb, Ah, Wh, perm, m0, n0, 0, tid, gather);
    CP_COMMIT();

    for (int ci = 0; ci < 16; ci++) {
        uint32_t cbuf = sb + (uint32_t)(ci & 1) * GB_STRIDE;
        CP_WAIT0();
        __syncthreads();
        if (ci + 1 < 16) {
            g_load(sb + (uint32_t)((ci+1) & 1) * GB_STRIDE, Ah, Wh, perm,
                   m0, n0, (ci+1)*64, tid, gather);
            CP_COMMIT();
        }
        #pragma unroll
        for (int kk = 0; kk < 4; kk++) {
            uint32_t af[4][4], bh2[2][4];
            #pragma unroll
            for (int mt = 0; mt < 4; mt++) {
                uint32_t off = SWZ(a_row[mt]*128 + (kk*2 + a_half)*16);
                ldmx4(cbuf + off, af[mt]);
            }
            #pragma unroll
            for (int g = 0; g < 2; g++) {
                uint32_t off = SWZ(b_row[g]*128 + (kk*2 + b_half)*16);
                ldmx4(cbuf + 16384 + off, bh2[g]);
            }
            #pragma unroll
            for (int mt = 0; mt < 4; mt++)
                #pragma unroll
                for (int j = 0; j < 4; j++) {
                    int g = j >> 1, pr = (j & 1) * 2;
                    mma_fp(acc[mt][j], af[mt], bh2[g][pr], bh2[g][pr+1]);
                }
        }
    }

    // Epilogue
    #pragma unroll
    for (int mt = 0; mt < 4; mt++) {
        int r0 = m0 + wm*64 + mt*16 + (lane >> 2);
        #pragma unroll
        for (int j = 0; j < 4; j++) {
            int cb = n0 + wn*32 + j*8 + 2*(lane & 3);
            float b0 = __ldg(&bias[cb]), b1 = __ldg(&bias[cb+1]);
            #pragma unroll
            for (int half = 0; half < 2; half++) {
                int m = r0 + half*8;
                float x0 = (acc[mt][j][half*2+0] + b0) * scale;
                float x1 = (acc[mt][j][half*2+1] + b1) * scale;
                if (mode == 0) {
                    float2 o; o.x = x0; o.y = x1;
                    *(float2*)(Cf + (size_t)m*DM + cb) = o;
                } else {
                    int b = m >> 11, s = m & 2047, h = cb >> 6, d = cb & 63;
                    size_t idx = (((size_t)(b*NH + h))*SEQ + s)*DK + d;
                    *(__half2*)(Ch + idx) = __floats2half2_rn(x0, x1);
                }
            }
        }
    }
}

// Q/K/V projections in one launch (z selects). All single-pass.
// K,V (z=1,2) are GATHERED over compacted rows; CTAs beyond ncnt exit.
// Q scale folds 1/sqrt(dk) AND log2(e) (softmax runs in exp2 domain).
__global__ void __launch_bounds__(256, 2)
proj3(const __half* __restrict__ A3, const __half* __restrict__ Wh4,
      const int* __restrict__ perm, const int* __restrict__ ncnt,
      const float* __restrict__ bq, const float* __restrict__ bk,
      const float* __restrict__ bv,
      __half* __restrict__ qh, __half* __restrict__ kh, __half* __restrict__ vh)
{
    extern __shared__ char smem[];
    int z = blockIdx.z;
    int gather = (z >= 1);
    if (gather) {
        int m0 = blockIdx.y * 128;
        if ((m0 & 2047) >= __ldg(&ncnt[m0 >> 11])) return;   // tile fully beyond n
    }
    const __half* Ah = A3 + (size_t)z*NA;
    const __half* Wh = Wh4 + (size_t)z*NW;
    const float* bias = (z == 0) ? bq : (z == 1) ? bk : bv;
    __half* Ch = (z == 0) ? qh : (z == 1) ? kh : vh;
    float scale = (z == 0) ? 0.125f * LOG2E : 1.0f;
    gemm_core(Ah, Wh, perm, bias, nullptr, Ch, scale, 2, gather, smem);
}

// Output projection (single-pass)
__global__ void __launch_bounds__(256, 2)
gemm_o(const __half* __restrict__ Ah, const __half* __restrict__ Wh,
       const float* __restrict__ bias, float* __restrict__ Cf)
{
    extern __shared__ char smem[];
    gemm_core(Ah, Wh, nullptr, bias, Cf, nullptr, 1.0f, 0, 0, smem);
}

// ---------------------------------------------------------------------------
// Flash attention over PRE-COMPACTED K/V (sequential loads, no indirection).
// 128-key smem tiles (cp.async double buffer, ONE barrier/tile),
// two 64-key compute subtiles. QK/PV single fp16, softmax exp2 domain.
// CTA: 64 q-rows, 128 threads, 3 CTAs/SM.
// ---------------------------------------------------------------------------
#define AT_K 0
#define AT_V 16384
#define AT_STRIDE 32768
#define AT_SMEM 65536

__device__ __forceinline__ void attn_load_tile(
    uint32_t sbuf, const __half* kh, const __half* vh, int kt, int tid)
{
    #pragma unroll
    for (int it = 0; it < 8; it++) {
        int q = tid + it*128; int r = q >> 3, c = q & 7;
        size_t ro = (size_t)(kt + r) * DK + c*8;
        uint32_t so = SWZ(r*128 + c*16);
        CP_ASYNC16(sbuf + AT_K + so, (const void*)(kh + ro));
        CP_ASYNC16(sbuf + AT_V + so, (const void*)(vh + ro));
    }
}

__global__ void __launch_bounds__(128, 3)
attn_tc(const __half* __restrict__ qhp, const __half* __restrict__ khp,
        const __half* __restrict__ vhp, const int* __restrict__ ncnt,
        __half* __restrict__ xout)
{
    extern __shared__ char dsm[];
    uint32_t sb = smem_to_u32(dsm);

    const int tid = threadIdx.x, lane = tid & 31, w = tid >> 5;
    const int bh = blockIdx.y, b = bh >> 4, h = bh & 15;
    const int q0 = blockIdx.x * 64;

    const int a_row  = w*16 + (lane & 15);
    const int a_half = lane >> 4;
    const int b_rowb = ((lane >> 4) << 3) + (lane & 7);
    const int b_half = (lane >> 3) & 1;
    const int v_krow = ((lane >> 3) & 1)*8 + (lane & 7);
    const int v_dhalf = lane >> 4;

    // ---- Stage Q through buf0 K region, pull fragments into registers ----
    uint32_t qfh[4][4];
    {
        const uint4* ph = (const uint4*)(qhp + ((size_t)bh*SEQ + q0)*DK);
        #pragma unroll
        for (int it = 0; it < 4; it++) {
            int q = tid + it*128; int r = q >> 3, c = q & 7;
            uint32_t so = SWZ(r*128 + c*16);
            uint4 v = ph[r*8 + c];
            STS128(sb + AT_K + so, v.x, v.y, v.z, v.w);
        }
        __syncthreads();
        #pragma unroll
        for (int kk = 0; kk < 4; kk++) {
            uint32_t off = SWZ(a_row*128 + (kk*2 + a_half)*16);
            ldmx4(sb + AT_K + off, qfh[kk]);
        }
        __syncthreads();   // buf0 free for tile 0
    }

    float acc[8][4] = {};
    float mrow[2] = {-1e30f, -1e30f}, lrow[2] = {0.f, 0.f};

    const __half* kh = khp + (size_t)bh*SEQ*DK;
    const __half* vh = vhp + (size_t)bh*SEQ*DK;

    const int n = __ldg(&ncnt[b]);
    const int nt = (n + 127) >> 7;

    attn_load_tile(sb, kh, vh, 0, tid);
    CP_COMMIT();

    for (int t = 0; t < nt; t++) {
        uint32_t cb = sb + (uint32_t)(t & 1) * AT_STRIDE;
        CP_WAIT0();
        __syncthreads();
        if (t + 1 < nt) {
            attn_load_tile(sb + (uint32_t)((t+1) & 1) * AT_STRIDE,
                           kh, vh, (t+1)*128, tid);
            CP_COMMIT();
        }

        // ---- two 64-key subtiles ----
        #pragma unroll
        for (int half64 = 0; half64 < 2; half64++) {
            int kbase = half64 * 64;
            int rem = n - t*128 - kbase;
            if (rem <= 0) break;

            // S = Q K^T over 64 keys (single fp16 pass)
            float s[8][4] = {};
            #pragma unroll
            for (int kk = 0; kk < 4; kk++) {
                #pragma unroll
                for (int g = 0; g < 4; g++) {
                    uint32_t kf[4];
                    uint32_t boff = SWZ((kbase + g*16 + b_rowb)*128 + (kk*2 + b_half)*16);
                    ldmx4(cb + AT_K + boff, kf);
                    #pragma unroll
                    for (int pr = 0; pr < 2; pr++)
                        mma_fp(s[g*2 + pr], qfh[kk], kf[pr*2], kf[pr*2+1]);
                }
            }

            // tail mask
            if (rem < 64) {
                int c0 = 2*(lane & 3);
                #pragma unroll
                for (int j = 0; j < 8; j++) {
                    if (j*8 + c0     >= rem) { s[j][0] = -1e9f; s[j][2] = -1e9f; }
                    if (j*8 + c0 + 1 >= rem) { s[j][1] = -1e9f; s[j][3] = -1e9f; }
                }
            }

            // online softmax (exp2 domain)
            float tlo = -1e30f, thi = -1e30f;
            #pragma unroll
            for (int j = 0; j < 8; j++) {
                tlo = fmaxf(tlo, fmaxf(s[j][0], s[j][1]));
                thi = fmaxf(thi, fmaxf(s[j][2], s[j][3]));
            }
            tlo = fmaxf(tlo, __shfl_xor_sync(0xffffffffu, tlo, 1));
            tlo = fmaxf(tlo, __shfl_xor_sync(0xffffffffu, tlo, 2));
            thi = fmaxf(thi, __shfl_xor_sync(0xffffffffu, thi, 1));
            thi = fmaxf(thi, __shfl_xor_sync(0xffffffffu, thi, 2));
            float mnlo = fmaxf(mrow[0], tlo), mnhi = fmaxf(mrow[1], thi);
            float alo = exp2f(mrow[0] - mnlo), ahi = exp2f(mrow[1] - mnhi);
            mrow[0] = mnlo; mrow[1] = mnhi;
            #pragma unroll
            for (int j = 0; j < 8; j++) {
                acc[j][0] *= alo; acc[j][1] *= alo;
                acc[j][2] *= ahi; acc[j][3] *= ahi;
            }

            // fused exp2 + PV over 4 x 16-key chunks
            float slo = 0.f, shi = 0.f;
            #pragma unroll
            for (int ks = 0; ks < 4; ks++) {
                uint32_t pa[4];
                #pragma unroll
                for (int jj = 0; jj < 2; jj++) {
                    int j = 2*ks + jj;
                    float p0 = exp2f(s[j][0] - mnlo), p1 = exp2f(s[j][1] - mnlo);
                    float p2 = exp2f(s[j][2] - mnhi), p3 = exp2f(s[j][3] - mnhi);
                    slo += p0 + p1; shi += p2 + p3;
                    __half2 h0 = __floats2half2_rn(p0, p1);
                    __half2 h1 = __floats2half2_rn(p2, p3);
                    pa[jj*2]   = *(uint32_t*)&h0;
                    pa[jj*2+1] = *(uint32_t*)&h1;
                }
                #pragma unroll
                for (int g = 0; g < 4; g++) {
                    uint32_t vb[4];
                    uint32_t voff = SWZ((kbase + ks*16 + v_krow)*128 + (g*2 + v_dhalf)*16);
                    ldmx4t(cb + AT_V + voff, vb);
                    #pragma unroll
                    for (int pr = 0; pr < 2; pr++)
                        mma_fp(acc[g*2+pr], pa, vb[pr*2], vb[pr*2+1]);
                }
            }
            slo += __shfl_xor_sync(0xffffffffu, slo, 1);
            slo += __shfl_xor_sync(0xffffffffu, slo, 2);
            shi += __shfl_xor_sync(0xffffffffu, shi, 1);
            shi += __shfl_xor_sync(0xffffffffu, shi, 2);
            lrow[0] = lrow[0]*alo + slo; lrow[1] = lrow[1]*ahi + shi;
        }
    }

    // ---- epilogue: x = acc / l, fp16, layout [b][s][h*64+d] ----
    float il0 = 1.0f / lrow[0], il1 = 1.0f / lrow[1];
    int r0g = q0 + w*16 + (lane >> 2);
    #pragma unroll
    for (int j = 0; j < 8; j++) {
        int d = j*8 + 2*(lane & 3);
        #pragma unroll
        for (int half = 0; half < 2; half++) {
            int srow = r0g + half*8;
            float il = half ? il1 : il0;
            __half2 o = __floats2half2_rn(acc[j][half*2+0] * il,
                                          acc[j][half*2+1] * il);
            *(__half2*)(xout + ((size_t)b*SEQ + srow)*DM + h*DK + d) = o;
        }
    }
}

// ---------------------------------------------------------------------------
extern "C" void kernel_launch(void* const* d_in, const int* in_sizes, int n_in,
                              void* d_out, int out_size)
{
    const float* query = (const float*)d_in[0];
    const float* key   = (const float*)d_in[1];
    const float* value = (const float*)d_in[2];
    const int*   mask  = (const int*)  d_in[3];
    const float* Wq    = (const float*)d_in[4];
    const float* bq    = (const float*)d_in[5];
    const float* Wk    = (const float*)d_in[6];
    const float* bk    = (const float*)d_in[7];
    const float* Wv    = (const float*)d_in[8];
    const float* bv    = (const float*)d_in[9];
    const float* Wo    = (const float*)d_in[10];
    const float* bo    = (const float*)d_in[11];
    float* out = (float*)d_out;

    __half *ah3, *wh4, *qh, *kh, *vh, *xh;
    int *perm, *ncnt;
    cudaGetSymbolAddress((void**)&ah3, g_ah3);
    cudaGetSymbolAddress((void**)&wh4, g_wh4);
    cudaGetSymbolAddress((void**)&qh, g_qh);
    cudaGetSymbolAddress((void**)&kh, g_kh);
    cudaGetSymbolAddress((void**)&vh, g_vh);
    cudaGetSymbolAddress((void**)&xh, g_xh);
    cudaGetSymbolAddress((void**)&perm, g_perm);
    cudaGetSymbolAddress((void**)&ncnt, g_ncnt);

    cudaFuncSetAttribute(proj3,  cudaFuncAttributeMaxDynamicSharedMemorySize, G2_SMEM);
    cudaFuncSetAttribute(gemm_o, cudaFuncAttributeMaxDynamicSharedMemorySize, G2_SMEM);
    cudaFuncSetAttribute(attn_tc, cudaFuncAttributeMaxDynamicSharedMemorySize, AT_SMEM);

    const int nW4 = NW/4;
    dim3 cgrid(nW4/256, 16);             // 12 input slices + 4 weights
    dim3 pgrid(DM/128, M_ROWS/128, 3);   // (8, 32, 3)
    dim3 ogrid(DM/128, M_ROWS/128);      // (8, 32)
    dim3 agrid(SEQ/64, BATCH*NH);        // (32, 32)

    mask_scan<<<BATCH, 1024>>>(mask, perm, ncnt);
    cvt_all<<<cgrid, 256>>>((const float4*)query, (const float4*)key,
                            (const float4*)value,
                            (const float4*)Wq, (const float4*)Wk,
                            (const float4*)Wv, (const float4*)Wo,
                            (__half2*)ah3, (__half2*)wh4);

    proj3<<<pgrid, 256, G2_SMEM>>>(ah3, wh4, perm, ncnt, bq, bk, bv, qh, kh, vh);

    attn_tc<<<agrid, 128, AT_SMEM>>>(qh, kh, vh, ncnt, xh);

    gemm_o<<<ogrid, 256, G2_SMEM>>>(xh, wh4 + 3*(size_t)NW, bo, out);
}